// round 5
// baseline (speedup 1.0000x reference)
#include <cuda_runtime.h>
#include <cuda_bf16.h>
#include <cstdint>

#define BDIM 32
#define TDIM 512
#define HID  1024
#define NH   16
#define HD   64
#define BT   (BDIM * TDIM)   // 16384

// ------------------------- scratch (device globals) -------------------------
__device__ float         g_scr[(size_t)2 * BDIM * HID];   // o-proj partial maxes
__device__ __nv_bfloat16 g_xhi[(size_t)BT * HID];
__device__ __nv_bfloat16 g_xlo[(size_t)BT * HID];
__device__ __nv_bfloat16 g_qhi[(size_t)BT * HID];
__device__ __nv_bfloat16 g_qlo[(size_t)BT * HID];
__device__ __nv_bfloat16 g_khi[(size_t)BT * HID];
__device__ __nv_bfloat16 g_klo[(size_t)BT * HID];
__device__ __nv_bfloat16 g_vhi[(size_t)BT * HID];
__device__ __nv_bfloat16 g_vlo[(size_t)BT * HID];
__device__ __nv_bfloat16 g_chi[(size_t)BT * HID];
__device__ __nv_bfloat16 g_clo[(size_t)BT * HID];
__device__ __nv_bfloat16 g_whi[(size_t)4 * HID * HID];
__device__ __nv_bfloat16 g_wlo[(size_t)4 * HID * HID];

// ------------------------------ PTX helpers --------------------------------
__device__ __forceinline__ uint32_t smem_u32(const void* p) {
    uint32_t a;
    asm("{ .reg .u64 t; cvta.to.shared.u64 t, %1; cvt.u32.u64 %0, t; }" : "=r"(a) : "l"(p));
    return a;
}
__device__ __forceinline__ void ldm_x4(uint32_t* r, uint32_t addr) {
    asm volatile("ldmatrix.sync.aligned.m8n8.x4.shared.b16 {%0,%1,%2,%3}, [%4];"
                 : "=r"(r[0]), "=r"(r[1]), "=r"(r[2]), "=r"(r[3]) : "r"(addr));
}
__device__ __forceinline__ void ldm_x4_t(uint32_t* r, uint32_t addr) {
    asm volatile("ldmatrix.sync.aligned.m8n8.x4.trans.shared.b16 {%0,%1,%2,%3}, [%4];"
                 : "=r"(r[0]), "=r"(r[1]), "=r"(r[2]), "=r"(r[3]) : "r"(addr));
}
__device__ __forceinline__ void mma16816(float* c, const uint32_t* a, const uint32_t* b) {
    asm volatile("mma.sync.aligned.m16n8k16.row.col.f32.bf16.bf16.f32 "
                 "{%0,%1,%2,%3}, {%4,%5,%6,%7}, {%8,%9}, {%0,%1,%2,%3};"
                 : "+f"(c[0]), "+f"(c[1]), "+f"(c[2]), "+f"(c[3])
                 : "r"(a[0]), "r"(a[1]), "r"(a[2]), "r"(a[3]), "r"(b[0]), "r"(b[1]));
}
#define CP_ASYNC16(saddr, gptr) \
    asm volatile("cp.async.cg.shared.global [%0], [%1], 16;" :: "r"(saddr), "l"(gptr))
#define CP_COMMIT() asm volatile("cp.async.commit_group;" ::: "memory")
#define CP_WAIT0()  asm volatile("cp.async.wait_group 0;" ::: "memory")

__device__ __forceinline__ uint32_t pack_hi(float a, float b) {
    __nv_bfloat162 h = __floats2bfloat162_rn(a, b);
    return *(uint32_t*)&h;
}
__device__ __forceinline__ uint32_t pack_lo(float a, float b) {
    float ra = a - __bfloat162float(__float2bfloat16_rn(a));
    float rb = b - __bfloat162float(__float2bfloat16_rn(b));
    __nv_bfloat162 l = __floats2bfloat162_rn(ra, rb);
    return *(uint32_t*)&l;
}

// ---------------------------------------------------------------------------
// GEMM v2: C[16384,1024] = (Ah+Al) @ (Wh+Wl)^T (+bias)   (fp32 acc)
// CTA tile 256x128, BK=32, 8 warps (4m x 2n), warp tile 64x64, acc 128 regs.
// SPLIT_OUT: write bf16 hi/lo (+bias). MAXOUT: column-max partials (no bias).
// ---------------------------------------------------------------------------
#define GM 256
#define GN 128
#define BK 32
#define NCHUNK (HID / BK)            // 32
#define PITCH  40                    // bf16/row (80 B)
#define P2     (PITCH * 2)
#define A_TILE (GM * P2)             // 20480
#define W_TILE (GN * P2)             // 10240
#define OFF_AH 0
#define OFF_AL A_TILE
#define OFF_WH (2 * A_TILE)
#define OFF_WL (2 * A_TILE + W_TILE)
#define STAGE2 (2 * A_TILE + 2 * W_TILE)   // 61440
#define GEMM2_SMEM (2 * STAGE2)            // 122880

template <bool SPLIT_OUT, bool MAXOUT>
__global__ void __launch_bounds__(256)
gemm2_kernel(const __nv_bfloat16* __restrict__ Ah, const __nv_bfloat16* __restrict__ Al,
             const __nv_bfloat16* __restrict__ Wh, const __nv_bfloat16* __restrict__ Wl,
             const float* __restrict__ bias,
             __nv_bfloat16* __restrict__ Chi, __nv_bfloat16* __restrict__ Clo,
             float* __restrict__ scr)
{
    extern __shared__ __align__(128) char smem[];
    const uint32_t sbase = smem_u32(smem);
    const int tid  = threadIdx.x;
    const int wid  = tid >> 5, lane = tid & 31;
    const int wm   = wid >> 1;          // 0..3  (64 rows)
    const int wn   = wid & 1;           // 0..1  (64 cols)
    const int m0   = blockIdx.y * GM;
    const int n0   = blockIdx.x * GN;

    float acc[4][8][4];
#pragma unroll
    for (int i = 0; i < 4; ++i)
#pragma unroll
        for (int j = 0; j < 8; ++j)
#pragma unroll
            for (int e = 0; e < 4; ++e) acc[i][j][e] = 0.f;

    auto issue_copy = [&](int c, int s) {
        const int k0 = c * BK;
        const uint32_t sb = sbase + s * STAGE2;
        // A hi/lo: 256 rows x 4 uint4
#pragma unroll
        for (int op = 0; op < 2; ++op) {
            const __nv_bfloat16* src = op ? Al : Ah;
            const uint32_t so = sb + (op ? OFF_AL : OFF_AH);
#pragma unroll
            for (int i = 0; i < 4; ++i) {
                const int u = i * 256 + tid;
                const int row = u >> 2, cv = u & 3;
                const void* g = src + (size_t)(m0 + row) * HID + k0 + cv * 8;
                CP_ASYNC16(so + row * P2 + cv * 16, g);
            }
        }
        // W hi/lo: 128 rows x 4 uint4
#pragma unroll
        for (int op = 0; op < 2; ++op) {
            const __nv_bfloat16* src = op ? Wl : Wh;
            const uint32_t so = sb + (op ? OFF_WL : OFF_WH);
#pragma unroll
            for (int i = 0; i < 2; ++i) {
                const int u = i * 256 + tid;
                const int row = u >> 2, cv = u & 3;
                const void* g = src + (size_t)(n0 + row) * HID + k0 + cv * 8;
                CP_ASYNC16(so + row * P2 + cv * 16, g);
            }
        }
        CP_COMMIT();
    };

    const int arow = wm * 64 + (lane & 15);
    const int acol = (lane >> 4) * 8;
    const int brow = wn * 64 + (lane & 7) + (lane >> 4) * 8;
    const int bcol = ((lane >> 3) & 1) * 8;

    auto compute = [&](int s) {
        const uint32_t sb = sbase + s * STAGE2;
#pragma unroll
        for (int ks = 0; ks < 2; ++ks) {
            uint32_t ah[4][4], al[4][4];
#pragma unroll
            for (int i = 0; i < 4; ++i) {
                const uint32_t off = (arow + i * 16) * P2 + (ks * 16 + acol) * 2;
                ldm_x4(ah[i], sb + OFF_AH + off);
                ldm_x4(al[i], sb + OFF_AL + off);
            }
#pragma unroll
            for (int jj = 0; jj < 4; ++jj) {
                uint32_t bh[4], bl[4];
                const uint32_t off = (brow + jj * 16) * P2 + (ks * 16 + bcol) * 2;
                ldm_x4(bh, sb + OFF_WH + off);
                ldm_x4(bl, sb + OFF_WL + off);
#pragma unroll
                for (int i = 0; i < 4; ++i) {
                    mma16816(acc[i][2 * jj],     ah[i], &bh[0]);
                    mma16816(acc[i][2 * jj],     ah[i], &bl[0]);
                    mma16816(acc[i][2 * jj],     al[i], &bh[0]);
                    mma16816(acc[i][2 * jj + 1], ah[i], &bh[2]);
                    mma16816(acc[i][2 * jj + 1], ah[i], &bl[2]);
                    mma16816(acc[i][2 * jj + 1], al[i], &bh[2]);
                }
            }
        }
    };

    issue_copy(0, 0);
#pragma unroll 1
    for (int c = 0; c < NCHUNK; ++c) {
        CP_WAIT0();
        __syncthreads();
        if (c + 1 < NCHUNK) issue_copy(c + 1, (c + 1) & 1);
        compute(c & 1);
        __syncthreads();
    }

    if (SPLIT_OUT) {
#pragma unroll
        for (int i = 0; i < 4; ++i) {
            const int r0 = m0 + wm * 64 + i * 16 + (lane >> 2);
#pragma unroll
            for (int j = 0; j < 8; ++j) {
                const int col = n0 + wn * 64 + j * 8 + (lane & 3) * 2;
                const float bx = bias[col], by = bias[col + 1];
                const float v0 = acc[i][j][0] + bx, v1 = acc[i][j][1] + by;
                const float v2 = acc[i][j][2] + bx, v3 = acc[i][j][3] + by;
                const size_t o0 = (size_t)r0 * HID + col;
                const size_t o1 = (size_t)(r0 + 8) * HID + col;
                *(uint32_t*)(Chi + o0) = pack_hi(v0, v1);
                *(uint32_t*)(Clo + o0) = pack_lo(v0, v1);
                *(uint32_t*)(Chi + o1) = pack_hi(v2, v3);
                *(uint32_t*)(Clo + o1) = pack_lo(v2, v3);
            }
        }
    }
    if (MAXOUT) {
        // column max over this CTA's 256 rows (bias added later: max(v)+b)
        float* maxbuf = (float*)smem;   // [4][128]
#pragma unroll
        for (int j = 0; j < 8; ++j) {
            float c0 = -3.402823466e38f, c1 = c0;
#pragma unroll
            for (int i = 0; i < 4; ++i) {
                c0 = fmaxf(c0, fmaxf(acc[i][j][0], acc[i][j][2]));
                c1 = fmaxf(c1, fmaxf(acc[i][j][1], acc[i][j][3]));
            }
            c0 = fmaxf(c0, __shfl_xor_sync(0xffffffff, c0, 4));
            c0 = fmaxf(c0, __shfl_xor_sync(0xffffffff, c0, 8));
            c0 = fmaxf(c0, __shfl_xor_sync(0xffffffff, c0, 16));
            c1 = fmaxf(c1, __shfl_xor_sync(0xffffffff, c1, 4));
            c1 = fmaxf(c1, __shfl_xor_sync(0xffffffff, c1, 8));
            c1 = fmaxf(c1, __shfl_xor_sync(0xffffffff, c1, 16));
            if ((lane >> 2) == 0) {
                const int cc = wn * 64 + j * 8 + (lane & 3) * 2;
                maxbuf[wm * 128 + cc]     = c0;
                maxbuf[wm * 128 + cc + 1] = c1;
            }
        }
        __syncthreads();
        if (tid < 128) {
            float f = fmaxf(fmaxf(maxbuf[tid], maxbuf[128 + tid]),
                            fmaxf(maxbuf[256 + tid], maxbuf[384 + tid]));
            const int b   = m0 >> 9;
            const int sub = (m0 >> 8) & 1;
            scr[((size_t)sub * BDIM + b) * HID + n0 + tid] = f;
        }
    }
}

// combine 2 partials + bias
__global__ void __launch_bounds__(256)
maxcombine_kernel(const float* __restrict__ scr, const float* __restrict__ bias,
                  float* __restrict__ out)
{
    const int i = blockIdx.x * 256 + threadIdx.x;   // over 32*1024
    out[i] = fmaxf(scr[i], scr[BDIM * HID + i]) + bias[i & (HID - 1)];
}

// ---------------------------------------------------------------------------
// Tensor-core attention (unchanged from R4)
// ---------------------------------------------------------------------------
#define APITCH 72
#define AP2    (APITCH * 2)
#define SM_QH  0
#define SM_QL  (128 * AP2)
#define SM_KH  (2 * 128 * AP2)
#define SM_KL  (SM_KH + 64 * AP2)
#define SM_VH  (SM_KH + 2 * 64 * AP2)
#define SM_VL  (SM_KH + 3 * 64 * AP2)
#define SM_MSK (SM_KH + 4 * 64 * AP2)
#define ATTN_SMEM_BYTES (SM_MSK + 64 * 4)

__global__ void __launch_bounds__(256)
attn_mma_kernel(const __nv_bfloat16* __restrict__ Qh, const __nv_bfloat16* __restrict__ Ql,
                const __nv_bfloat16* __restrict__ Kh, const __nv_bfloat16* __restrict__ Kl,
                const __nv_bfloat16* __restrict__ Vh, const __nv_bfloat16* __restrict__ Vl,
                const int* __restrict__ mask,
                __nv_bfloat16* __restrict__ Chi, __nv_bfloat16* __restrict__ Clo)
{
    extern __shared__ __align__(128) char smem[];
    const uint32_t sb = smem_u32(smem);
    float* msk01 = (float*)(smem + SM_MSK);

    const int tid  = threadIdx.x;
    const int wid  = tid >> 5, lane = tid & 31;
    const int q0   = blockIdx.x * 128;
    const int h    = blockIdx.y;
    const int b    = blockIdx.z;
    const size_t rowbase = (size_t)b * TDIM;
    const int colbase = h * HD;

    {
#pragma unroll
        for (int op = 0; op < 2; ++op) {
            const __nv_bfloat16* src = op ? Ql : Qh;
            const uint32_t so = sb + (op ? SM_QL : SM_QH);
#pragma unroll
            for (int i = 0; i < 4; ++i) {
                const int u = i * 256 + tid;
                const int r = u >> 3, cv = u & 7;
                const void* g = src + (rowbase + q0 + r) * HID + colbase + cv * 8;
                CP_ASYNC16(so + r * AP2 + cv * 16, g);
            }
        }
        CP_COMMIT();
    }

    float oacc[8][4];
#pragma unroll
    for (int j = 0; j < 8; ++j)
#pragma unroll
        for (int e = 0; e < 4; ++e) oacc[j][e] = 0.f;
    float den_r = 0.f, den_r8 = 0.f;

    const int qoff_row = (wid * 16 + (lane & 15)) * AP2;
    const int qoff_col = ((lane >> 4) * 8) * 2;
    const int koff_row = ((lane & 7) + (lane >> 4) * 8) * AP2;
    const int koff_col = (((lane >> 3) & 1) * 8) * 2;
    const int voff_row = ((lane & 15)) * AP2;
    const int voff_col = ((lane >> 4) * 8) * 2;

#pragma unroll 1
    for (int c = 0; c < 8; ++c) {
        const int k0 = c * 64;
#pragma unroll
        for (int op = 0; op < 4; ++op) {
            const __nv_bfloat16* src = (op == 0) ? Kh : (op == 1) ? Kl : (op == 2) ? Vh : Vl;
            const uint32_t so = sb + SM_KH + op * (64 * AP2);
#pragma unroll
            for (int i = 0; i < 2; ++i) {
                const int u = i * 256 + tid;
                const int r = u >> 3, cv = u & 7;
                const void* g = src + (rowbase + k0 + r) * HID + colbase + cv * 8;
                CP_ASYNC16(so + r * AP2 + cv * 16, g);
            }
        }
        CP_COMMIT();
        if (tid < 64) msk01[tid] = (float)mask[b * TDIM + k0 + tid];
        CP_WAIT0();
        __syncthreads();

        float sacc[8][4];
#pragma unroll
        for (int j = 0; j < 8; ++j)
#pragma unroll
            for (int e = 0; e < 4; ++e) sacc[j][e] = 0.f;

#pragma unroll
        for (int dk = 0; dk < 4; ++dk) {
            uint32_t ah[4], al[4];
            const uint32_t qa = sb + qoff_row + dk * 32 + qoff_col;
            ldm_x4(ah, qa + SM_QH);
            ldm_x4(al, qa + SM_QL);
#pragma unroll
            for (int kb = 0; kb < 4; ++kb) {
                uint32_t bh[4], bl[4];
                const uint32_t ka = sb + (kb * 16) * AP2 + koff_row + dk * 32 + koff_col;
                ldm_x4(bh, ka + SM_KH);
                ldm_x4(bl, ka + SM_KL);
                mma16816(sacc[2 * kb],     ah, &bh[0]);
                mma16816(sacc[2 * kb],     ah, &bl[0]);
                mma16816(sacc[2 * kb],     al, &bh[0]);
                mma16816(sacc[2 * kb + 1], ah, &bh[2]);
                mma16816(sacc[2 * kb + 1], ah, &bl[2]);
                mma16816(sacc[2 * kb + 1], al, &bh[2]);
            }
        }

        float dr = 0.f, dr8 = 0.f;
#pragma unroll
        for (int nt = 0; nt < 8; ++nt) {
            const int c0 = nt * 8 + (lane & 3) * 2;
            const float m0 = msk01[c0], m1 = msk01[c0 + 1];
#pragma unroll
            for (int e = 0; e < 4; ++e) {
                float s = sacc[nt][e] * 0.125f;
                s = fminf(fmaxf(s, -50.f), 50.f);
                s = ((e & 1) ? m1 : m0) * (s + 50.f) - 50.f;
                sacc[nt][e] = __expf(s);
            }
            dr  += sacc[nt][0] + sacc[nt][1];
            dr8 += sacc[nt][2] + sacc[nt][3];
        }
        dr  += __shfl_xor_sync(0xffffffff, dr, 1);
        dr  += __shfl_xor_sync(0xffffffff, dr, 2);
        dr8 += __shfl_xor_sync(0xffffffff, dr8, 1);
        dr8 += __shfl_xor_sync(0xffffffff, dr8, 2);
        den_r  += dr;
        den_r8 += dr8;

#pragma unroll
        for (int kb = 0; kb < 4; ++kb) {
            uint32_t pah[4], pal[4];
            const int t0 = 2 * kb, t1 = 2 * kb + 1;
            pah[0] = pack_hi(sacc[t0][0], sacc[t0][1]);
            pah[1] = pack_hi(sacc[t0][2], sacc[t0][3]);
            pah[2] = pack_hi(sacc[t1][0], sacc[t1][1]);
            pah[3] = pack_hi(sacc[t1][2], sacc[t1][3]);
            pal[0] = pack_lo(sacc[t0][0], sacc[t0][1]);
            pal[1] = pack_lo(sacc[t0][2], sacc[t0][3]);
            pal[2] = pack_lo(sacc[t1][0], sacc[t1][1]);
            pal[3] = pack_lo(sacc[t1][2], sacc[t1][3]);
#pragma unroll
            for (int dnp = 0; dnp < 4; ++dnp) {
                uint32_t vh[4], vl[4];
                const uint32_t va = sb + (kb * 16) * AP2 + voff_row + dnp * 32 + voff_col;
                ldm_x4_t(vh, va + SM_VH);
                ldm_x4_t(vl, va + SM_VL);
                mma16816(oacc[2 * dnp],     pah, &vh[0]);
                mma16816(oacc[2 * dnp],     pah, &vl[0]);
                mma16816(oacc[2 * dnp],     pal, &vh[0]);
                mma16816(oacc[2 * dnp + 1], pah, &vh[2]);
                mma16816(oacc[2 * dnp + 1], pah, &vl[2]);
                mma16816(oacc[2 * dnp + 1], pal, &vh[2]);
            }
        }
        __syncthreads();
    }

    const float invr  = 1.f / den_r;
    const float invr8 = 1.f / den_r8;
    const size_t r0 = (rowbase + q0 + wid * 16 + (lane >> 2)) * HID + colbase;
    const size_t r8 = r0 + 8 * HID;
#pragma unroll
    for (int dn = 0; dn < 8; ++dn) {
        const int col = dn * 8 + (lane & 3) * 2;
        const float v0 = oacc[dn][0] * invr,  v1 = oacc[dn][1] * invr;
        const float v2 = oacc[dn][2] * invr8, v3 = oacc[dn][3] * invr8;
        *(uint32_t*)(Chi + r0 + col) = pack_hi(v0, v1);
        *(uint32_t*)(Clo + r0 + col) = pack_lo(v0, v1);
        *(uint32_t*)(Chi + r8 + col) = pack_hi(v2, v3);
        *(uint32_t*)(Clo + r8 + col) = pack_lo(v2, v3);
    }
}

// ---------------------------------------------------------------------------
__global__ void __launch_bounds__(256)
xpose_split_kernel(const float* __restrict__ x,
                   __nv_bfloat16* __restrict__ hi, __nv_bfloat16* __restrict__ lo)
{
    __shared__ float s[32][33];
    const int b = blockIdx.z, k0 = blockIdx.y * 32, t0 = blockIdx.x * 32;
    const int tx = threadIdx.x & 31, ty = threadIdx.x >> 5;
    const float* src = x + ((size_t)b * HID + k0) * TDIM + t0;
#pragma unroll
    for (int i = 0; i < 4; ++i)
        s[ty + 8 * i][tx] = src[(size_t)(ty + 8 * i) * TDIM + tx];
    __syncthreads();
#pragma unroll
    for (int i = 0; i < 4; ++i) {
        const int t = ty + 8 * i;
        const float v = s[tx][t];
        const __nv_bfloat16 hh = __float2bfloat16_rn(v);
        const __nv_bfloat16 ll = __float2bfloat16_rn(v - __bfloat162float(hh));
        const size_t o = (size_t)(b * TDIM + t0 + t) * HID + k0 + tx;
        hi[o] = hh;
        lo[o] = ll;
    }
}

__global__ void __launch_bounds__(256)
split_kernel(const float* __restrict__ src,
             __nv_bfloat16* __restrict__ hi, __nv_bfloat16* __restrict__ lo, int n4)
{
    const int i = blockIdx.x * 256 + threadIdx.x;
    if (i >= n4) return;
    const float4 v = ((const float4*)src)[i];
    uint2 hp, lp;
    hp.x = pack_hi(v.x, v.y); hp.y = pack_hi(v.z, v.w);
    lp.x = pack_lo(v.x, v.y); lp.y = pack_lo(v.z, v.w);
    ((uint2*)hi)[i] = hp;
    ((uint2*)lo)[i] = lp;
}

// ---------------------------------------------------------------------------
extern "C" void kernel_launch(void* const* d_in, const int* in_sizes, int n_in,
                              void* d_out, int out_size)
{
    const float* x    = (const float*)d_in[0];
    const int*   mask = (const int*)d_in[1];
    const float* W[4] = { (const float*)d_in[2], (const float*)d_in[4],
                          (const float*)d_in[6], (const float*)d_in[8] };
    const float* bq   = (const float*)d_in[3];
    const float* bk   = (const float*)d_in[5];
    const float* bv   = (const float*)d_in[7];
    const float* bo   = (const float*)d_in[9];
    float* out = (float*)d_out;

    float* scr;
    __nv_bfloat16 *xhi, *xlo, *qhi, *qlo, *khi, *klo, *vhi, *vlo, *chi, *clo, *whi, *wlo;
    cudaGetSymbolAddress((void**)&scr, g_scr);
    cudaGetSymbolAddress((void**)&xhi, g_xhi);
    cudaGetSymbolAddress((void**)&xlo, g_xlo);
    cudaGetSymbolAddress((void**)&qhi, g_qhi);
    cudaGetSymbolAddress((void**)&qlo, g_qlo);
    cudaGetSymbolAddress((void**)&khi, g_khi);
    cudaGetSymbolAddress((void**)&klo, g_klo);
    cudaGetSymbolAddress((void**)&vhi, g_vhi);
    cudaGetSymbolAddress((void**)&vlo, g_vlo);
    cudaGetSymbolAddress((void**)&chi, g_chi);
    cudaGetSymbolAddress((void**)&clo, g_clo);
    cudaGetSymbolAddress((void**)&whi, g_whi);
    cudaGetSymbolAddress((void**)&wlo, g_wlo);

    cudaFuncSetAttribute(gemm2_kernel<true, false>,
                         cudaFuncAttributeMaxDynamicSharedMemorySize, GEMM2_SMEM);
    cudaFuncSetAttribute(gemm2_kernel<false, true>,
                         cudaFuncAttributeMaxDynamicSharedMemorySize, GEMM2_SMEM);
    cudaFuncSetAttribute(attn_mma_kernel,
                         cudaFuncAttributeMaxDynamicSharedMemorySize, ATTN_SMEM_BYTES);

    const int wn4 = HID * HID / 4;
    for (int i = 0; i < 4; ++i)
        split_kernel<<<(wn4 + 255) / 256, 256>>>(W[i], whi + (size_t)i * HID * HID,
                                                 wlo + (size_t)i * HID * HID, wn4);
    xpose_split_kernel<<<dim3(TDIM / 32, HID / 32, BDIM), 256>>>(x, xhi, xlo);

    const dim3 gg(HID / GN, BT / GM);   // (8, 64)
    const size_t WSZ = (size_t)HID * HID;

    gemm2_kernel<true, false><<<gg, 256, GEMM2_SMEM>>>(xhi, xlo, whi + 0 * WSZ, wlo + 0 * WSZ,
                                                       bq, qhi, qlo, nullptr);
    gemm2_kernel<true, false><<<gg, 256, GEMM2_SMEM>>>(xhi, xlo, whi + 1 * WSZ, wlo + 1 * WSZ,
                                                       bk, khi, klo, nullptr);
    gemm2_kernel<true, false><<<gg, 256, GEMM2_SMEM>>>(xhi, xlo, whi + 2 * WSZ, wlo + 2 * WSZ,
                                                       bv, vhi, vlo, nullptr);

    attn_mma_kernel<<<dim3(TDIM / 128, NH, BDIM), 256, ATTN_SMEM_BYTES>>>(
        qhi, qlo, khi, klo, vhi, vlo, mask, chi, clo);

    gemm2_kernel<false, true><<<gg, 256, GEMM2_SMEM>>>(chi, clo, whi + 3 * WSZ, wlo + 3 * WSZ,
                                                       nullptr, nullptr, nullptr, scr);

    maxcombine_kernel<<<(BDIM * HID) / 256, 256>>>(scr, bo, out);
}

// round 6
// speedup vs baseline: 1.1717x; 1.1717x over previous
#include <cuda_runtime.h>
#include <cuda_bf16.h>
#include <cstdint>

#define BDIM 32
#define TDIM 512
#define HID  1024
#define NH   16
#define HD   64
#define BT   (BDIM * TDIM)   // 16384

// ------------------------- scratch (device globals) -------------------------
__device__ float         g_scr[(size_t)4 * BDIM * HID];   // o-proj partial maxes
__device__ __nv_bfloat16 g_xhi[(size_t)BT * HID];
__device__ __nv_bfloat16 g_xlo[(size_t)BT * HID];
__device__ __nv_bfloat16 g_qhi[(size_t)BT * HID];
__device__ __nv_bfloat16 g_qlo[(size_t)BT * HID];
__device__ __nv_bfloat16 g_khi[(size_t)BT * HID];
__device__ __nv_bfloat16 g_klo[(size_t)BT * HID];
__device__ __nv_bfloat16 g_vhi[(size_t)BT * HID];
__device__ __nv_bfloat16 g_vlo[(size_t)BT * HID];
__device__ __nv_bfloat16 g_chi[(size_t)BT * HID];
__device__ __nv_bfloat16 g_clo[(size_t)BT * HID];
__device__ __nv_bfloat16 g_whi[(size_t)4 * HID * HID];
__device__ __nv_bfloat16 g_wlo[(size_t)4 * HID * HID];

// ------------------------------ PTX helpers --------------------------------
__device__ __forceinline__ uint32_t smem_u32(const void* p) {
    uint32_t a;
    asm("{ .reg .u64 t; cvta.to.shared.u64 t, %1; cvt.u32.u64 %0, t; }" : "=r"(a) : "l"(p));
    return a;
}
__device__ __forceinline__ void ldm_x4(uint32_t* r, uint32_t addr) {
    asm volatile("ldmatrix.sync.aligned.m8n8.x4.shared.b16 {%0,%1,%2,%3}, [%4];"
                 : "=r"(r[0]), "=r"(r[1]), "=r"(r[2]), "=r"(r[3]) : "r"(addr));
}
__device__ __forceinline__ void ldm_x4_t(uint32_t* r, uint32_t addr) {
    asm volatile("ldmatrix.sync.aligned.m8n8.x4.trans.shared.b16 {%0,%1,%2,%3}, [%4];"
                 : "=r"(r[0]), "=r"(r[1]), "=r"(r[2]), "=r"(r[3]) : "r"(addr));
}
__device__ __forceinline__ void mma16816(float* c, const uint32_t* a, const uint32_t* b) {
    asm volatile("mma.sync.aligned.m16n8k16.row.col.f32.bf16.bf16.f32 "
                 "{%0,%1,%2,%3}, {%4,%5,%6,%7}, {%8,%9}, {%0,%1,%2,%3};"
                 : "+f"(c[0]), "+f"(c[1]), "+f"(c[2]), "+f"(c[3])
                 : "r"(a[0]), "r"(a[1]), "r"(a[2]), "r"(a[3]), "r"(b[0]), "r"(b[1]));
}
#define CP_ASYNC16(saddr, gptr) \
    asm volatile("cp.async.cg.shared.global [%0], [%1], 16;" :: "r"(saddr), "l"(gptr))
#define CP_COMMIT() asm volatile("cp.async.commit_group;" ::: "memory")
#define CP_WAIT0()  asm volatile("cp.async.wait_group 0;" ::: "memory")

__device__ __forceinline__ uint32_t pack_hi(float a, float b) {
    __nv_bfloat162 h = __floats2bfloat162_rn(a, b);
    return *(uint32_t*)&h;
}
__device__ __forceinline__ uint32_t pack_lo(float a, float b) {
    float ra = a - __bfloat162float(__float2bfloat16_rn(a));
    float rb = b - __bfloat162float(__float2bfloat16_rn(b));
    __nv_bfloat162 l = __floats2bfloat162_rn(ra, rb);
    return *(uint32_t*)&l;
}

// ---------------------------------------------------------------------------
// R4 GEMM core: 128x128 tile, BK=32, 8 warps (2m x 4n), warp tile 64x32.
// 2-stage cp.async pipeline, smem 80KB => 2 CTAs/SM.
// ---------------------------------------------------------------------------
#define BK      32
#define NCHUNK  (HID / BK)          // 32
#define PITCH   40                  // bf16 elems per smem row (80B)
#define P2      (PITCH * 2)
#define TILE_B  (128 * P2)          // 10240 bytes
#define STAGE_B (4 * TILE_B)        // 40960
#define GEMM_SMEM_BYTES (2 * STAGE_B)

struct GemmCore {
    uint32_t sbase;
    int tid, wid, lane, wm, wn, m0, n0;
    float acc[4][4][4];

    __device__ __forceinline__ void init(uint32_t sb, int m, int n) {
        sbase = sb;
        tid = threadIdx.x; wid = tid >> 5; lane = tid & 31;
        wm = wid >> 2; wn = wid & 3;
        m0 = m; n0 = n;
#pragma unroll
        for (int i = 0; i < 4; ++i)
#pragma unroll
            for (int j = 0; j < 4; ++j)
#pragma unroll
                for (int e = 0; e < 4; ++e) acc[i][j][e] = 0.f;
    }

    __device__ __forceinline__ void issue_copy(
        const __nv_bfloat16* Ah, const __nv_bfloat16* Al,
        const __nv_bfloat16* Wh, const __nv_bfloat16* Wl, int c, int s)
    {
        const int k0 = c * BK;
        const uint32_t sb = sbase + s * STAGE_B;
#pragma unroll
        for (int op = 0; op < 4; ++op) {
            const __nv_bfloat16* src = (op == 0) ? Ah : (op == 1) ? Al : (op == 2) ? Wh : Wl;
            const int rbase = (op < 2) ? m0 : n0;
#pragma unroll
            for (int i = 0; i < 2; ++i) {
                const int u   = i * 256 + tid;
                const int row = u >> 2;
                const int cv  = u & 3;
                const void* g = src + (size_t)(rbase + row) * HID + k0 + cv * 8;
                CP_ASYNC16(sb + op * TILE_B + row * P2 + cv * 16, g);
            }
        }
        CP_COMMIT();
    }

    __device__ __forceinline__ void compute(int s) {
        const uint32_t sb  = sbase + s * STAGE_B;
        const uint32_t aAh = sb;
        const uint32_t aAl = sb + TILE_B;
        const uint32_t aWh = sb + 2 * TILE_B;
        const uint32_t aWl = sb + 3 * TILE_B;

        const int arow = wm * 64 + (lane & 15);
        const int acol = (lane >> 4) * 8;
        const int brow = wn * 32 + (lane & 7) + (lane >> 4) * 8;
        const int bcol = ((lane >> 3) & 1) * 8;

#pragma unroll
        for (int ks = 0; ks < 2; ++ks) {
            uint32_t ah[4][4], al[4][4];
#pragma unroll
            for (int i = 0; i < 4; ++i) {
                const uint32_t off = (arow + i * 16) * P2 + (ks * 16 + acol) * 2;
                ldm_x4(ah[i], aAh + off);
                ldm_x4(al[i], aAl + off);
            }
            uint32_t bh[8], bl[8];
#pragma unroll
            for (int jj = 0; jj < 2; ++jj) {
                const uint32_t off = (brow + jj * 16) * P2 + (ks * 16 + bcol) * 2;
                ldm_x4(&bh[jj * 4], aWh + off);
                ldm_x4(&bl[jj * 4], aWl + off);
            }
#pragma unroll
            for (int i = 0; i < 4; ++i)
#pragma unroll
                for (int j = 0; j < 4; ++j) {
                    const int bi = (j >> 1) * 4 + (j & 1) * 2;
                    mma16816(acc[i][j], ah[i], &bh[bi]);
                    mma16816(acc[i][j], ah[i], &bl[bi]);
                    mma16816(acc[i][j], al[i], &bh[bi]);
                }
        }
    }

    __device__ __forceinline__ void mainloop(
        const __nv_bfloat16* Ah, const __nv_bfloat16* Al,
        const __nv_bfloat16* Wh, const __nv_bfloat16* Wl)
    {
        issue_copy(Ah, Al, Wh, Wl, 0, 0);
#pragma unroll 1
        for (int c = 0; c < NCHUNK; ++c) {
            CP_WAIT0();
            __syncthreads();
            if (c + 1 < NCHUNK) issue_copy(Ah, Al, Wh, Wl, c + 1, (c + 1) & 1);
            compute(c & 1);
            __syncthreads();
        }
    }
};

// ---- fused QKV: gridDim.z in {0,1,2} selects weight / bias / destination ----
__global__ void __launch_bounds__(256)
gemm_qkv_kernel(const __nv_bfloat16* __restrict__ xhi, const __nv_bfloat16* __restrict__ xlo,
                const __nv_bfloat16* __restrict__ whi, const __nv_bfloat16* __restrict__ wlo,
                const float* __restrict__ bq, const float* __restrict__ bk,
                const float* __restrict__ bv,
                __nv_bfloat16* __restrict__ qhi, __nv_bfloat16* __restrict__ qlo,
                __nv_bfloat16* __restrict__ khi, __nv_bfloat16* __restrict__ klo,
                __nv_bfloat16* __restrict__ vhi, __nv_bfloat16* __restrict__ vlo)
{
    extern __shared__ __align__(128) char smem[];
    const int z = blockIdx.z;
    const size_t WSZ = (size_t)HID * HID;
    const __nv_bfloat16* Wh = whi + z * WSZ;
    const __nv_bfloat16* Wl = wlo + z * WSZ;
    const float* bias = (z == 0) ? bq : (z == 1) ? bk : bv;
    __nv_bfloat16* Chi = (z == 0) ? qhi : (z == 1) ? khi : vhi;
    __nv_bfloat16* Clo = (z == 0) ? qlo : (z == 1) ? klo : vlo;

    GemmCore g;
    g.init(smem_u32(smem), blockIdx.y * 128, blockIdx.x * 128);
    g.mainloop(xhi, xlo, Wh, Wl);

#pragma unroll
    for (int i = 0; i < 4; ++i) {
        const int r0 = g.m0 + g.wm * 64 + i * 16 + (g.lane >> 2);
#pragma unroll
        for (int j = 0; j < 4; ++j) {
            const int col = g.n0 + g.wn * 32 + j * 8 + (g.lane & 3) * 2;
            const float bx = bias[col], by = bias[col + 1];
            const float v0 = g.acc[i][j][0] + bx, v1 = g.acc[i][j][1] + by;
            const float v2 = g.acc[i][j][2] + bx, v3 = g.acc[i][j][3] + by;
            const size_t o0 = (size_t)r0 * HID + col;
            const size_t o1 = (size_t)(r0 + 8) * HID + col;
            *(uint32_t*)(Chi + o0) = pack_hi(v0, v1);
            *(uint32_t*)(Clo + o0) = pack_lo(v0, v1);
            *(uint32_t*)(Chi + o1) = pack_hi(v2, v3);
            *(uint32_t*)(Clo + o1) = pack_lo(v2, v3);
        }
    }
}

// ---- o-proj with fused column-max epilogue (bias added in combine) ----
__global__ void __launch_bounds__(256)
gemm_omax_kernel(const __nv_bfloat16* __restrict__ chi, const __nv_bfloat16* __restrict__ clo,
                 const __nv_bfloat16* __restrict__ Wh, const __nv_bfloat16* __restrict__ Wl,
                 float* __restrict__ scr)
{
    extern __shared__ __align__(128) char smem[];
    GemmCore g;
    g.init(smem_u32(smem), blockIdx.y * 128, blockIdx.x * 128);
    g.mainloop(chi, clo, Wh, Wl);

    // column max over this CTA's 128 rows
    float* maxbuf = (float*)smem;   // [2][128] indexed by wm
#pragma unroll
    for (int j = 0; j < 4; ++j) {
        float c0 = -3.402823466e38f, c1 = c0;
#pragma unroll
        for (int i = 0; i < 4; ++i) {
            c0 = fmaxf(c0, fmaxf(g.acc[i][j][0], g.acc[i][j][2]));
            c1 = fmaxf(c1, fmaxf(g.acc[i][j][1], g.acc[i][j][3]));
        }
        c0 = fmaxf(c0, __shfl_xor_sync(0xffffffff, c0, 4));
        c0 = fmaxf(c0, __shfl_xor_sync(0xffffffff, c0, 8));
        c0 = fmaxf(c0, __shfl_xor_sync(0xffffffff, c0, 16));
        c1 = fmaxf(c1, __shfl_xor_sync(0xffffffff, c1, 4));
        c1 = fmaxf(c1, __shfl_xor_sync(0xffffffff, c1, 8));
        c1 = fmaxf(c1, __shfl_xor_sync(0xffffffff, c1, 16));
        if ((g.lane >> 2) == 0) {
            const int cc = g.wn * 32 + j * 8 + (g.lane & 3) * 2;
            maxbuf[g.wm * 128 + cc]     = c0;
            maxbuf[g.wm * 128 + cc + 1] = c1;
        }
    }
    __syncthreads();
    if (g.tid < 128) {
        const float f = fmaxf(maxbuf[g.tid], maxbuf[128 + g.tid]);
        const int b   = g.m0 >> 9;           // batch
        const int sub = (g.m0 >> 7) & 3;     // 4 m-subtiles per batch
        scr[((size_t)sub * BDIM + b) * HID + g.n0 + g.tid] = f;
    }
}

// combine 4 partials + bias
__global__ void __launch_bounds__(256)
maxcombine_kernel(const float* __restrict__ scr, const float* __restrict__ bias,
                  float* __restrict__ out)
{
    const int i = blockIdx.x * 256 + threadIdx.x;   // over 32*1024
    const float f = fmaxf(fmaxf(scr[i], scr[BDIM * HID + i]),
                          fmaxf(scr[2 * BDIM * HID + i], scr[3 * BDIM * HID + i]));
    out[i] = f + bias[i & (HID - 1)];
}

// ---------------------------------------------------------------------------
// Tensor-core attention (unchanged from R4)
// ---------------------------------------------------------------------------
#define APITCH 72
#define AP2    (APITCH * 2)
#define SM_QH  0
#define SM_QL  (128 * AP2)
#define SM_KH  (2 * 128 * AP2)
#define SM_KL  (SM_KH + 64 * AP2)
#define SM_VH  (SM_KH + 2 * 64 * AP2)
#define SM_VL  (SM_KH + 3 * 64 * AP2)
#define SM_MSK (SM_KH + 4 * 64 * AP2)
#define ATTN_SMEM_BYTES (SM_MSK + 64 * 4)

__global__ void __launch_bounds__(256)
attn_mma_kernel(const __nv_bfloat16* __restrict__ Qh, const __nv_bfloat16* __restrict__ Ql,
                const __nv_bfloat16* __restrict__ Kh, const __nv_bfloat16* __restrict__ Kl,
                const __nv_bfloat16* __restrict__ Vh, const __nv_bfloat16* __restrict__ Vl,
                const int* __restrict__ mask,
                __nv_bfloat16* __restrict__ Chi, __nv_bfloat16* __restrict__ Clo)
{
    extern __shared__ __align__(128) char smem[];
    const uint32_t sb = smem_u32(smem);
    float* msk01 = (float*)(smem + SM_MSK);

    const int tid  = threadIdx.x;
    const int wid  = tid >> 5, lane = tid & 31;
    const int q0   = blockIdx.x * 128;
    const int h    = blockIdx.y;
    const int b    = blockIdx.z;
    const size_t rowbase = (size_t)b * TDIM;
    const int colbase = h * HD;

    {
#pragma unroll
        for (int op = 0; op < 2; ++op) {
            const __nv_bfloat16* src = op ? Ql : Qh;
            const uint32_t so = sb + (op ? SM_QL : SM_QH);
#pragma unroll
            for (int i = 0; i < 4; ++i) {
                const int u = i * 256 + tid;
                const int r = u >> 3, cv = u & 7;
                const void* g = src + (rowbase + q0 + r) * HID + colbase + cv * 8;
                CP_ASYNC16(so + r * AP2 + cv * 16, g);
            }
        }
        CP_COMMIT();
    }

    float oacc[8][4];
#pragma unroll
    for (int j = 0; j < 8; ++j)
#pragma unroll
        for (int e = 0; e < 4; ++e) oacc[j][e] = 0.f;
    float den_r = 0.f, den_r8 = 0.f;

    const int qoff_row = (wid * 16 + (lane & 15)) * AP2;
    const int qoff_col = ((lane >> 4) * 8) * 2;
    const int koff_row = ((lane & 7) + (lane >> 4) * 8) * AP2;
    const int koff_col = (((lane >> 3) & 1) * 8) * 2;
    const int voff_row = ((lane & 15)) * AP2;
    const int voff_col = ((lane >> 4) * 8) * 2;

#pragma unroll 1
    for (int c = 0; c < 8; ++c) {
        const int k0 = c * 64;
#pragma unroll
        for (int op = 0; op < 4; ++op) {
            const __nv_bfloat16* src = (op == 0) ? Kh : (op == 1) ? Kl : (op == 2) ? Vh : Vl;
            const uint32_t so = sb + SM_KH + op * (64 * AP2);
#pragma unroll
            for (int i = 0; i < 2; ++i) {
                const int u = i * 256 + tid;
                const int r = u >> 3, cv = u & 7;
                const void* g = src + (rowbase + k0 + r) * HID + colbase + cv * 8;
                CP_ASYNC16(so + r * AP2 + cv * 16, g);
            }
        }
        CP_COMMIT();
        if (tid < 64) msk01[tid] = (float)mask[b * TDIM + k0 + tid];
        CP_WAIT0();
        __syncthreads();

        float sacc[8][4];
#pragma unroll
        for (int j = 0; j < 8; ++j)
#pragma unroll
            for (int e = 0; e < 4; ++e) sacc[j][e] = 0.f;

#pragma unroll
        for (int dk = 0; dk < 4; ++dk) {
            uint32_t ah[4], al[4];
            const uint32_t qa = sb + qoff_row + dk * 32 + qoff_col;
            ldm_x4(ah, qa + SM_QH);
            ldm_x4(al, qa + SM_QL);
#pragma unroll
            for (int kb = 0; kb < 4; ++kb) {
                uint32_t bh[4], bl[4];
                const uint32_t ka = sb + (kb * 16) * AP2 + koff_row + dk * 32 + koff_col;
                ldm_x4(bh, ka + SM_KH);
                ldm_x4(bl, ka + SM_KL);
                mma16816(sacc[2 * kb],     ah, &bh[0]);
                mma16816(sacc[2 * kb],     ah, &bl[0]);
                mma16816(sacc[2 * kb],     al, &bh[0]);
                mma16816(sacc[2 * kb + 1], ah, &bh[2]);
                mma16816(sacc[2 * kb + 1], ah, &bl[2]);
                mma16816(sacc[2 * kb + 1], al, &bh[2]);
            }
        }

        float dr = 0.f, dr8 = 0.f;
#pragma unroll
        for (int nt = 0; nt < 8; ++nt) {
            const int c0 = nt * 8 + (lane & 3) * 2;
            const float m0 = msk01[c0], m1 = msk01[c0 + 1];
#pragma unroll
            for (int e = 0; e < 4; ++e) {
                float s = sacc[nt][e] * 0.125f;
                s = fminf(fmaxf(s, -50.f), 50.f);
                s = ((e & 1) ? m1 : m0) * (s + 50.f) - 50.f;
                sacc[nt][e] = __expf(s);
            }
            dr  += sacc[nt][0] + sacc[nt][1];
            dr8 += sacc[nt][2] + sacc[nt][3];
        }
        dr  += __shfl_xor_sync(0xffffffff, dr, 1);
        dr  += __shfl_xor_sync(0xffffffff, dr, 2);
        dr8 += __shfl_xor_sync(0xffffffff, dr8, 1);
        dr8 += __shfl_xor_sync(0xffffffff, dr8, 2);
        den_r  += dr;
        den_r8 += dr8;

#pragma unroll
        for (int kb = 0; kb < 4; ++kb) {
            uint32_t pah[4], pal[4];
            const int t0 = 2 * kb, t1 = 2 * kb + 1;
            pah[0] = pack_hi(sacc[t0][0], sacc[t0][1]);
            pah[1] = pack_hi(sacc[t0][2], sacc[t0][3]);
            pah[2] = pack_hi(sacc[t1][0], sacc[t1][1]);
            pah[3] = pack_hi(sacc[t1][2], sacc[t1][3]);
            pal[0] = pack_lo(sacc[t0][0], sacc[t0][1]);
            pal[1] = pack_lo(sacc[t0][2], sacc[t0][3]);
            pal[2] = pack_lo(sacc[t1][0], sacc[t1][1]);
            pal[3] = pack_lo(sacc[t1][2], sacc[t1][3]);
#pragma unroll
            for (int dnp = 0; dnp < 4; ++dnp) {
                uint32_t vh[4], vl[4];
                const uint32_t va = sb + (kb * 16) * AP2 + voff_row + dnp * 32 + voff_col;
                ldm_x4_t(vh, va + SM_VH);
                ldm_x4_t(vl, va + SM_VL);
                mma16816(oacc[2 * dnp],     pah, &vh[0]);
                mma16816(oacc[2 * dnp],     pah, &vl[0]);
                mma16816(oacc[2 * dnp],     pal, &vh[0]);
                mma16816(oacc[2 * dnp + 1], pah, &vh[2]);
                mma16816(oacc[2 * dnp + 1], pah, &vl[2]);
                mma16816(oacc[2 * dnp + 1], pal, &vh[2]);
            }
        }
        __syncthreads();
    }

    const float invr  = 1.f / den_r;
    const float invr8 = 1.f / den_r8;
    const size_t r0 = (rowbase + q0 + wid * 16 + (lane >> 2)) * HID + colbase;
    const size_t r8 = r0 + 8 * HID;
#pragma unroll
    for (int dn = 0; dn < 8; ++dn) {
        const int col = dn * 8 + (lane & 3) * 2;
        const float v0 = oacc[dn][0] * invr,  v1 = oacc[dn][1] * invr;
        const float v2 = oacc[dn][2] * invr8, v3 = oacc[dn][3] * invr8;
        *(uint32_t*)(Chi + r0 + col) = pack_hi(v0, v1);
        *(uint32_t*)(Clo + r0 + col) = pack_lo(v0, v1);
        *(uint32_t*)(Chi + r8 + col) = pack_hi(v2, v3);
        *(uint32_t*)(Clo + r8 + col) = pack_lo(v2, v3);
    }
}

// ---------------------------------------------------------------------------
__global__ void __launch_bounds__(256)
xpose_split_kernel(const float* __restrict__ x,
                   __nv_bfloat16* __restrict__ hi, __nv_bfloat16* __restrict__ lo)
{
    __shared__ float s[32][33];
    const int b = blockIdx.z, k0 = blockIdx.y * 32, t0 = blockIdx.x * 32;
    const int tx = threadIdx.x & 31, ty = threadIdx.x >> 5;
    const float* src = x + ((size_t)b * HID + k0) * TDIM + t0;
#pragma unroll
    for (int i = 0; i < 4; ++i)
        s[ty + 8 * i][tx] = src[(size_t)(ty + 8 * i) * TDIM + tx];
    __syncthreads();
#pragma unroll
    for (int i = 0; i < 4; ++i) {
        const int t = ty + 8 * i;
        const float v = s[tx][t];
        const __nv_bfloat16 hh = __float2bfloat16_rn(v);
        const __nv_bfloat16 ll = __float2bfloat16_rn(v - __bfloat162float(hh));
        const size_t o = (size_t)(b * TDIM + t0 + t) * HID + k0 + tx;
        hi[o] = hh;
        lo[o] = ll;
    }
}

__global__ void __launch_bounds__(256)
split_kernel(const float* __restrict__ src,
             __nv_bfloat16* __restrict__ hi, __nv_bfloat16* __restrict__ lo, int n4)
{
    const int i = blockIdx.x * 256 + threadIdx.x;
    if (i >= n4) return;
    const float4 v = ((const float4*)src)[i];
    uint2 hp, lp;
    hp.x = pack_hi(v.x, v.y); hp.y = pack_hi(v.z, v.w);
    lp.x = pack_lo(v.x, v.y); lp.y = pack_lo(v.z, v.w);
    ((uint2*)hi)[i] = hp;
    ((uint2*)lo)[i] = lp;
}

// ---------------------------------------------------------------------------
extern "C" void kernel_launch(void* const* d_in, const int* in_sizes, int n_in,
                              void* d_out, int out_size)
{
    const float* x    = (const float*)d_in[0];
    const int*   mask = (const int*)d_in[1];
    const float* W[4] = { (const float*)d_in[2], (const float*)d_in[4],
                          (const float*)d_in[6], (const float*)d_in[8] };
    const float* bq   = (const float*)d_in[3];
    const float* bk   = (const float*)d_in[5];
    const float* bv   = (const float*)d_in[7];
    const float* bo   = (const float*)d_in[9];
    float* out = (float*)d_out;

    float* scr;
    __nv_bfloat16 *xhi, *xlo, *qhi, *qlo, *khi, *klo, *vhi, *vlo, *chi, *clo, *whi, *wlo;
    cudaGetSymbolAddress((void**)&scr, g_scr);
    cudaGetSymbolAddress((void**)&xhi, g_xhi);
    cudaGetSymbolAddress((void**)&xlo, g_xlo);
    cudaGetSymbolAddress((void**)&qhi, g_qhi);
    cudaGetSymbolAddress((void**)&qlo, g_qlo);
    cudaGetSymbolAddress((void**)&khi, g_khi);
    cudaGetSymbolAddress((void**)&klo, g_klo);
    cudaGetSymbolAddress((void**)&vhi, g_vhi);
    cudaGetSymbolAddress((void**)&vlo, g_vlo);
    cudaGetSymbolAddress((void**)&chi, g_chi);
    cudaGetSymbolAddress((void**)&clo, g_clo);
    cudaGetSymbolAddress((void**)&whi, g_whi);
    cudaGetSymbolAddress((void**)&wlo, g_wlo);

    cudaFuncSetAttribute(gemm_qkv_kernel,
                         cudaFuncAttributeMaxDynamicSharedMemorySize, GEMM_SMEM_BYTES);
    cudaFuncSetAttribute(gemm_omax_kernel,
                         cudaFuncAttributeMaxDynamicSharedMemorySize, GEMM_SMEM_BYTES);
    cudaFuncSetAttribute(attn_mma_kernel,
                         cudaFuncAttributeMaxDynamicSharedMemorySize, ATTN_SMEM_BYTES);

    const int wn4 = HID * HID / 4;
    for (int i = 0; i < 4; ++i)
        split_kernel<<<(wn4 + 255) / 256, 256>>>(W[i], whi + (size_t)i * HID * HID,
                                                 wlo + (size_t)i * HID * HID, wn4);
    xpose_split_kernel<<<dim3(TDIM / 32, HID / 32, BDIM), 256>>>(x, xhi, xlo);

    const size_t WSZ = (size_t)HID * HID;

    gemm_qkv_kernel<<<dim3(HID / 128, BT / 128, 3), 256, GEMM_SMEM_BYTES>>>(
        xhi, xlo, whi, wlo, bq, bk, bv, qhi, qlo, khi, klo, vhi, vlo);

    attn_mma_kernel<<<dim3(TDIM / 128, NH, BDIM), 256, ATTN_SMEM_BYTES>>>(
        qhi, qlo, khi, klo, vhi, vlo, mask, chi, clo);

    gemm_omax_kernel<<<dim3(HID / 128, BT / 128), 256, GEMM_SMEM_BYTES>>>(
        chi, clo, whi + 3 * WSZ, wlo + 3 * WSZ, scr);

    maxcombine_kernel<<<(BDIM * HID) / 256, 256>>>(scr, bo, out);
}

// round 7
// speedup vs baseline: 1.4976x; 1.2781x over previous
#include <cuda_runtime.h>
#include <cuda_bf16.h>
#include <cuda_fp16.h>
#include <cstdint>

#define BDIM 32
#define TDIM 512
#define HID  1024
#define NH   16
#define HD   64
#define BT   (BDIM * TDIM)   // 16384

// ------------------------- scratch (device globals) -------------------------
__device__ float         g_scr[(size_t)4 * BDIM * HID];   // o-proj partial maxes
__device__ __half        g_xhi[(size_t)BT * HID];
__device__ __half        g_xlo[(size_t)BT * HID];
__device__ __half        g_qhi[(size_t)BT * HID];
__device__ __half        g_qlo[(size_t)BT * HID];
__device__ __half        g_khi[(size_t)BT * HID];
__device__ __half        g_klo[(size_t)BT * HID];
__device__ __nv_bfloat16 g_vhi[(size_t)BT * HID];
__device__ __nv_bfloat16 g_vlo[(size_t)BT * HID];
__device__ __half        g_chi[(size_t)BT * HID];
__device__ __half        g_clo[(size_t)BT * HID];
__device__ __half        g_whf[(size_t)4 * HID * HID];    // fp16 weights (q,k,v,o)

// ------------------------------ PTX helpers --------------------------------
__device__ __forceinline__ uint32_t smem_u32(const void* p) {
    uint32_t a;
    asm("{ .reg .u64 t; cvta.to.shared.u64 t, %1; cvt.u32.u64 %0, t; }" : "=r"(a) : "l"(p));
    return a;
}
__device__ __forceinline__ void ldm_x4(uint32_t* r, uint32_t addr) {
    asm volatile("ldmatrix.sync.aligned.m8n8.x4.shared.b16 {%0,%1,%2,%3}, [%4];"
                 : "=r"(r[0]), "=r"(r[1]), "=r"(r[2]), "=r"(r[3]) : "r"(addr));
}
__device__ __forceinline__ void ldm_x4_t(uint32_t* r, uint32_t addr) {
    asm volatile("ldmatrix.sync.aligned.m8n8.x4.trans.shared.b16 {%0,%1,%2,%3}, [%4];"
                 : "=r"(r[0]), "=r"(r[1]), "=r"(r[2]), "=r"(r[3]) : "r"(addr));
}
// bf16 mma (used by attention PV)
__device__ __forceinline__ void mma_bf16(float* c, const uint32_t* a, const uint32_t* b) {
    asm volatile("mma.sync.aligned.m16n8k16.row.col.f32.bf16.bf16.f32 "
                 "{%0,%1,%2,%3}, {%4,%5,%6,%7}, {%8,%9}, {%0,%1,%2,%3};"
                 : "+f"(c[0]), "+f"(c[1]), "+f"(c[2]), "+f"(c[3])
                 : "r"(a[0]), "r"(a[1]), "r"(a[2]), "r"(a[3]), "r"(b[0]), "r"(b[1]));
}
// fp16 mma (projections + attention QK)
__device__ __forceinline__ void mma_f16(float* c, const uint32_t* a, const uint32_t* b) {
    asm volatile("mma.sync.aligned.m16n8k16.row.col.f32.f16.f16.f32 "
                 "{%0,%1,%2,%3}, {%4,%5,%6,%7}, {%8,%9}, {%0,%1,%2,%3};"
                 : "+f"(c[0]), "+f"(c[1]), "+f"(c[2]), "+f"(c[3])
                 : "r"(a[0]), "r"(a[1]), "r"(a[2]), "r"(a[3]), "r"(b[0]), "r"(b[1]));
}
#define CP_ASYNC16(saddr, gptr) \
    asm volatile("cp.async.cg.shared.global [%0], [%1], 16;" :: "r"(saddr), "l"(gptr))
#define CP_COMMIT() asm volatile("cp.async.commit_group;" ::: "memory")
#define CP_WAIT0()  asm volatile("cp.async.wait_group 0;" ::: "memory")

// bf16 packers (attention P / V path)
__device__ __forceinline__ uint32_t pack_hi(float a, float b) {
    __nv_bfloat162 h = __floats2bfloat162_rn(a, b);
    return *(uint32_t*)&h;
}
__device__ __forceinline__ uint32_t pack_lo(float a, float b) {
    float ra = a - __bfloat162float(__float2bfloat16_rn(a));
    float rb = b - __bfloat162float(__float2bfloat16_rn(b));
    __nv_bfloat162 l = __floats2bfloat162_rn(ra, rb);
    return *(uint32_t*)&l;
}
// fp16 packers
__device__ __forceinline__ uint32_t pack_h_hi(float a, float b) {
    __half2 h = __floats2half2_rn(a, b);
    return *(uint32_t*)&h;
}
__device__ __forceinline__ uint32_t pack_h_lo(float a, float b) {
    float ra = a - __half2float(__float2half_rn(a));
    float rb = b - __half2float(__float2half_rn(b));
    __half2 l = __floats2half2_rn(ra, rb);
    return *(uint32_t*)&l;
}

// ---------------------------------------------------------------------------
// fp16 2-term GEMM core: C = (Ah+Al) @ W^T   (fp32 acc)
// 128x128 tile, BK=32, 8 warps (2m x 4n), warp tile 64x32, 2-stage cp.async.
// smem: 2 stages x 3 operands x 10240 B = 61440 B  => 2 CTAs/SM.
// ---------------------------------------------------------------------------
#define BK      32
#define NCHUNK  (HID / BK)          // 32
#define PITCH   40                  // b16 elems per smem row (80B)
#define P2      (PITCH * 2)
#define TILE_B  (128 * P2)          // 10240 bytes
#define STAGE_B (3 * TILE_B)        // 30720
#define GEMM_SMEM_BYTES (2 * STAGE_B)

struct GemmCore {
    uint32_t sbase;
    int tid, wid, lane, wm, wn, m0, n0;
    float acc[4][4][4];

    __device__ __forceinline__ void init(uint32_t sb, int m, int n) {
        sbase = sb;
        tid = threadIdx.x; wid = tid >> 5; lane = tid & 31;
        wm = wid >> 2; wn = wid & 3;
        m0 = m; n0 = n;
#pragma unroll
        for (int i = 0; i < 4; ++i)
#pragma unroll
            for (int j = 0; j < 4; ++j)
#pragma unroll
                for (int e = 0; e < 4; ++e) acc[i][j][e] = 0.f;
    }

    __device__ __forceinline__ void issue_copy(
        const __half* Ah, const __half* Al, const __half* W, int c, int s)
    {
        const int k0 = c * BK;
        const uint32_t sb = sbase + s * STAGE_B;
#pragma unroll
        for (int op = 0; op < 3; ++op) {
            const __half* src = (op == 0) ? Ah : (op == 1) ? Al : W;
            const int rbase = (op < 2) ? m0 : n0;
#pragma unroll
            for (int i = 0; i < 2; ++i) {
                const int u   = i * 256 + tid;
                const int row = u >> 2;
                const int cv  = u & 3;
                const void* g = src + (size_t)(rbase + row) * HID + k0 + cv * 8;
                CP_ASYNC16(sb + op * TILE_B + row * P2 + cv * 16, g);
            }
        }
        CP_COMMIT();
    }

    __device__ __forceinline__ void compute(int s) {
        const uint32_t sb  = sbase + s * STAGE_B;
        const uint32_t aAh = sb;
        const uint32_t aAl = sb + TILE_B;
        const uint32_t aW  = sb + 2 * TILE_B;

        const int arow = wm * 64 + (lane & 15);
        const int acol = (lane >> 4) * 8;
        const int brow = wn * 32 + (lane & 7) + (lane >> 4) * 8;
        const int bcol = ((lane >> 3) & 1) * 8;

#pragma unroll
        for (int ks = 0; ks < 2; ++ks) {
            uint32_t ah[4][4], al[4][4];
#pragma unroll
            for (int i = 0; i < 4; ++i) {
                const uint32_t off = (arow + i * 16) * P2 + (ks * 16 + acol) * 2;
                ldm_x4(ah[i], aAh + off);
                ldm_x4(al[i], aAl + off);
            }
            uint32_t bw[8];
#pragma unroll
            for (int jj = 0; jj < 2; ++jj) {
                const uint32_t off = (brow + jj * 16) * P2 + (ks * 16 + bcol) * 2;
                ldm_x4(&bw[jj * 4], aW + off);
            }
#pragma unroll
            for (int i = 0; i < 4; ++i)
#pragma unroll
                for (int j = 0; j < 4; ++j) {
                    const int bi = (j >> 1) * 4 + (j & 1) * 2;
                    mma_f16(acc[i][j], ah[i], &bw[bi]);
                    mma_f16(acc[i][j], al[i], &bw[bi]);
                }
        }
    }

    __device__ __forceinline__ void mainloop(
        const __half* Ah, const __half* Al, const __half* W)
    {
        issue_copy(Ah, Al, W, 0, 0);
#pragma unroll 1
        for (int c = 0; c < NCHUNK; ++c) {
            CP_WAIT0();
            __syncthreads();
            if (c + 1 < NCHUNK) issue_copy(Ah, Al, W, c + 1, (c + 1) & 1);
            compute(c & 1);
            __syncthreads();
        }
    }
};

// ---- fused QKV: blockIdx.z selects weight/bias/dest. q,k -> fp16; v -> bf16 ----
__global__ void __launch_bounds__(256)
gemm_qkv_kernel(const __half* __restrict__ xhi, const __half* __restrict__ xlo,
                const __half* __restrict__ whf,
                const float* __restrict__ bq, const float* __restrict__ bk,
                const float* __restrict__ bv,
                __half* __restrict__ qhi, __half* __restrict__ qlo,
                __half* __restrict__ khi, __half* __restrict__ klo,
                __nv_bfloat16* __restrict__ vhi, __nv_bfloat16* __restrict__ vlo)
{
    extern __shared__ __align__(128) char smem[];
    const int z = blockIdx.z;
    const size_t WSZ = (size_t)HID * HID;
    const float* bias = (z == 0) ? bq : (z == 1) ? bk : bv;

    GemmCore g;
    g.init(smem_u32(smem), blockIdx.y * 128, blockIdx.x * 128);
    g.mainloop(xhi, xlo, whf + z * WSZ);

    __half* Hhi = (z == 0) ? qhi : khi;
    __half* Hlo = (z == 0) ? qlo : klo;

#pragma unroll
    for (int i = 0; i < 4; ++i) {
        const int r0 = g.m0 + g.wm * 64 + i * 16 + (g.lane >> 2);
#pragma unroll
        for (int j = 0; j < 4; ++j) {
            const int col = g.n0 + g.wn * 32 + j * 8 + (g.lane & 3) * 2;
            const float bx = bias[col], by = bias[col + 1];
            const float v0 = g.acc[i][j][0] + bx, v1 = g.acc[i][j][1] + by;
            const float v2 = g.acc[i][j][2] + bx, v3 = g.acc[i][j][3] + by;
            const size_t o0 = (size_t)r0 * HID + col;
            const size_t o1 = (size_t)(r0 + 8) * HID + col;
            if (z < 2) {
                *(uint32_t*)(Hhi + o0) = pack_h_hi(v0, v1);
                *(uint32_t*)(Hlo + o0) = pack_h_lo(v0, v1);
                *(uint32_t*)(Hhi + o1) = pack_h_hi(v2, v3);
                *(uint32_t*)(Hlo + o1) = pack_h_lo(v2, v3);
            } else {
                *(uint32_t*)(vhi + o0) = pack_hi(v0, v1);
                *(uint32_t*)(vlo + o0) = pack_lo(v0, v1);
                *(uint32_t*)(vhi + o1) = pack_hi(v2, v3);
                *(uint32_t*)(vlo + o1) = pack_lo(v2, v3);
            }
        }
    }
}

// ---- o-proj with fused column-max epilogue (bias added in combine) ----
__global__ void __launch_bounds__(256)
gemm_omax_kernel(const __half* __restrict__ chi, const __half* __restrict__ clo,
                 const __half* __restrict__ Wo, float* __restrict__ scr)
{
    extern __shared__ __align__(128) char smem[];
    GemmCore g;
    g.init(smem_u32(smem), blockIdx.y * 128, blockIdx.x * 128);
    g.mainloop(chi, clo, Wo);

    float* maxbuf = (float*)smem;   // [2][128] indexed by wm
#pragma unroll
    for (int j = 0; j < 4; ++j) {
        float c0 = -3.402823466e38f, c1 = c0;
#pragma unroll
        for (int i = 0; i < 4; ++i) {
            c0 = fmaxf(c0, fmaxf(g.acc[i][j][0], g.acc[i][j][2]));
            c1 = fmaxf(c1, fmaxf(g.acc[i][j][1], g.acc[i][j][3]));
        }
        c0 = fmaxf(c0, __shfl_xor_sync(0xffffffff, c0, 4));
        c0 = fmaxf(c0, __shfl_xor_sync(0xffffffff, c0, 8));
        c0 = fmaxf(c0, __shfl_xor_sync(0xffffffff, c0, 16));
        c1 = fmaxf(c1, __shfl_xor_sync(0xffffffff, c1, 4));
        c1 = fmaxf(c1, __shfl_xor_sync(0xffffffff, c1, 8));
        c1 = fmaxf(c1, __shfl_xor_sync(0xffffffff, c1, 16));
        if ((g.lane >> 2) == 0) {
            const int cc = g.wn * 32 + j * 8 + (g.lane & 3) * 2;
            maxbuf[g.wm * 128 + cc]     = c0;
            maxbuf[g.wm * 128 + cc + 1] = c1;
        }
    }
    __syncthreads();
    if (g.tid < 128) {
        const float f = fmaxf(maxbuf[g.tid], maxbuf[128 + g.tid]);
        const int b   = g.m0 >> 9;
        const int sub = (g.m0 >> 7) & 3;
        scr[((size_t)sub * BDIM + b) * HID + g.n0 + g.tid] = f;
    }
}

__global__ void __launch_bounds__(256)
maxcombine_kernel(const float* __restrict__ scr, const float* __restrict__ bias,
                  float* __restrict__ out)
{
    const int i = blockIdx.x * 256 + threadIdx.x;
    const float f = fmaxf(fmaxf(scr[i], scr[BDIM * HID + i]),
                          fmaxf(scr[2 * BDIM * HID + i], scr[3 * BDIM * HID + i]));
    out[i] = f + bias[i & (HID - 1)];
}

// ---------------------------------------------------------------------------
// Attention: QK fp16 3-term, softmax in regs, PV bf16 3-term, out fp16 hi/lo.
// ---------------------------------------------------------------------------
#define APITCH 72
#define AP2    (APITCH * 2)
#define SM_QH  0
#define SM_QL  (128 * AP2)
#define SM_KH  (2 * 128 * AP2)
#define SM_KL  (SM_KH + 64 * AP2)
#define SM_VH  (SM_KH + 2 * 64 * AP2)
#define SM_VL  (SM_KH + 3 * 64 * AP2)
#define SM_MSK (SM_KH + 4 * 64 * AP2)
#define ATTN_SMEM_BYTES (SM_MSK + 64 * 4)

__global__ void __launch_bounds__(256)
attn_mma_kernel(const __half* __restrict__ Qh, const __half* __restrict__ Ql,
                const __half* __restrict__ Kh, const __half* __restrict__ Kl,
                const __nv_bfloat16* __restrict__ Vh, const __nv_bfloat16* __restrict__ Vl,
                const int* __restrict__ mask,
                __half* __restrict__ Chi, __half* __restrict__ Clo)
{
    extern __shared__ __align__(128) char smem[];
    const uint32_t sb = smem_u32(smem);
    float* msk01 = (float*)(smem + SM_MSK);

    const int tid  = threadIdx.x;
    const int wid  = tid >> 5, lane = tid & 31;
    const int q0   = blockIdx.x * 128;
    const int h    = blockIdx.y;
    const int b    = blockIdx.z;
    const size_t rowbase = (size_t)b * TDIM;
    const int colbase = h * HD;

    {
#pragma unroll
        for (int op = 0; op < 2; ++op) {
            const __half* src = op ? Ql : Qh;
            const uint32_t so = sb + (op ? SM_QL : SM_QH);
#pragma unroll
            for (int i = 0; i < 4; ++i) {
                const int u = i * 256 + tid;
                const int r = u >> 3, cv = u & 7;
                const void* g = src + (rowbase + q0 + r) * HID + colbase + cv * 8;
                CP_ASYNC16(so + r * AP2 + cv * 16, g);
            }
        }
        CP_COMMIT();
    }

    float oacc[8][4];
#pragma unroll
    for (int j = 0; j < 8; ++j)
#pragma unroll
        for (int e = 0; e < 4; ++e) oacc[j][e] = 0.f;
    float den_r = 0.f, den_r8 = 0.f;

    const int qoff_row = (wid * 16 + (lane & 15)) * AP2;
    const int qoff_col = ((lane >> 4) * 8) * 2;
    const int koff_row = ((lane & 7) + (lane >> 4) * 8) * AP2;
    const int koff_col = (((lane >> 3) & 1) * 8) * 2;
    const int voff_row = ((lane & 15)) * AP2;
    const int voff_col = ((lane >> 4) * 8) * 2;

#pragma unroll 1
    for (int c = 0; c < 8; ++c) {
        const int k0 = c * 64;
        // K fp16 hi/lo
#pragma unroll
        for (int op = 0; op < 2; ++op) {
            const __half* src = op ? Kl : Kh;
            const uint32_t so = sb + SM_KH + op * (64 * AP2);
#pragma unroll
            for (int i = 0; i < 2; ++i) {
                const int u = i * 256 + tid;
                const int r = u >> 3, cv = u & 7;
                const void* g = src + (rowbase + k0 + r) * HID + colbase + cv * 8;
                CP_ASYNC16(so + r * AP2 + cv * 16, g);
            }
        }
        // V bf16 hi/lo
#pragma unroll
        for (int op = 0; op < 2; ++op) {
            const __nv_bfloat16* src = op ? Vl : Vh;
            const uint32_t so = sb + SM_VH + op * (64 * AP2);
#pragma unroll
            for (int i = 0; i < 2; ++i) {
                const int u = i * 256 + tid;
                const int r = u >> 3, cv = u & 7;
                const void* g = src + (rowbase + k0 + r) * HID + colbase + cv * 8;
                CP_ASYNC16(so + r * AP2 + cv * 16, g);
            }
        }
        CP_COMMIT();
        if (tid < 64) msk01[tid] = (float)mask[b * TDIM + k0 + tid];
        CP_WAIT0();
        __syncthreads();

        float sacc[8][4];
#pragma unroll
        for (int j = 0; j < 8; ++j)
#pragma unroll
            for (int e = 0; e < 4; ++e) sacc[j][e] = 0.f;

#pragma unroll
        for (int dk = 0; dk < 4; ++dk) {
            uint32_t ah[4], al[4];
            const uint32_t qa = sb + qoff_row + dk * 32 + qoff_col;
            ldm_x4(ah, qa + SM_QH);
            ldm_x4(al, qa + SM_QL);
#pragma unroll
            for (int kb = 0; kb < 4; ++kb) {
                uint32_t bh[4], bl[4];
                const uint32_t ka = sb + (kb * 16) * AP2 + koff_row + dk * 32 + koff_col;
                ldm_x4(bh, ka + SM_KH);
                ldm_x4(bl, ka + SM_KL);
                mma_f16(sacc[2 * kb],     ah, &bh[0]);
                mma_f16(sacc[2 * kb],     ah, &bl[0]);
                mma_f16(sacc[2 * kb],     al, &bh[0]);
                mma_f16(sacc[2 * kb + 1], ah, &bh[2]);
                mma_f16(sacc[2 * kb + 1], ah, &bl[2]);
                mma_f16(sacc[2 * kb + 1], al, &bh[2]);
            }
        }

        float dr = 0.f, dr8 = 0.f;
#pragma unroll
        for (int nt = 0; nt < 8; ++nt) {
            const int c0 = nt * 8 + (lane & 3) * 2;
            const float m0 = msk01[c0], m1 = msk01[c0 + 1];
#pragma unroll
            for (int e = 0; e < 4; ++e) {
                float s = sacc[nt][e] * 0.125f;
                s = fminf(fmaxf(s, -50.f), 50.f);
                s = ((e & 1) ? m1 : m0) * (s + 50.f) - 50.f;
                sacc[nt][e] = __expf(s);
            }
            dr  += sacc[nt][0] + sacc[nt][1];
            dr8 += sacc[nt][2] + sacc[nt][3];
        }
        dr  += __shfl_xor_sync(0xffffffff, dr, 1);
        dr  += __shfl_xor_sync(0xffffffff, dr, 2);
        dr8 += __shfl_xor_sync(0xffffffff, dr8, 1);
        dr8 += __shfl_xor_sync(0xffffffff, dr8, 2);
        den_r  += dr;
        den_r8 += dr8;

#pragma unroll
        for (int kb = 0; kb < 4; ++kb) {
            uint32_t pah[4], pal[4];
            const int t0 = 2 * kb, t1 = 2 * kb + 1;
            pah[0] = pack_hi(sacc[t0][0], sacc[t0][1]);
            pah[1] = pack_hi(sacc[t0][2], sacc[t0][3]);
            pah[2] = pack_hi(sacc[t1][0], sacc[t1][1]);
            pah[3] = pack_hi(sacc[t1][2], sacc[t1][3]);
            pal[0] = pack_lo(sacc[t0][0], sacc[t0][1]);
            pal[1] = pack_lo(sacc[t0][2], sacc[t0][3]);
            pal[2] = pack_lo(sacc[t1][0], sacc[t1][1]);
            pal[3] = pack_lo(sacc[t1][2], sacc[t1][3]);
#pragma unroll
            for (int dnp = 0; dnp < 4; ++dnp) {
                uint32_t vh[4], vl[4];
                const uint32_t va = sb + (kb * 16) * AP2 + voff_row + dnp * 32 + voff_col;
                ldm_x4_t(vh, va + SM_VH);
                ldm_x4_t(vl, va + SM_VL);
                mma_bf16(oacc[2 * dnp],     pah, &vh[0]);
                mma_bf16(oacc[2 * dnp],     pah, &vl[0]);
                mma_bf16(oacc[2 * dnp],     pal, &vh[0]);
                mma_bf16(oacc[2 * dnp + 1], pah, &vh[2]);
                mma_bf16(oacc[2 * dnp + 1], pah, &vl[2]);
                mma_bf16(oacc[2 * dnp + 1], pal, &vh[2]);
            }
        }
        __syncthreads();
    }

    const float invr  = 1.f / den_r;
    const float invr8 = 1.f / den_r8;
    const size_t r0 = (rowbase + q0 + wid * 16 + (lane >> 2)) * HID + colbase;
    const size_t r8 = r0 + 8 * HID;
#pragma unroll
    for (int dn = 0; dn < 8; ++dn) {
        const int col = dn * 8 + (lane & 3) * 2;
        const float v0 = oacc[dn][0] * invr,  v1 = oacc[dn][1] * invr;
        const float v2 = oacc[dn][2] * invr8, v3 = oacc[dn][3] * invr8;
        *(uint32_t*)(Chi + r0 + col) = pack_h_hi(v0, v1);
        *(uint32_t*)(Clo + r0 + col) = pack_h_lo(v0, v1);
        *(uint32_t*)(Chi + r8 + col) = pack_h_hi(v2, v3);
        *(uint32_t*)(Clo + r8 + col) = pack_h_lo(v2, v3);
    }
}

// ---------------------------------------------------------------------------
// x [B, HID, T] fp32 -> transpose to [BT, HID] + split into fp16 hi/lo
// ---------------------------------------------------------------------------
__global__ void __launch_bounds__(256)
xpose_split_kernel(const float* __restrict__ x,
                   __half* __restrict__ hi, __half* __restrict__ lo)
{
    __shared__ float s[32][33];
    const int b = blockIdx.z, k0 = blockIdx.y * 32, t0 = blockIdx.x * 32;
    const int tx = threadIdx.x & 31, ty = threadIdx.x >> 5;
    const float* src = x + ((size_t)b * HID + k0) * TDIM + t0;
#pragma unroll
    for (int i = 0; i < 4; ++i)
        s[ty + 8 * i][tx] = src[(size_t)(ty + 8 * i) * TDIM + tx];
    __syncthreads();
#pragma unroll
    for (int i = 0; i < 4; ++i) {
        const int t = ty + 8 * i;
        const float v = s[tx][t];
        const __half hh = __float2half_rn(v);
        const __half ll = __float2half_rn(v - __half2float(hh));
        const size_t o = (size_t)(b * TDIM + t0 + t) * HID + k0 + tx;
        hi[o] = hh;
        lo[o] = ll;
    }
}

// W fp32 -> fp16 (single array), vectorized x4
__global__ void __launch_bounds__(256)
wconv_kernel(const float* __restrict__ src, __half* __restrict__ dst, int n4)
{
    const int i = blockIdx.x * 256 + threadIdx.x;
    if (i >= n4) return;
    const float4 v = ((const float4*)src)[i];
    uint2 hp;
    hp.x = pack_h_hi(v.x, v.y);
    hp.y = pack_h_hi(v.z, v.w);
    ((uint2*)dst)[i] = hp;
}

// ---------------------------------------------------------------------------
extern "C" void kernel_launch(void* const* d_in, const int* in_sizes, int n_in,
                              void* d_out, int out_size)
{
    const float* x    = (const float*)d_in[0];
    const int*   mask = (const int*)d_in[1];
    const float* W[4] = { (const float*)d_in[2], (const float*)d_in[4],
                          (const float*)d_in[6], (const float*)d_in[8] };
    const float* bq   = (const float*)d_in[3];
    const float* bk   = (const float*)d_in[5];
    const float* bv   = (const float*)d_in[7];
    const float* bo   = (const float*)d_in[9];
    float* out = (float*)d_out;

    float* scr;
    __half *xhi, *xlo, *qhi, *qlo, *khi, *klo, *chi, *clo, *whf;
    __nv_bfloat16 *vhi, *vlo;
    cudaGetSymbolAddress((void**)&scr, g_scr);
    cudaGetSymbolAddress((void**)&xhi, g_xhi);
    cudaGetSymbolAddress((void**)&xlo, g_xlo);
    cudaGetSymbolAddress((void**)&qhi, g_qhi);
    cudaGetSymbolAddress((void**)&qlo, g_qlo);
    cudaGetSymbolAddress((void**)&khi, g_khi);
    cudaGetSymbolAddress((void**)&klo, g_klo);
    cudaGetSymbolAddress((void**)&vhi, g_vhi);
    cudaGetSymbolAddress((void**)&vlo, g_vlo);
    cudaGetSymbolAddress((void**)&chi, g_chi);
    cudaGetSymbolAddress((void**)&clo, g_clo);
    cudaGetSymbolAddress((void**)&whf, g_whf);

    cudaFuncSetAttribute(gemm_qkv_kernel,
                         cudaFuncAttributeMaxDynamicSharedMemorySize, GEMM_SMEM_BYTES);
    cudaFuncSetAttribute(gemm_omax_kernel,
                         cudaFuncAttributeMaxDynamicSharedMemorySize, GEMM_SMEM_BYTES);
    cudaFuncSetAttribute(attn_mma_kernel,
                         cudaFuncAttributeMaxDynamicSharedMemorySize, ATTN_SMEM_BYTES);

    const int wn4 = HID * HID / 4;
    for (int i = 0; i < 4; ++i)
        wconv_kernel<<<(wn4 + 255) / 256, 256>>>(W[i], whf + (size_t)i * HID * HID, wn4);
    xpose_split_kernel<<<dim3(TDIM / 32, HID / 32, BDIM), 256>>>(x, xhi, xlo);

    const size_t WSZ = (size_t)HID * HID;

    gemm_qkv_kernel<<<dim3(HID / 128, BT / 128, 3), 256, GEMM_SMEM_BYTES>>>(
        xhi, xlo, whf, bq, bk, bv, qhi, qlo, khi, klo, vhi, vlo);

    attn_mma_kernel<<<dim3(TDIM / 128, NH, BDIM), 256, ATTN_SMEM_BYTES>>>(
        qhi, qlo, khi, klo, vhi, vlo, mask, chi, clo);

    gemm_omax_kernel<<<dim3(HID / 128, BT / 128), 256, GEMM_SMEM_BYTES>>>(
        chi, clo, whf + 3 * WSZ, scr);

    maxcombine_kernel<<<(BDIM * HID) / 256, 256>>>(scr, bo, out);
}

// round 8
// speedup vs baseline: 2.1477x; 1.4341x over previous
#include <cuda_runtime.h>
#include <cuda_bf16.h>
#include <cuda_fp16.h>
#include <cstdint>

#define BDIM 32
#define TDIM 512
#define HID  1024
#define NH   16
#define HD   64
#define BT   (BDIM * TDIM)   // 16384

// ------------------------- scratch (device globals) -------------------------
__device__ float         g_scr[(size_t)4 * BDIM * HID];   // o-proj partial maxes
__device__ __half        g_xh [(size_t)BT * HID];
__device__ __half        g_qhi[(size_t)BT * HID];
__device__ __half        g_qlo[(size_t)BT * HID];
__device__ __half        g_khi[(size_t)BT * HID];
__device__ __half        g_klo[(size_t)BT * HID];
__device__ __nv_bfloat16 g_vhi[(size_t)BT * HID];
__device__ __nv_bfloat16 g_vlo[(size_t)BT * HID];
__device__ __half        g_ch [(size_t)BT * HID];
__device__ __half        g_whf[(size_t)4 * HID * HID];    // fp16 weights (q,k,v,o)

// ------------------------------ PTX helpers --------------------------------
__device__ __forceinline__ uint32_t smem_u32(const void* p) {
    uint32_t a;
    asm("{ .reg .u64 t; cvta.to.shared.u64 t, %1; cvt.u32.u64 %0, t; }" : "=r"(a) : "l"(p));
    return a;
}
__device__ __forceinline__ void ldm_x4(uint32_t* r, uint32_t addr) {
    asm volatile("ldmatrix.sync.aligned.m8n8.x4.shared.b16 {%0,%1,%2,%3}, [%4];"
                 : "=r"(r[0]), "=r"(r[1]), "=r"(r[2]), "=r"(r[3]) : "r"(addr));
}
__device__ __forceinline__ void ldm_x4_t(uint32_t* r, uint32_t addr) {
    asm volatile("ldmatrix.sync.aligned.m8n8.x4.trans.shared.b16 {%0,%1,%2,%3}, [%4];"
                 : "=r"(r[0]), "=r"(r[1]), "=r"(r[2]), "=r"(r[3]) : "r"(addr));
}
__device__ __forceinline__ void mma_bf16(float* c, const uint32_t* a, const uint32_t* b) {
    asm volatile("mma.sync.aligned.m16n8k16.row.col.f32.bf16.bf16.f32 "
                 "{%0,%1,%2,%3}, {%4,%5,%6,%7}, {%8,%9}, {%0,%1,%2,%3};"
                 : "+f"(c[0]), "+f"(c[1]), "+f"(c[2]), "+f"(c[3])
                 : "r"(a[0]), "r"(a[1]), "r"(a[2]), "r"(a[3]), "r"(b[0]), "r"(b[1]));
}
__device__ __forceinline__ void mma_f16(float* c, const uint32_t* a, const uint32_t* b) {
    asm volatile("mma.sync.aligned.m16n8k16.row.col.f32.f16.f16.f32 "
                 "{%0,%1,%2,%3}, {%4,%5,%6,%7}, {%8,%9}, {%0,%1,%2,%3};"
                 : "+f"(c[0]), "+f"(c[1]), "+f"(c[2]), "+f"(c[3])
                 : "r"(a[0]), "r"(a[1]), "r"(a[2]), "r"(a[3]), "r"(b[0]), "r"(b[1]));
}
#define CP_ASYNC16(saddr, gptr) \
    asm volatile("cp.async.cg.shared.global [%0], [%1], 16;" :: "r"(saddr), "l"(gptr))
#define CP_COMMIT() asm volatile("cp.async.commit_group;" ::: "memory")
#define CP_WAIT0()  asm volatile("cp.async.wait_group 0;" ::: "memory")

__device__ __forceinline__ uint32_t pack_hi(float a, float b) {
    __nv_bfloat162 h = __floats2bfloat162_rn(a, b);
    return *(uint32_t*)&h;
}
__device__ __forceinline__ uint32_t pack_lo(float a, float b) {
    float ra = a - __bfloat162float(__float2bfloat16_rn(a));
    float rb = b - __bfloat162float(__float2bfloat16_rn(b));
    __nv_bfloat162 l = __floats2bfloat162_rn(ra, rb);
    return *(uint32_t*)&l;
}
__device__ __forceinline__ uint32_t pack_h_hi(float a, float b) {
    __half2 h = __floats2half2_rn(a, b);
    return *(uint32_t*)&h;
}
__device__ __forceinline__ uint32_t pack_h_lo(float a, float b) {
    float ra = a - __half2float(__float2half_rn(a));
    float rb = b - __half2float(__float2half_rn(b));
    __half2 l = __floats2half2_rn(ra, rb);
    return *(uint32_t*)&l;
}

// ---------------------------------------------------------------------------
// Plain fp16 GEMM core: C = A @ W^T   (fp32 acc)
// 128x128 tile, BK=32, 8 warps (2m x 4n), warp tile 64x32, 2-stage cp.async.
// smem: 2 stages x 2 operands x 10240 B = 40960 B  => 2+ CTAs/SM.
// ---------------------------------------------------------------------------
#define BK      32
#define NCHUNK  (HID / BK)          // 32
#define PITCH   40                  // b16 elems per smem row (80B)
#define P2      (PITCH * 2)
#define TILE_B  (128 * P2)          // 10240 bytes
#define STAGE_B (2 * TILE_B)        // 20480
#define GEMM_SMEM_BYTES (2 * STAGE_B)

struct GemmCore {
    uint32_t sbase;
    int tid, wid, lane, wm, wn, m0, n0;
    float acc[4][4][4];

    __device__ __forceinline__ void init(uint32_t sb, int m, int n) {
        sbase = sb;
        tid = threadIdx.x; wid = tid >> 5; lane = tid & 31;
        wm = wid >> 2; wn = wid & 3;
        m0 = m; n0 = n;
#pragma unroll
        for (int i = 0; i < 4; ++i)
#pragma unroll
            for (int j = 0; j < 4; ++j)
#pragma unroll
                for (int e = 0; e < 4; ++e) acc[i][j][e] = 0.f;
    }

    __device__ __forceinline__ void issue_copy(
        const __half* A, const __half* W, int c, int s)
    {
        const int k0 = c * BK;
        const uint32_t sb = sbase + s * STAGE_B;
#pragma unroll
        for (int op = 0; op < 2; ++op) {
            const __half* src = (op == 0) ? A : W;
            const int rbase = (op == 0) ? m0 : n0;
#pragma unroll
            for (int i = 0; i < 2; ++i) {
                const int u   = i * 256 + tid;
                const int row = u >> 2;
                const int cv  = u & 3;
                const void* g = src + (size_t)(rbase + row) * HID + k0 + cv * 8;
                CP_ASYNC16(sb + op * TILE_B + row * P2 + cv * 16, g);
            }
        }
        CP_COMMIT();
    }

    __device__ __forceinline__ void compute(int s) {
        const uint32_t sb = sbase + s * STAGE_B;
        const uint32_t aA = sb;
        const uint32_t aW = sb + TILE_B;

        const int arow = wm * 64 + (lane & 15);
        const int acol = (lane >> 4) * 8;
        const int brow = wn * 32 + (lane & 7) + (lane >> 4) * 8;
        const int bcol = ((lane >> 3) & 1) * 8;

#pragma unroll
        for (int ks = 0; ks < 2; ++ks) {
            uint32_t a[4][4];
#pragma unroll
            for (int i = 0; i < 4; ++i) {
                const uint32_t off = (arow + i * 16) * P2 + (ks * 16 + acol) * 2;
                ldm_x4(a[i], aA + off);
            }
            uint32_t bw[8];
#pragma unroll
            for (int jj = 0; jj < 2; ++jj) {
                const uint32_t off = (brow + jj * 16) * P2 + (ks * 16 + bcol) * 2;
                ldm_x4(&bw[jj * 4], aW + off);
            }
#pragma unroll
            for (int i = 0; i < 4; ++i)
#pragma unroll
                for (int j = 0; j < 4; ++j) {
                    const int bi = (j >> 1) * 4 + (j & 1) * 2;
                    mma_f16(acc[i][j], a[i], &bw[bi]);
                }
        }
    }

    __device__ __forceinline__ void mainloop(const __half* A, const __half* W)
    {
        issue_copy(A, W, 0, 0);
#pragma unroll 1
        for (int c = 0; c < NCHUNK; ++c) {
            CP_WAIT0();
            __syncthreads();
            if (c + 1 < NCHUNK) issue_copy(A, W, c + 1, (c + 1) & 1);
            compute(c & 1);
            __syncthreads();
        }
    }
};

// ---- fused QKV: blockIdx.z selects weight/bias/dest. q,k -> fp16 hi/lo; v -> bf16 hi/lo ----
__global__ void __launch_bounds__(256)
gemm_qkv_kernel(const __half* __restrict__ xh, const __half* __restrict__ whf,
                const float* __restrict__ bq, const float* __restrict__ bk,
                const float* __restrict__ bv,
                __half* __restrict__ qhi, __half* __restrict__ qlo,
                __half* __restrict__ khi, __half* __restrict__ klo,
                __nv_bfloat16* __restrict__ vhi, __nv_bfloat16* __restrict__ vlo)
{
    extern __shared__ __align__(128) char smem[];
    const int z = blockIdx.z;
    const size_t WSZ = (size_t)HID * HID;
    const float* bias = (z == 0) ? bq : (z == 1) ? bk : bv;

    GemmCore g;
    g.init(smem_u32(smem), blockIdx.y * 128, blockIdx.x * 128);
    g.mainloop(xh, whf + z * WSZ);

    __half* Hhi = (z == 0) ? qhi : khi;
    __half* Hlo = (z == 0) ? qlo : klo;

#pragma unroll
    for (int i = 0; i < 4; ++i) {
        const int r0 = g.m0 + g.wm * 64 + i * 16 + (g.lane >> 2);
#pragma unroll
        for (int j = 0; j < 4; ++j) {
            const int col = g.n0 + g.wn * 32 + j * 8 + (g.lane & 3) * 2;
            const float bx = bias[col], by = bias[col + 1];
            const float v0 = g.acc[i][j][0] + bx, v1 = g.acc[i][j][1] + by;
            const float v2 = g.acc[i][j][2] + bx, v3 = g.acc[i][j][3] + by;
            const size_t o0 = (size_t)r0 * HID + col;
            const size_t o1 = (size_t)(r0 + 8) * HID + col;
            if (z < 2) {
                *(uint32_t*)(Hhi + o0) = pack_h_hi(v0, v1);
                *(uint32_t*)(Hlo + o0) = pack_h_lo(v0, v1);
                *(uint32_t*)(Hhi + o1) = pack_h_hi(v2, v3);
                *(uint32_t*)(Hlo + o1) = pack_h_lo(v2, v3);
            } else {
                *(uint32_t*)(vhi + o0) = pack_hi(v0, v1);
                *(uint32_t*)(vlo + o0) = pack_lo(v0, v1);
                *(uint32_t*)(vhi + o1) = pack_hi(v2, v3);
                *(uint32_t*)(vlo + o1) = pack_lo(v2, v3);
            }
        }
    }
}

// ---- o-proj with fused column-max epilogue (bias added in combine) ----
__global__ void __launch_bounds__(256)
gemm_omax_kernel(const __half* __restrict__ ch, const __half* __restrict__ Wo,
                 float* __restrict__ scr)
{
    extern __shared__ __align__(128) char smem[];
    GemmCore g;
    g.init(smem_u32(smem), blockIdx.y * 128, blockIdx.x * 128);
    g.mainloop(ch, Wo);

    float* maxbuf = (float*)smem;   // [2][128] indexed by wm
#pragma unroll
    for (int j = 0; j < 4; ++j) {
        float c0 = -3.402823466e38f, c1 = c0;
#pragma unroll
        for (int i = 0; i < 4; ++i) {
            c0 = fmaxf(c0, fmaxf(g.acc[i][j][0], g.acc[i][j][2]));
            c1 = fmaxf(c1, fmaxf(g.acc[i][j][1], g.acc[i][j][3]));
        }
        c0 = fmaxf(c0, __shfl_xor_sync(0xffffffff, c0, 4));
        c0 = fmaxf(c0, __shfl_xor_sync(0xffffffff, c0, 8));
        c0 = fmaxf(c0, __shfl_xor_sync(0xffffffff, c0, 16));
        c1 = fmaxf(c1, __shfl_xor_sync(0xffffffff, c1, 4));
        c1 = fmaxf(c1, __shfl_xor_sync(0xffffffff, c1, 8));
        c1 = fmaxf(c1, __shfl_xor_sync(0xffffffff, c1, 16));
        if ((g.lane >> 2) == 0) {
            const int cc = g.wn * 32 + j * 8 + (g.lane & 3) * 2;
            maxbuf[g.wm * 128 + cc]     = c0;
            maxbuf[g.wm * 128 + cc + 1] = c1;
        }
    }
    __syncthreads();
    if (g.tid < 128) {
        const float f = fmaxf(maxbuf[g.tid], maxbuf[128 + g.tid]);
        const int b   = g.m0 >> 9;
        const int sub = (g.m0 >> 7) & 3;
        scr[((size_t)sub * BDIM + b) * HID + g.n0 + g.tid] = f;
    }
}

__global__ void __launch_bounds__(256)
maxcombine_kernel(const float* __restrict__ scr, const float* __restrict__ bias,
                  float* __restrict__ out)
{
    const int i = blockIdx.x * 256 + threadIdx.x;
    const float f = fmaxf(fmaxf(scr[i], scr[BDIM * HID + i]),
                          fmaxf(scr[2 * BDIM * HID + i], scr[3 * BDIM * HID + i]));
    out[i] = f + bias[i & (HID - 1)];
}

// ---------------------------------------------------------------------------
// Attention: QK fp16 3-term, softmax in regs, PV bf16 3-term, ctx single fp16.
// ---------------------------------------------------------------------------
#define APITCH 72
#define AP2    (APITCH * 2)
#define SM_QH  0
#define SM_QL  (128 * AP2)
#define SM_KH  (2 * 128 * AP2)
#define SM_KL  (SM_KH + 64 * AP2)
#define SM_VH  (SM_KH + 2 * 64 * AP2)
#define SM_VL  (SM_KH + 3 * 64 * AP2)
#define SM_MSK (SM_KH + 4 * 64 * AP2)
#define ATTN_SMEM_BYTES (SM_MSK + 64 * 4)

__global__ void __launch_bounds__(256)
attn_mma_kernel(const __half* __restrict__ Qh, const __half* __restrict__ Ql,
                const __half* __restrict__ Kh, const __half* __restrict__ Kl,
                const __nv_bfloat16* __restrict__ Vh, const __nv_bfloat16* __restrict__ Vl,
                const int* __restrict__ mask, __half* __restrict__ Ch)
{
    extern __shared__ __align__(128) char smem[];
    const uint32_t sb = smem_u32(smem);
    float* msk01 = (float*)(smem + SM_MSK);

    const int tid  = threadIdx.x;
    const int wid  = tid >> 5, lane = tid & 31;
    const int q0   = blockIdx.x * 128;
    const int h    = blockIdx.y;
    const int b    = blockIdx.z;
    const size_t rowbase = (size_t)b * TDIM;
    const int colbase = h * HD;

    {
#pragma unroll
        for (int op = 0; op < 2; ++op) {
            const __half* src = op ? Ql : Qh;
            const uint32_t so = sb + (op ? SM_QL : SM_QH);
#pragma unroll
            for (int i = 0; i < 4; ++i) {
                const int u = i * 256 + tid;
                const int r = u >> 3, cv = u & 7;
                const void* g = src + (rowbase + q0 + r) * HID + colbase + cv * 8;
                CP_ASYNC16(so + r * AP2 + cv * 16, g);
            }
        }
        CP_COMMIT();
    }

    float oacc[8][4];
#pragma unroll
    for (int j = 0; j < 8; ++j)
#pragma unroll
        for (int e = 0; e < 4; ++e) oacc[j][e] = 0.f;
    float den_r = 0.f, den_r8 = 0.f;

    const int qoff_row = (wid * 16 + (lane & 15)) * AP2;
    const int qoff_col = ((lane >> 4) * 8) * 2;
    const int koff_row = ((lane & 7) + (lane >> 4) * 8) * AP2;
    const int koff_col = (((lane >> 3) & 1) * 8) * 2;
    const int voff_row = ((lane & 15)) * AP2;
    const int voff_col = ((lane >> 4) * 8) * 2;

#pragma unroll 1
    for (int c = 0; c < 8; ++c) {
        const int k0 = c * 64;
#pragma unroll
        for (int op = 0; op < 2; ++op) {
            const __half* src = op ? Kl : Kh;
            const uint32_t so = sb + SM_KH + op * (64 * AP2);
#pragma unroll
            for (int i = 0; i < 2; ++i) {
                const int u = i * 256 + tid;
                const int r = u >> 3, cv = u & 7;
                const void* g = src + (rowbase + k0 + r) * HID + colbase + cv * 8;
                CP_ASYNC16(so + r * AP2 + cv * 16, g);
            }
        }
#pragma unroll
        for (int op = 0; op < 2; ++op) {
            const __nv_bfloat16* src = op ? Vl : Vh;
            const uint32_t so = sb + SM_VH + op * (64 * AP2);
#pragma unroll
            for (int i = 0; i < 2; ++i) {
                const int u = i * 256 + tid;
                const int r = u >> 3, cv = u & 7;
                const void* g = src + (rowbase + k0 + r) * HID + colbase + cv * 8;
                CP_ASYNC16(so + r * AP2 + cv * 16, g);
            }
        }
        CP_COMMIT();
        if (tid < 64) msk01[tid] = (float)mask[b * TDIM + k0 + tid];
        CP_WAIT0();
        __syncthreads();

        float sacc[8][4];
#pragma unroll
        for (int j = 0; j < 8; ++j)
#pragma unroll
            for (int e = 0; e < 4; ++e) sacc[j][e] = 0.f;

#pragma unroll
        for (int dk = 0; dk < 4; ++dk) {
            uint32_t ah[4], al[4];
            const uint32_t qa = sb + qoff_row + dk * 32 + qoff_col;
            ldm_x4(ah, qa + SM_QH);
            ldm_x4(al, qa + SM_QL);
#pragma unroll
            for (int kb = 0; kb < 4; ++kb) {
                uint32_t bh[4], bl[4];
                const uint32_t ka = sb + (kb * 16) * AP2 + koff_row + dk * 32 + koff_col;
                ldm_x4(bh, ka + SM_KH);
                ldm_x4(bl, ka + SM_KL);
                mma_f16(sacc[2 * kb],     ah, &bh[0]);
                mma_f16(sacc[2 * kb],     ah, &bl[0]);
                mma_f16(sacc[2 * kb],     al, &bh[0]);
                mma_f16(sacc[2 * kb + 1], ah, &bh[2]);
                mma_f16(sacc[2 * kb + 1], ah, &bl[2]);
                mma_f16(sacc[2 * kb + 1], al, &bh[2]);
            }
        }

        float dr = 0.f, dr8 = 0.f;
#pragma unroll
        for (int nt = 0; nt < 8; ++nt) {
            const int c0 = nt * 8 + (lane & 3) * 2;
            const float m0 = msk01[c0], m1 = msk01[c0 + 1];
#pragma unroll
            for (int e = 0; e < 4; ++e) {
                float s = sacc[nt][e] * 0.125f;
                s = fminf(fmaxf(s, -50.f), 50.f);
                s = ((e & 1) ? m1 : m0) * (s + 50.f) - 50.f;
                sacc[nt][e] = __expf(s);
            }
            dr  += sacc[nt][0] + sacc[nt][1];
            dr8 += sacc[nt][2] + sacc[nt][3];
        }
        dr  += __shfl_xor_sync(0xffffffff, dr, 1);
        dr  += __shfl_xor_sync(0xffffffff, dr, 2);
        dr8 += __shfl_xor_sync(0xffffffff, dr8, 1);
        dr8 += __shfl_xor_sync(0xffffffff, dr8, 2);
        den_r  += dr;
        den_r8 += dr8;

#pragma unroll
        for (int kb = 0; kb < 4; ++kb) {
            uint32_t pah[4], pal[4];
            const int t0 = 2 * kb, t1 = 2 * kb + 1;
            pah[0] = pack_hi(sacc[t0][0], sacc[t0][1]);
            pah[1] = pack_hi(sacc[t0][2], sacc[t0][3]);
            pah[2] = pack_hi(sacc[t1][0], sacc[t1][1]);
            pah[3] = pack_hi(sacc[t1][2], sacc[t1][3]);
            pal[0] = pack_lo(sacc[t0][0], sacc[t0][1]);
            pal[1] = pack_lo(sacc[t0][2], sacc[t0][3]);
            pal[2] = pack_lo(sacc[t1][0], sacc[t1][1]);
            pal[3] = pack_lo(sacc[t1][2], sacc[t1][3]);
#pragma unroll
            for (int dnp = 0; dnp < 4; ++dnp) {
                uint32_t vh[4], vl[4];
                const uint32_t va = sb + (kb * 16) * AP2 + voff_row + dnp * 32 + voff_col;
                ldm_x4_t(vh, va + SM_VH);
                ldm_x4_t(vl, va + SM_VL);
                mma_bf16(oacc[2 * dnp],     pah, &vh[0]);
                mma_bf16(oacc[2 * dnp],     pah, &vl[0]);
                mma_bf16(oacc[2 * dnp],     pal, &vh[0]);
                mma_bf16(oacc[2 * dnp + 1], pah, &vh[2]);
                mma_bf16(oacc[2 * dnp + 1], pah, &vl[2]);
                mma_bf16(oacc[2 * dnp + 1], pal, &vh[2]);
            }
        }
        __syncthreads();
    }

    const float invr  = 1.f / den_r;
    const float invr8 = 1.f / den_r8;
    const size_t r0 = (rowbase + q0 + wid * 16 + (lane >> 2)) * HID + colbase;
    const size_t r8 = r0 + 8 * HID;
#pragma unroll
    for (int dn = 0; dn < 8; ++dn) {
        const int col = dn * 8 + (lane & 3) * 2;
        *(uint32_t*)(Ch + r0 + col) = pack_h_hi(oacc[dn][0] * invr,  oacc[dn][1] * invr);
        *(uint32_t*)(Ch + r8 + col) = pack_h_hi(oacc[dn][2] * invr8, oacc[dn][3] * invr8);
    }
}

// ---------------------------------------------------------------------------
// x [B, HID, T] fp32 -> transpose to [BT, HID], single fp16
// ---------------------------------------------------------------------------
__global__ void __launch_bounds__(256)
xpose_kernel(const float* __restrict__ x, __half* __restrict__ xh)
{
    __shared__ float s[32][33];
    const int b = blockIdx.z, k0 = blockIdx.y * 32, t0 = blockIdx.x * 32;
    const int tx = threadIdx.x & 31, ty = threadIdx.x >> 5;
    const float* src = x + ((size_t)b * HID + k0) * TDIM + t0;
#pragma unroll
    for (int i = 0; i < 4; ++i)
        s[ty + 8 * i][tx] = src[(size_t)(ty + 8 * i) * TDIM + tx];
    __syncthreads();
#pragma unroll
    for (int i = 0; i < 4; ++i) {
        const int t = ty + 8 * i;
        const size_t o = (size_t)(b * TDIM + t0 + t) * HID + k0 + tx;
        xh[o] = __float2half_rn(s[tx][t]);
    }
}

// W fp32 -> fp16 (single array), vectorized x4
__global__ void __launch_bounds__(256)
wconv_kernel(const float* __restrict__ src, __half* __restrict__ dst, int n4)
{
    const int i = blockIdx.x * 256 + threadIdx.x;
    if (i >= n4) return;
    const float4 v = ((const float4*)src)[i];
    uint2 hp;
    hp.x = pack_h_hi(v.x, v.y);
    hp.y = pack_h_hi(v.z, v.w);
    ((uint2*)dst)[i] = hp;
}

// ---------------------------------------------------------------------------
extern "C" void kernel_launch(void* const* d_in, const int* in_sizes, int n_in,
                              void* d_out, int out_size)
{
    const float* x    = (const float*)d_in[0];
    const int*   mask = (const int*)d_in[1];
    const float* W[4] = { (const float*)d_in[2], (const float*)d_in[4],
                          (const float*)d_in[6], (const float*)d_in[8] };
    const float* bq   = (const float*)d_in[3];
    const float* bk   = (const float*)d_in[5];
    const float* bv   = (const float*)d_in[7];
    const float* bo   = (const float*)d_in[9];
    float* out = (float*)d_out;

    float* scr;
    __half *xh, *qhi, *qlo, *khi, *klo, *ch, *whf;
    __nv_bfloat16 *vhi, *vlo;
    cudaGetSymbolAddress((void**)&scr, g_scr);
    cudaGetSymbolAddress((void**)&xh,  g_xh);
    cudaGetSymbolAddress((void**)&qhi, g_qhi);
    cudaGetSymbolAddress((void**)&qlo, g_qlo);
    cudaGetSymbolAddress((void**)&khi, g_khi);
    cudaGetSymbolAddress((void**)&klo, g_klo);
    cudaGetSymbolAddress((void**)&vhi, g_vhi);
    cudaGetSymbolAddress((void**)&vlo, g_vlo);
    cudaGetSymbolAddress((void**)&ch,  g_ch);
    cudaGetSymbolAddress((void**)&whf, g_whf);

    cudaFuncSetAttribute(gemm_qkv_kernel,
                         cudaFuncAttributeMaxDynamicSharedMemorySize, GEMM_SMEM_BYTES);
    cudaFuncSetAttribute(gemm_omax_kernel,
                         cudaFuncAttributeMaxDynamicSharedMemorySize, GEMM_SMEM_BYTES);
    cudaFuncSetAttribute(attn_mma_kernel,
                         cudaFuncAttributeMaxDynamicSharedMemorySize, ATTN_SMEM_BYTES);

    const int wn4 = HID * HID / 4;
    for (int i = 0; i < 4; ++i)
        wconv_kernel<<<(wn4 + 255) / 256, 256>>>(W[i], whf + (size_t)i * HID * HID, wn4);
    xpose_kernel<<<dim3(TDIM / 32, HID / 32, BDIM), 256>>>(x, xh);

    const size_t WSZ = (size_t)HID * HID;

    gemm_qkv_kernel<<<dim3(HID / 128, BT / 128, 3), 256, GEMM_SMEM_BYTES>>>(
        xh, whf, bq, bk, bv, qhi, qlo, khi, klo, vhi, vlo);

    attn_mma_kernel<<<dim3(TDIM / 128, NH, BDIM), 256, ATTN_SMEM_BYTES>>>(
        qhi, qlo, khi, klo, vhi, vlo, mask, ch);

    gemm_omax_kernel<<<dim3(HID / 128, BT / 128), 256, GEMM_SMEM_BYTES>>>(
        ch, whf + 3 * WSZ, scr);

    maxcombine_kernel<<<(BDIM * HID) / 256, 256>>>(scr, bo, out);
}

// round 9
// speedup vs baseline: 2.4753x; 1.1525x over previous
#include <cuda_runtime.h>
#include <cuda_bf16.h>
#include <cuda_fp16.h>
#include <cstdint>

#define BDIM 32
#define TDIM 512
#define HID  1024
#define NH   16
#define HD   64
#define BT   (BDIM * TDIM)   // 16384

// ------------------------- scratch (device globals) -------------------------
__device__ float  g_scr[(size_t)4 * BDIM * HID];   // o-proj partial maxes
__device__ __half g_xh [(size_t)BT * HID];
__device__ __half g_qh [(size_t)BT * HID];
__device__ __half g_kh [(size_t)BT * HID];
__device__ __half g_vh [(size_t)BT * HID];
__device__ __half g_ch [(size_t)BT * HID];
__device__ __half g_whf[(size_t)4 * HID * HID];    // fp16 weights (q,k,v,o)

// ------------------------------ PTX helpers --------------------------------
__device__ __forceinline__ uint32_t smem_u32(const void* p) {
    uint32_t a;
    asm("{ .reg .u64 t; cvta.to.shared.u64 t, %1; cvt.u32.u64 %0, t; }" : "=r"(a) : "l"(p));
    return a;
}
__device__ __forceinline__ void ldm_x4(uint32_t* r, uint32_t addr) {
    asm volatile("ldmatrix.sync.aligned.m8n8.x4.shared.b16 {%0,%1,%2,%3}, [%4];"
                 : "=r"(r[0]), "=r"(r[1]), "=r"(r[2]), "=r"(r[3]) : "r"(addr));
}
__device__ __forceinline__ void ldm_x4_t(uint32_t* r, uint32_t addr) {
    asm volatile("ldmatrix.sync.aligned.m8n8.x4.trans.shared.b16 {%0,%1,%2,%3}, [%4];"
                 : "=r"(r[0]), "=r"(r[1]), "=r"(r[2]), "=r"(r[3]) : "r"(addr));
}
__device__ __forceinline__ void mma_f16(float* c, const uint32_t* a, const uint32_t* b) {
    asm volatile("mma.sync.aligned.m16n8k16.row.col.f32.f16.f16.f32 "
                 "{%0,%1,%2,%3}, {%4,%5,%6,%7}, {%8,%9}, {%0,%1,%2,%3};"
                 : "+f"(c[0]), "+f"(c[1]), "+f"(c[2]), "+f"(c[3])
                 : "r"(a[0]), "r"(a[1]), "r"(a[2]), "r"(a[3]), "r"(b[0]), "r"(b[1]));
}
#define CP_ASYNC16(saddr, gptr) \
    asm volatile("cp.async.cg.shared.global [%0], [%1], 16;" :: "r"(saddr), "l"(gptr))
#define CP_COMMIT() asm volatile("cp.async.commit_group;" ::: "memory")
#define CP_WAIT0()  asm volatile("cp.async.wait_group 0;" ::: "memory")
#define CP_WAIT1()  asm volatile("cp.async.wait_group 1;" ::: "memory")

__device__ __forceinline__ uint32_t pack_h_hi(float a, float b) {
    __half2 h = __floats2half2_rn(a, b);
    return *(uint32_t*)&h;
}

// ---------------------------------------------------------------------------
// Plain fp16 GEMM core: C = A @ W^T   (fp32 acc)
// 128x128 tile, BK=32, 8 warps (2m x 4n), warp tile 64x32, 3-stage cp.async.
// smem: 3 stages x 2 operands x 10240 B = 61440 B  => 2+ CTAs/SM.
// ---------------------------------------------------------------------------
#define BK      32
#define NCHUNK  (HID / BK)          // 32
#define PITCH   40                  // b16 elems per smem row (80B)
#define P2      (PITCH * 2)
#define TILE_B  (128 * P2)          // 10240 bytes
#define STAGE_B (2 * TILE_B)        // 20480
#define GEMM_SMEM_BYTES (3 * STAGE_B)

struct GemmCore {
    uint32_t sbase;
    int tid, wid, lane, wm, wn, m0, n0;
    float acc[4][4][4];

    __device__ __forceinline__ void init(uint32_t sb, int m, int n) {
        sbase = sb;
        tid = threadIdx.x; wid = tid >> 5; lane = tid & 31;
        wm = wid >> 2; wn = wid & 3;
        m0 = m; n0 = n;
#pragma unroll
        for (int i = 0; i < 4; ++i)
#pragma unroll
            for (int j = 0; j < 4; ++j)
#pragma unroll
                for (int e = 0; e < 4; ++e) acc[i][j][e] = 0.f;
    }

    __device__ __forceinline__ void issue_copy(
        const __half* A, const __half* W, int c, int s)
    {
        const int k0 = c * BK;
        const uint32_t sb = sbase + s * STAGE_B;
#pragma unroll
        for (int op = 0; op < 2; ++op) {
            const __half* src = (op == 0) ? A : W;
            const int rbase = (op == 0) ? m0 : n0;
#pragma unroll
            for (int i = 0; i < 2; ++i) {
                const int u   = i * 256 + tid;
                const int row = u >> 2;
                const int cv  = u & 3;
                const void* g = src + (size_t)(rbase + row) * HID + k0 + cv * 8;
                CP_ASYNC16(sb + op * TILE_B + row * P2 + cv * 16, g);
            }
        }
        CP_COMMIT();
    }

    __device__ __forceinline__ void compute(int s) {
        const uint32_t sb = sbase + s * STAGE_B;
        const uint32_t aA = sb;
        const uint32_t aW = sb + TILE_B;

        const int arow = wm * 64 + (lane & 15);
        const int acol = (lane >> 4) * 8;
        const int brow = wn * 32 + (lane & 7) + (lane >> 4) * 8;
        const int bcol = ((lane >> 3) & 1) * 8;

#pragma unroll
        for (int ks = 0; ks < 2; ++ks) {
            uint32_t a[4][4];
#pragma unroll
            for (int i = 0; i < 4; ++i) {
                const uint32_t off = (arow + i * 16) * P2 + (ks * 16 + acol) * 2;
                ldm_x4(a[i], aA + off);
            }
            uint32_t bw[8];
#pragma unroll
            for (int jj = 0; jj < 2; ++jj) {
                const uint32_t off = (brow + jj * 16) * P2 + (ks * 16 + bcol) * 2;
                ldm_x4(&bw[jj * 4], aW + off);
            }
#pragma unroll
            for (int i = 0; i < 4; ++i)
#pragma unroll
                for (int j = 0; j < 4; ++j) {
                    const int bi = (j >> 1) * 4 + (j & 1) * 2;
                    mma_f16(acc[i][j], a[i], &bw[bi]);
                }
        }
    }

    __device__ __forceinline__ void mainloop(const __half* A, const __half* W)
    {
        issue_copy(A, W, 0, 0);
        issue_copy(A, W, 1, 1);
#pragma unroll 1
        for (int c = 0; c < NCHUNK; ++c) {
            if (c + 1 < NCHUNK) { CP_WAIT1(); } else { CP_WAIT0(); }
            __syncthreads();
            if (c + 2 < NCHUNK) issue_copy(A, W, c + 2, (c + 2) % 3);
            compute(c % 3);
            __syncthreads();
        }
    }
};

// ---- fused QKV: blockIdx.z selects weight/bias/dest; all outputs single fp16 ----
__global__ void __launch_bounds__(256)
gemm_qkv_kernel(const __half* __restrict__ xh, const __half* __restrict__ whf,
                const float* __restrict__ bq, const float* __restrict__ bk,
                const float* __restrict__ bv,
                __half* __restrict__ qh, __half* __restrict__ kh,
                __half* __restrict__ vh)
{
    extern __shared__ __align__(128) char smem[];
    const int z = blockIdx.z;
    const size_t WSZ = (size_t)HID * HID;
    const float* bias = (z == 0) ? bq : (z == 1) ? bk : bv;
    __half* C = (z == 0) ? qh : (z == 1) ? kh : vh;

    GemmCore g;
    g.init(smem_u32(smem), blockIdx.y * 128, blockIdx.x * 128);
    g.mainloop(xh, whf + z * WSZ);

#pragma unroll
    for (int i = 0; i < 4; ++i) {
        const int r0 = g.m0 + g.wm * 64 + i * 16 + (g.lane >> 2);
#pragma unroll
        for (int j = 0; j < 4; ++j) {
            const int col = g.n0 + g.wn * 32 + j * 8 + (g.lane & 3) * 2;
            const float bx = bias[col], by = bias[col + 1];
            const size_t o0 = (size_t)r0 * HID + col;
            const size_t o1 = (size_t)(r0 + 8) * HID + col;
            *(uint32_t*)(C + o0) = pack_h_hi(g.acc[i][j][0] + bx, g.acc[i][j][1] + by);
            *(uint32_t*)(C + o1) = pack_h_hi(g.acc[i][j][2] + bx, g.acc[i][j][3] + by);
        }
    }
}

// ---- o-proj with fused column-max epilogue (bias added in combine) ----
__global__ void __launch_bounds__(256)
gemm_omax_kernel(const __half* __restrict__ ch, const __half* __restrict__ Wo,
                 float* __restrict__ scr)
{
    extern __shared__ __align__(128) char smem[];
    GemmCore g;
    g.init(smem_u32(smem), blockIdx.y * 128, blockIdx.x * 128);
    g.mainloop(ch, Wo);

    float* maxbuf = (float*)smem;   // [2][128] indexed by wm
#pragma unroll
    for (int j = 0; j < 4; ++j) {
        float c0 = -3.402823466e38f, c1 = c0;
#pragma unroll
        for (int i = 0; i < 4; ++i) {
            c0 = fmaxf(c0, fmaxf(g.acc[i][j][0], g.acc[i][j][2]));
            c1 = fmaxf(c1, fmaxf(g.acc[i][j][1], g.acc[i][j][3]));
        }
        c0 = fmaxf(c0, __shfl_xor_sync(0xffffffff, c0, 4));
        c0 = fmaxf(c0, __shfl_xor_sync(0xffffffff, c0, 8));
        c0 = fmaxf(c0, __shfl_xor_sync(0xffffffff, c0, 16));
        c1 = fmaxf(c1, __shfl_xor_sync(0xffffffff, c1, 4));
        c1 = fmaxf(c1, __shfl_xor_sync(0xffffffff, c1, 8));
        c1 = fmaxf(c1, __shfl_xor_sync(0xffffffff, c1, 16));
        if ((g.lane >> 2) == 0) {
            const int cc = g.wn * 32 + j * 8 + (g.lane & 3) * 2;
            maxbuf[g.wm * 128 + cc]     = c0;
            maxbuf[g.wm * 128 + cc + 1] = c1;
        }
    }
    __syncthreads();
    if (g.tid < 128) {
        const float f = fmaxf(maxbuf[g.tid], maxbuf[128 + g.tid]);
        const int b   = g.m0 >> 9;
        const int sub = (g.m0 >> 7) & 3;
        scr[((size_t)sub * BDIM + b) * HID + g.n0 + g.tid] = f;
    }
}

__global__ void __launch_bounds__(256)
maxcombine_kernel(const float* __restrict__ scr, const float* __restrict__ bias,
                  float* __restrict__ out)
{
    const int i = blockIdx.x * 256 + threadIdx.x;
    const float f = fmaxf(fmaxf(scr[i], scr[BDIM * HID + i]),
                          fmaxf(scr[2 * BDIM * HID + i], scr[3 * BDIM * HID + i]));
    out[i] = f + bias[i & (HID - 1)];
}

// ---------------------------------------------------------------------------
// Attention: QK 1-term fp16, softmax in regs, PV 1-term fp16, ctx single fp16.
// 2-stage KV pipeline (copy chunk c+1 overlaps compute chunk c).
// ---------------------------------------------------------------------------
#define APITCH 72
#define AP2    (APITCH * 2)
#define SM_Q   0
#define SM_K0  (128 * AP2)              // 18432
#define KVST   (64 * AP2)               // 9216
#define SM_V0  (SM_K0 + 2 * KVST)       // 36864
#define SM_MSK (SM_V0 + 2 * KVST)       // 55296
#define ATTN_SMEM_BYTES (SM_MSK + 2 * 64 * 4)   // 55808

__global__ void __launch_bounds__(256)
attn_mma_kernel(const __half* __restrict__ Qh, const __half* __restrict__ Kh,
                const __half* __restrict__ Vh, const int* __restrict__ mask,
                __half* __restrict__ Ch)
{
    extern __shared__ __align__(128) char smem[];
    const uint32_t sb = smem_u32(smem);
    float* msk01 = (float*)(smem + SM_MSK);

    const int tid  = threadIdx.x;
    const int wid  = tid >> 5, lane = tid & 31;
    const int q0   = blockIdx.x * 128;
    const int h    = blockIdx.y;
    const int b    = blockIdx.z;
    const size_t rowbase = (size_t)b * TDIM;
    const int colbase = h * HD;

    // ---- Q tile load (group 0) ----
    {
#pragma unroll
        for (int i = 0; i < 4; ++i) {
            const int u = i * 256 + tid;
            const int r = u >> 3, cv = u & 7;
            const void* g = Qh + (rowbase + q0 + r) * HID + colbase + cv * 8;
            CP_ASYNC16(sb + SM_Q + r * AP2 + cv * 16, g);
        }
        CP_COMMIT();
    }

    // ---- KV chunk copy: chunk c into stage s ----
    auto issue_kv = [&](int c, int s) {
        const int k0 = c * 64;
        const uint32_t soK = sb + SM_K0 + s * KVST;
        const uint32_t soV = sb + SM_V0 + s * KVST;
#pragma unroll
        for (int i = 0; i < 2; ++i) {
            const int u = i * 256 + tid;
            const int r = u >> 3, cv = u & 7;
            CP_ASYNC16(soK + r * AP2 + cv * 16,
                       Kh + (rowbase + k0 + r) * HID + colbase + cv * 8);
            CP_ASYNC16(soV + r * AP2 + cv * 16,
                       Vh + (rowbase + k0 + r) * HID + colbase + cv * 8);
        }
        CP_COMMIT();
        if (tid < 64) msk01[s * 64 + tid] = (float)mask[b * TDIM + k0 + tid];
    };

    float oacc[8][4];
#pragma unroll
    for (int j = 0; j < 8; ++j)
#pragma unroll
        for (int e = 0; e < 4; ++e) oacc[j][e] = 0.f;
    float den_r = 0.f, den_r8 = 0.f;

    const int qoff_row = (wid * 16 + (lane & 15)) * AP2;
    const int qoff_col = ((lane >> 4) * 8) * 2;
    const int koff_row = ((lane & 7) + (lane >> 4) * 8) * AP2;
    const int koff_col = (((lane >> 3) & 1) * 8) * 2;
    const int voff_row = ((lane & 15)) * AP2;
    const int voff_col = ((lane >> 4) * 8) * 2;

    issue_kv(0, 0);

#pragma unroll 1
    for (int c = 0; c < 8; ++c) {
        const int s = c & 1;
        if (c < 7) { issue_kv(c + 1, s ^ 1); CP_WAIT1(); }
        else       { CP_WAIT0(); }
        __syncthreads();

        // ---- S = Q K^T (1-term fp16) ----
        float sacc[8][4];
#pragma unroll
        for (int j = 0; j < 8; ++j)
#pragma unroll
            for (int e = 0; e < 4; ++e) sacc[j][e] = 0.f;

#pragma unroll
        for (int dk = 0; dk < 4; ++dk) {
            uint32_t a[4];
            ldm_x4(a, sb + SM_Q + qoff_row + dk * 32 + qoff_col);
#pragma unroll
            for (int kb = 0; kb < 4; ++kb) {
                uint32_t bh[4];
                const uint32_t ka = sb + SM_K0 + s * KVST +
                                    (kb * 16) * AP2 + koff_row + dk * 32 + koff_col;
                ldm_x4(bh, ka);
                mma_f16(sacc[2 * kb],     a, &bh[0]);
                mma_f16(sacc[2 * kb + 1], a, &bh[2]);
            }
        }

        // ---- softmax (unnormalized): p = exp(mask/clip(s/8)) ----
        float dr = 0.f, dr8 = 0.f;
        const float* mk = msk01 + s * 64;
#pragma unroll
        for (int nt = 0; nt < 8; ++nt) {
            const int c0 = nt * 8 + (lane & 3) * 2;
            const float m0 = mk[c0], m1 = mk[c0 + 1];
#pragma unroll
            for (int e = 0; e < 4; ++e) {
                float sv = sacc[nt][e] * 0.125f;
                sv = fminf(fmaxf(sv, -50.f), 50.f);
                sv = ((e & 1) ? m1 : m0) * (sv + 50.f) - 50.f;
                sacc[nt][e] = __expf(sv);
            }
            dr  += sacc[nt][0] + sacc[nt][1];
            dr8 += sacc[nt][2] + sacc[nt][3];
        }
        dr  += __shfl_xor_sync(0xffffffff, dr, 1);
        dr  += __shfl_xor_sync(0xffffffff, dr, 2);
        dr8 += __shfl_xor_sync(0xffffffff, dr8, 1);
        dr8 += __shfl_xor_sync(0xffffffff, dr8, 2);
        den_r  += dr;
        den_r8 += dr8;

        // ---- PV: oacc += P @ V  (1-term fp16) ----
#pragma unroll
        for (int kb = 0; kb < 4; ++kb) {
            uint32_t pa[4];
            const int t0 = 2 * kb, t1 = 2 * kb + 1;
            pa[0] = pack_h_hi(sacc[t0][0], sacc[t0][1]);
            pa[1] = pack_h_hi(sacc[t0][2], sacc[t0][3]);
            pa[2] = pack_h_hi(sacc[t1][0], sacc[t1][1]);
            pa[3] = pack_h_hi(sacc[t1][2], sacc[t1][3]);
#pragma unroll
            for (int dnp = 0; dnp < 4; ++dnp) {
                uint32_t vv[4];
                const uint32_t va = sb + SM_V0 + s * KVST +
                                    (kb * 16) * AP2 + voff_row + dnp * 32 + voff_col;
                ldm_x4_t(vv, va);
                mma_f16(oacc[2 * dnp],     pa, &vv[0]);
                mma_f16(oacc[2 * dnp + 1], pa, &vv[2]);
            }
        }
        __syncthreads();   // all warps done reading stage s before it is refilled
    }

    const float invr  = 1.f / den_r;
    const float invr8 = 1.f / den_r8;
    const size_t r0 = (rowbase + q0 + wid * 16 + (lane >> 2)) * HID + colbase;
    const size_t r8 = r0 + 8 * HID;
#pragma unroll
    for (int dn = 0; dn < 8; ++dn) {
        const int col = dn * 8 + (lane & 3) * 2;
        *(uint32_t*)(Ch + r0 + col) = pack_h_hi(oacc[dn][0] * invr,  oacc[dn][1] * invr);
        *(uint32_t*)(Ch + r8 + col) = pack_h_hi(oacc[dn][2] * invr8, oacc[dn][3] * invr8);
    }
}

// ---------------------------------------------------------------------------
// x [B, HID, T] fp32 -> transpose to [BT, HID], single fp16
// ---------------------------------------------------------------------------
__global__ void __launch_bounds__(256)
xpose_kernel(const float* __restrict__ x, __half* __restrict__ xh)
{
    __shared__ float s[32][33];
    const int b = blockIdx.z, k0 = blockIdx.y * 32, t0 = blockIdx.x * 32;
    const int tx = threadIdx.x & 31, ty = threadIdx.x >> 5;
    const float* src = x + ((size_t)b * HID + k0) * TDIM + t0;
#pragma unroll
    for (int i = 0; i < 4; ++i)
        s[ty + 8 * i][tx] = src[(size_t)(ty + 8 * i) * TDIM + tx];
    __syncthreads();
#pragma unroll
    for (int i = 0; i < 4; ++i) {
        const int t = ty + 8 * i;
        const size_t o = (size_t)(b * TDIM + t0 + t) * HID + k0 + tx;
        xh[o] = __float2half_rn(s[tx][t]);
    }
}

// all 4 weights fp32 -> fp16 in one launch (blockIdx.y selects)
__global__ void __launch_bounds__(256)
wconv4_kernel(const float* __restrict__ w0, const float* __restrict__ w1,
              const float* __restrict__ w2, const float* __restrict__ w3,
              __half* __restrict__ dst, int n4)
{
    const int z = blockIdx.y;
    const float* src = (z == 0) ? w0 : (z == 1) ? w1 : (z == 2) ? w2 : w3;
    __half* d = dst + (size_t)z * HID * HID;
    const int i = blockIdx.x * 256 + threadIdx.x;
    if (i >= n4) return;
    const float4 v = ((const float4*)src)[i];
    uint2 hp;
    hp.x = pack_h_hi(v.x, v.y);
    hp.y = pack_h_hi(v.z, v.w);
    ((uint2*)d)[i] = hp;
}

// ---------------------------------------------------------------------------
extern "C" void kernel_launch(void* const* d_in, const int* in_sizes, int n_in,
                              void* d_out, int out_size)
{
    const float* x    = (const float*)d_in[0];
    const int*   mask = (const int*)d_in[1];
    const float* Wq   = (const float*)d_in[2];
    const float* bq   = (const float*)d_in[3];
    const float* Wk   = (const float*)d_in[4];
    const float* bk   = (const float*)d_in[5];
    const float* Wv   = (const float*)d_in[6];
    const float* bv   = (const float*)d_in[7];
    const float* Wo   = (const float*)d_in[8];
    const float* bo   = (const float*)d_in[9];
    float* out = (float*)d_out;

    float* scr;
    __half *xh, *qh, *kh, *vh, *ch, *whf;
    cudaGetSymbolAddress((void**)&scr, g_scr);
    cudaGetSymbolAddress((void**)&xh,  g_xh);
    cudaGetSymbolAddress((void**)&qh,  g_qh);
    cudaGetSymbolAddress((void**)&kh,  g_kh);
    cudaGetSymbolAddress((void**)&vh,  g_vh);
    cudaGetSymbolAddress((void**)&ch,  g_ch);
    cudaGetSymbolAddress((void**)&whf, g_whf);

    cudaFuncSetAttribute(gemm_qkv_kernel,
                         cudaFuncAttributeMaxDynamicSharedMemorySize, GEMM_SMEM_BYTES);
    cudaFuncSetAttribute(gemm_omax_kernel,
                         cudaFuncAttributeMaxDynamicSharedMemorySize, GEMM_SMEM_BYTES);
    cudaFuncSetAttribute(attn_mma_kernel,
                         cudaFuncAttributeMaxDynamicSharedMemorySize, ATTN_SMEM_BYTES);

    const int wn4 = HID * HID / 4;
    wconv4_kernel<<<dim3((wn4 + 255) / 256, 4), 256>>>(Wq, Wk, Wv, Wo, whf, wn4);
    xpose_kernel<<<dim3(TDIM / 32, HID / 32, BDIM), 256>>>(x, xh);

    const size_t WSZ = (size_t)HID * HID;

    gemm_qkv_kernel<<<dim3(HID / 128, BT / 128, 3), 256, GEMM_SMEM_BYTES>>>(
        xh, whf, bq, bk, bv, qh, kh, vh);

    attn_mma_kernel<<<dim3(TDIM / 128, NH, BDIM), 256, ATTN_SMEM_BYTES>>>(
        qh, kh, vh, mask, ch);

    gemm_omax_kernel<<<dim3(HID / 128, BT / 128), 256, GEMM_SMEM_BYTES>>>(
        ch, whf + 3 * WSZ, scr);

    maxcombine_kernel<<<(BDIM * HID) / 256, 256>>>(scr, bo, out);
}

// round 10
// speedup vs baseline: 2.9595x; 1.1956x over previous
#include <cuda_runtime.h>
#include <cuda_bf16.h>
#include <cuda_fp16.h>
#include <cstdint>

#define BDIM 32
#define TDIM 512
#define HID  1024
#define NH   16
#define HD   64
#define BT   (BDIM * TDIM)   // 16384

// ------------------------- scratch (device globals) -------------------------
__device__ float  g_scr[(size_t)4 * BDIM * HID];   // o-proj partial maxes
__device__ __half g_xh [(size_t)BT * HID];
__device__ __half g_qh [(size_t)BT * HID];
__device__ __half g_kh [(size_t)BT * HID];
__device__ __half g_vh [(size_t)BT * HID];
__device__ __half g_ch [(size_t)BT * HID];
__device__ __half g_whf[(size_t)4 * HID * HID];    // fp16 weights (q,k,v,o)

// ------------------------------ PTX helpers --------------------------------
__device__ __forceinline__ uint32_t smem_u32(const void* p) {
    uint32_t a;
    asm("{ .reg .u64 t; cvta.to.shared.u64 t, %1; cvt.u32.u64 %0, t; }" : "=r"(a) : "l"(p));
    return a;
}
__device__ __forceinline__ void ldm_x4(uint32_t* r, uint32_t addr) {
    asm volatile("ldmatrix.sync.aligned.m8n8.x4.shared.b16 {%0,%1,%2,%3}, [%4];"
                 : "=r"(r[0]), "=r"(r[1]), "=r"(r[2]), "=r"(r[3]) : "r"(addr));
}
__device__ __forceinline__ void ldm_x4_t(uint32_t* r, uint32_t addr) {
    asm volatile("ldmatrix.sync.aligned.m8n8.x4.trans.shared.b16 {%0,%1,%2,%3}, [%4];"
                 : "=r"(r[0]), "=r"(r[1]), "=r"(r[2]), "=r"(r[3]) : "r"(addr));
}
__device__ __forceinline__ void mma_f16(float* c, const uint32_t* a, const uint32_t* b) {
    asm volatile("mma.sync.aligned.m16n8k16.row.col.f32.f16.f16.f32 "
                 "{%0,%1,%2,%3}, {%4,%5,%6,%7}, {%8,%9}, {%0,%1,%2,%3};"
                 : "+f"(c[0]), "+f"(c[1]), "+f"(c[2]), "+f"(c[3])
                 : "r"(a[0]), "r"(a[1]), "r"(a[2]), "r"(a[3]), "r"(b[0]), "r"(b[1]));
}
#define CP_ASYNC16(saddr, gptr) \
    asm volatile("cp.async.cg.shared.global [%0], [%1], 16;" :: "r"(saddr), "l"(gptr))
#define CP_COMMIT() asm volatile("cp.async.commit_group;" ::: "memory")
#define CP_WAIT0()  asm volatile("cp.async.wait_group 0;" ::: "memory")
#define CP_WAIT1()  asm volatile("cp.async.wait_group 1;" ::: "memory")

__device__ __forceinline__ uint32_t pack_h_hi(float a, float b) {
    __half2 h = __floats2half2_rn(a, b);
    return *(uint32_t*)&h;
}

// ---------------------------------------------------------------------------
// fp16 GEMM core: C = A @ W^T (fp32 acc)
// 128x128 tile, BK=64, 8 warps (2m x 4n), warp tile 64x32.
// 3-stage cp.async ring, ONE __syncthreads per iteration (issue-after-sync:
// write target (c+2)%3 == (c-1)%3 whose readers all passed this barrier).
// smem: 3 stages x 2 ops x 18432 B = 110592 B; regs limit occupancy to 2 CTAs.
// ---------------------------------------------------------------------------
#define BK      64
#define NCHUNK  (HID / BK)          // 16
#define PITCH   72                  // fp16 elems per smem row (144B, gcd(9,8)=1)
#define P2      (PITCH * 2)
#define TILE_B  (128 * P2)          // 18432 bytes
#define STAGE_B (2 * TILE_B)        // 36864
#define GEMM_SMEM_BYTES (3 * STAGE_B)   // 110592

struct GemmCore {
    uint32_t sbase;
    int tid, wid, lane, wm, wn, m0, n0;
    float acc[4][4][4];

    __device__ __forceinline__ void init(uint32_t sb, int m, int n) {
        sbase = sb;
        tid = threadIdx.x; wid = tid >> 5; lane = tid & 31;
        wm = wid >> 2; wn = wid & 3;
        m0 = m; n0 = n;
#pragma unroll
        for (int i = 0; i < 4; ++i)
#pragma unroll
            for (int j = 0; j < 4; ++j)
#pragma unroll
                for (int e = 0; e < 4; ++e) acc[i][j][e] = 0.f;
    }

    __device__ __forceinline__ void issue_copy(
        const __half* A, const __half* W, int c, int s)
    {
        const int k0 = c * BK;
        const uint32_t sb = sbase + s * STAGE_B;
#pragma unroll
        for (int op = 0; op < 2; ++op) {
            const __half* src = (op == 0) ? A : W;
            const int rbase = (op == 0) ? m0 : n0;
#pragma unroll
            for (int i = 0; i < 4; ++i) {
                const int u   = i * 256 + tid;      // 1024 uint4 per operand
                const int row = u >> 3;
                const int cv  = u & 7;
                const void* g = src + (size_t)(rbase + row) * HID + k0 + cv * 8;
                CP_ASYNC16(sb + op * TILE_B + row * P2 + cv * 16, g);
            }
        }
        CP_COMMIT();
    }

    __device__ __forceinline__ void compute(int s) {
        const uint32_t sb = sbase + s * STAGE_B;
        const uint32_t aA = sb;
        const uint32_t aW = sb + TILE_B;

        const int arow = wm * 64 + (lane & 15);
        const int acol = (lane >> 4) * 8;
        const int brow = wn * 32 + (lane & 7) + (lane >> 4) * 8;
        const int bcol = ((lane >> 3) & 1) * 8;

#pragma unroll
        for (int ks = 0; ks < 4; ++ks) {
            uint32_t a[4][4];
#pragma unroll
            for (int i = 0; i < 4; ++i) {
                const uint32_t off = (arow + i * 16) * P2 + (ks * 16 + acol) * 2;
                ldm_x4(a[i], aA + off);
            }
            uint32_t bw[8];
#pragma unroll
            for (int jj = 0; jj < 2; ++jj) {
                const uint32_t off = (brow + jj * 16) * P2 + (ks * 16 + bcol) * 2;
                ldm_x4(&bw[jj * 4], aW + off);
            }
#pragma unroll
            for (int i = 0; i < 4; ++i)
#pragma unroll
                for (int j = 0; j < 4; ++j) {
                    const int bi = (j >> 1) * 4 + (j & 1) * 2;
                    mma_f16(acc[i][j], a[i], &bw[bi]);
                }
        }
    }

    __device__ __forceinline__ void mainloop(const __half* A, const __half* W)
    {
        issue_copy(A, W, 0, 0);
        issue_copy(A, W, 1, 1);
#pragma unroll 1
        for (int c = 0; c < NCHUNK; ++c) {
            if (c + 1 < NCHUNK) { CP_WAIT1(); } else { CP_WAIT0(); }
            __syncthreads();
            if (c + 2 < NCHUNK) issue_copy(A, W, c + 2, (c + 2) % 3);
            compute(c % 3);
            // no trailing sync: next iter's barrier protects stage reuse
        }
    }
};

// ---- fused QKV: blockIdx.z selects weight/bias/dest; outputs single fp16 ----
__global__ void __launch_bounds__(256)
gemm_qkv_kernel(const __half* __restrict__ xh, const __half* __restrict__ whf,
                const float* __restrict__ bq, const float* __restrict__ bk,
                const float* __restrict__ bv,
                __half* __restrict__ qh, __half* __restrict__ kh,
                __half* __restrict__ vh)
{
    extern __shared__ __align__(128) char smem[];
    const int z = blockIdx.z;
    const size_t WSZ = (size_t)HID * HID;
    const float* bias = (z == 0) ? bq : (z == 1) ? bk : bv;
    __half* C = (z == 0) ? qh : (z == 1) ? kh : vh;

    GemmCore g;
    g.init(smem_u32(smem), blockIdx.y * 128, blockIdx.x * 128);
    g.mainloop(xh, whf + z * WSZ);

#pragma unroll
    for (int i = 0; i < 4; ++i) {
        const int r0 = g.m0 + g.wm * 64 + i * 16 + (g.lane >> 2);
#pragma unroll
        for (int j = 0; j < 4; ++j) {
            const int col = g.n0 + g.wn * 32 + j * 8 + (g.lane & 3) * 2;
            const float bx = bias[col], by = bias[col + 1];
            const size_t o0 = (size_t)r0 * HID + col;
            const size_t o1 = (size_t)(r0 + 8) * HID + col;
            *(uint32_t*)(C + o0) = pack_h_hi(g.acc[i][j][0] + bx, g.acc[i][j][1] + by);
            *(uint32_t*)(C + o1) = pack_h_hi(g.acc[i][j][2] + bx, g.acc[i][j][3] + by);
        }
    }
}

// ---- o-proj with fused column-max epilogue (bias added in combine) ----
__global__ void __launch_bounds__(256)
gemm_omax_kernel(const __half* __restrict__ ch, const __half* __restrict__ Wo,
                 float* __restrict__ scr)
{
    extern __shared__ __align__(128) char smem[];
    GemmCore g;
    g.init(smem_u32(smem), blockIdx.y * 128, blockIdx.x * 128);
    g.mainloop(ch, Wo);
    __syncthreads();   // all warps done with smem before reuse as maxbuf

    float* maxbuf = (float*)smem;   // [2][128] indexed by wm
#pragma unroll
    for (int j = 0; j < 4; ++j) {
        float c0 = -3.402823466e38f, c1 = c0;
#pragma unroll
        for (int i = 0; i < 4; ++i) {
            c0 = fmaxf(c0, fmaxf(g.acc[i][j][0], g.acc[i][j][2]));
            c1 = fmaxf(c1, fmaxf(g.acc[i][j][1], g.acc[i][j][3]));
        }
        c0 = fmaxf(c0, __shfl_xor_sync(0xffffffff, c0, 4));
        c0 = fmaxf(c0, __shfl_xor_sync(0xffffffff, c0, 8));
        c0 = fmaxf(c0, __shfl_xor_sync(0xffffffff, c0, 16));
        c1 = fmaxf(c1, __shfl_xor_sync(0xffffffff, c1, 4));
        c1 = fmaxf(c1, __shfl_xor_sync(0xffffffff, c1, 8));
        c1 = fmaxf(c1, __shfl_xor_sync(0xffffffff, c1, 16));
        if ((g.lane >> 2) == 0) {
            const int cc = g.wn * 32 + j * 8 + (g.lane & 3) * 2;
            maxbuf[g.wm * 128 + cc]     = c0;
            maxbuf[g.wm * 128 + cc + 1] = c1;
        }
    }
    __syncthreads();
    if (g.tid < 128) {
        const float f = fmaxf(maxbuf[g.tid], maxbuf[128 + g.tid]);
        const int b   = g.m0 >> 9;
        const int sub = (g.m0 >> 7) & 3;
        scr[((size_t)sub * BDIM + b) * HID + g.n0 + g.tid] = f;
    }
}

__global__ void __launch_bounds__(256)
maxcombine_kernel(const float* __restrict__ scr, const float* __restrict__ bias,
                  float* __restrict__ out)
{
    const int i = blockIdx.x * 256 + threadIdx.x;
    const float f = fmaxf(fmaxf(scr[i], scr[BDIM * HID + i]),
                          fmaxf(scr[2 * BDIM * HID + i], scr[3 * BDIM * HID + i]));
    out[i] = f + bias[i & (HID - 1)];
}

// ---------------------------------------------------------------------------
// Attention: QK 1-term fp16, reg softmax, PV 1-term fp16, ctx single fp16.
// 3-stage KV ring, one __syncthreads per chunk (issue-after-sync).
// ---------------------------------------------------------------------------
#define APITCH 72
#define AP2    (APITCH * 2)
#define SM_Q   0
#define KVST   (64 * AP2)               // 9216
#define SM_K0  (128 * AP2)              // 18432
#define SM_V0  (SM_K0 + 3 * KVST)       // 46080
#define SM_MSK (SM_V0 + 3 * KVST)       // 73728
#define ATTN_SMEM_BYTES (SM_MSK + 3 * 64 * 4)   // 74496

__global__ void __launch_bounds__(256)
attn_mma_kernel(const __half* __restrict__ Qh, const __half* __restrict__ Kh,
                const __half* __restrict__ Vh, const int* __restrict__ mask,
                __half* __restrict__ Ch)
{
    extern __shared__ __align__(128) char smem[];
    const uint32_t sb = smem_u32(smem);
    float* msk01 = (float*)(smem + SM_MSK);

    const int tid  = threadIdx.x;
    const int wid  = tid >> 5, lane = tid & 31;
    const int q0   = blockIdx.x * 128;
    const int h    = blockIdx.y;
    const int b    = blockIdx.z;
    const size_t rowbase = (size_t)b * TDIM;
    const int colbase = h * HD;

    // ---- Q tile load ----
    {
#pragma unroll
        for (int i = 0; i < 4; ++i) {
            const int u = i * 256 + tid;
            const int r = u >> 3, cv = u & 7;
            const void* g = Qh + (rowbase + q0 + r) * HID + colbase + cv * 8;
            CP_ASYNC16(sb + SM_Q + r * AP2 + cv * 16, g);
        }
        CP_COMMIT();
    }

    auto issue_kv = [&](int c, int s) {
        const int k0 = c * 64;
        const uint32_t soK = sb + SM_K0 + s * KVST;
        const uint32_t soV = sb + SM_V0 + s * KVST;
#pragma unroll
        for (int i = 0; i < 2; ++i) {
            const int u = i * 256 + tid;
            const int r = u >> 3, cv = u & 7;
            CP_ASYNC16(soK + r * AP2 + cv * 16,
                       Kh + (rowbase + k0 + r) * HID + colbase + cv * 8);
            CP_ASYNC16(soV + r * AP2 + cv * 16,
                       Vh + (rowbase + k0 + r) * HID + colbase + cv * 8);
        }
        CP_COMMIT();
        if (tid < 64) msk01[s * 64 + tid] = (float)mask[b * TDIM + k0 + tid];
    };

    float oacc[8][4];
#pragma unroll
    for (int j = 0; j < 8; ++j)
#pragma unroll
        for (int e = 0; e < 4; ++e) oacc[j][e] = 0.f;
    float den_r = 0.f, den_r8 = 0.f;

    const int qoff_row = (wid * 16 + (lane & 15)) * AP2;
    const int qoff_col = ((lane >> 4) * 8) * 2;
    const int koff_row = ((lane & 7) + (lane >> 4) * 8) * AP2;
    const int koff_col = (((lane >> 3) & 1) * 8) * 2;
    const int voff_row = ((lane & 15)) * AP2;
    const int voff_col = ((lane >> 4) * 8) * 2;

    issue_kv(0, 0);
    issue_kv(1, 1);

#pragma unroll 1
    for (int c = 0; c < 8; ++c) {
        const int s = c % 3;
        if (c < 7) { CP_WAIT1(); } else { CP_WAIT0(); }
        __syncthreads();
        if (c + 2 < 8) issue_kv(c + 2, (c + 2) % 3);

        // ---- S = Q K^T (1-term fp16) ----
        float sacc[8][4];
#pragma unroll
        for (int j = 0; j < 8; ++j)
#pragma unroll
            for (int e = 0; e < 4; ++e) sacc[j][e] = 0.f;

#pragma unroll
        for (int dk = 0; dk < 4; ++dk) {
            uint32_t a[4];
            ldm_x4(a, sb + SM_Q + qoff_row + dk * 32 + qoff_col);
#pragma unroll
            for (int kb = 0; kb < 4; ++kb) {
                uint32_t bh[4];
                const uint32_t ka = sb + SM_K0 + s * KVST +
                                    (kb * 16) * AP2 + koff_row + dk * 32 + koff_col;
                ldm_x4(bh, ka);
                mma_f16(sacc[2 * kb],     a, &bh[0]);
                mma_f16(sacc[2 * kb + 1], a, &bh[2]);
            }
        }

        // ---- softmax (unnormalized): p = exp(mask/clip(s/8)) ----
        float dr = 0.f, dr8 = 0.f;
        const float* mk = msk01 + s * 64;
#pragma unroll
        for (int nt = 0; nt < 8; ++nt) {
            const int c0 = nt * 8 + (lane & 3) * 2;
            const float m0 = mk[c0], m1 = mk[c0 + 1];
#pragma unroll
            for (int e = 0; e < 4; ++e) {
                float sv = sacc[nt][e] * 0.125f;
                sv = fminf(fmaxf(sv, -50.f), 50.f);
                sv = ((e & 1) ? m1 : m0) * (sv + 50.f) - 50.f;
                sacc[nt][e] = __expf(sv);
            }
            dr  += sacc[nt][0] + sacc[nt][1];
            dr8 += sacc[nt][2] + sacc[nt][3];
        }
        dr  += __shfl_xor_sync(0xffffffff, dr, 1);
        dr  += __shfl_xor_sync(0xffffffff, dr, 2);
        dr8 += __shfl_xor_sync(0xffffffff, dr8, 1);
        dr8 += __shfl_xor_sync(0xffffffff, dr8, 2);
        den_r  += dr;
        den_r8 += dr8;

        // ---- PV: oacc += P @ V  (1-term fp16) ----
#pragma unroll
        for (int kb = 0; kb < 4; ++kb) {
            uint32_t pa[4];
            const int t0 = 2 * kb, t1 = 2 * kb + 1;
            pa[0] = pack_h_hi(sacc[t0][0], sacc[t0][1]);
            pa[1] = pack_h_hi(sacc[t0][2], sacc[t0][3]);
            pa[2] = pack_h_hi(sacc[t1][0], sacc[t1][1]);
            pa[3] = pack_h_hi(sacc[t1][2], sacc[t1][3]);
#pragma unroll
            for (int dnp = 0; dnp < 4; ++dnp) {
                uint32_t vv[4];
                const uint32_t va = sb + SM_V0 + s * KVST +
                                    (kb * 16) * AP2 + voff_row + dnp * 32 + voff_col;
                ldm_x4_t(vv, va);
                mma_f16(oacc[2 * dnp],     pa, &vv[0]);
                mma_f16(oacc[2 * dnp + 1], pa, &vv[2]);
            }
        }
        // no trailing sync: 3-stage ring + issue-after-sync protects stage reuse
    }

    const float invr  = 1.f / den_r;
    const float invr8 = 1.f / den_r8;
    const size_t r0 = (rowbase + q0 + wid * 16 + (lane >> 2)) * HID + colbase;
    const size_t r8 = r0 + 8 * HID;
#pragma unroll
    for (int dn = 0; dn < 8; ++dn) {
        const int col = dn * 8 + (lane & 3) * 2;
        *(uint32_t*)(Ch + r0 + col) = pack_h_hi(oacc[dn][0] * invr,  oacc[dn][1] * invr);
        *(uint32_t*)(Ch + r8 + col) = pack_h_hi(oacc[dn][2] * invr8, oacc[dn][3] * invr8);
    }
}

// ---------------------------------------------------------------------------
// x [B, HID, T] fp32 -> transpose to [BT, HID], single fp16
// ---------------------------------------------------------------------------
__global__ void __launch_bounds__(256)
xpose_kernel(const float* __restrict__ x, __half* __restrict__ xh)
{
    __shared__ float s[32][33];
    const int b = blockIdx.z, k0 = blockIdx.y * 32, t0 = blockIdx.x * 32;
    const int tx = threadIdx.x & 31, ty = threadIdx.x >> 5;
    const float* src = x + ((size_t)b * HID + k0) * TDIM + t0;
#pragma unroll
    for (int i = 0; i < 4; ++i)
        s[ty + 8 * i][tx] = src[(size_t)(ty + 8 * i) * TDIM + tx];
    __syncthreads();
#pragma unroll
    for (int i = 0; i < 4; ++i) {
        const int t = ty + 8 * i;
        const size_t o = (size_t)(b * TDIM + t0 + t) * HID + k0 + tx;
        xh[o] = __float2half_rn(s[tx][t]);
    }
}

// all 4 weights fp32 -> fp16 in one launch (blockIdx.y selects)
__global__ void __launch_bounds__(256)
wconv4_kernel(const float* __restrict__ w0, const float* __restrict__ w1,
              const float* __restrict__ w2, const float* __restrict__ w3,
              __half* __restrict__ dst, int n4)
{
    const int z = blockIdx.y;
    const float* src = (z == 0) ? w0 : (z == 1) ? w1 : (z == 2) ? w2 : w3;
    __half* d = dst + (size_t)z * HID * HID;
    const int i = blockIdx.x * 256 + threadIdx.x;
    if (i >= n4) return;
    const float4 v = ((const float4*)src)[i];
    uint2 hp;
    hp.x = pack_h_hi(v.x, v.y);
    hp.y = pack_h_hi(v.z, v.w);
    ((uint2*)d)[i] = hp;
}

// ---------------------------------------------------------------------------
extern "C" void kernel_launch(void* const* d_in, const int* in_sizes, int n_in,
                              void* d_out, int out_size)
{
    const float* x    = (const float*)d_in[0];
    const int*   mask = (const int*)d_in[1];
    const float* Wq   = (const float*)d_in[2];
    const float* bq   = (const float*)d_in[3];
    const float* Wk   = (const float*)d_in[4];
    const float* bk   = (const float*)d_in[5];
    const float* Wv   = (const float*)d_in[6];
    const float* bv   = (const float*)d_in[7];
    const float* Wo   = (const float*)d_in[8];
    const float* bo   = (const float*)d_in[9];
    float* out = (float*)d_out;

    float* scr;
    __half *xh, *qh, *kh, *vh, *ch, *whf;
    cudaGetSymbolAddress((void**)&scr, g_scr);
    cudaGetSymbolAddress((void**)&xh,  g_xh);
    cudaGetSymbolAddress((void**)&qh,  g_qh);
    cudaGetSymbolAddress((void**)&kh,  g_kh);
    cudaGetSymbolAddress((void**)&vh,  g_vh);
    cudaGetSymbolAddress((void**)&ch,  g_ch);
    cudaGetSymbolAddress((void**)&whf, g_whf);

    cudaFuncSetAttribute(gemm_qkv_kernel,
                         cudaFuncAttributeMaxDynamicSharedMemorySize, GEMM_SMEM_BYTES);
    cudaFuncSetAttribute(gemm_omax_kernel,
                         cudaFuncAttributeMaxDynamicSharedMemorySize, GEMM_SMEM_BYTES);
    cudaFuncSetAttribute(attn_mma_kernel,
                         cudaFuncAttributeMaxDynamicSharedMemorySize, ATTN_SMEM_BYTES);

    const int wn4 = HID * HID / 4;
    wconv4_kernel<<<dim3((wn4 + 255) / 256, 4), 256>>>(Wq, Wk, Wv, Wo, whf, wn4);
    xpose_kernel<<<dim3(TDIM / 32, HID / 32, BDIM), 256>>>(x, xh);

    const size_t WSZ = (size_t)HID * HID;

    gemm_qkv_kernel<<<dim3(HID / 128, BT / 128, 3), 256, GEMM_SMEM_BYTES>>>(
        xh, whf, bq, bk, bv, qh, kh, vh);

    attn_mma_kernel<<<dim3(TDIM / 128, NH, BDIM), 256, ATTN_SMEM_BYTES>>>(
        qh, kh, vh, mask, ch);

    gemm_omax_kernel<<<dim3(HID / 128, BT / 128), 256, GEMM_SMEM_BYTES>>>(
        ch, whf + 3 * WSZ, scr);

    maxcombine_kernel<<<(BDIM * HID) / 256, 256>>>(scr, bo, out);
}

// round 11
// speedup vs baseline: 3.0731x; 1.0384x over previous
#include <cuda_runtime.h>
#include <cuda_bf16.h>
#include <cuda_fp16.h>
#include <cstdint>

#define BDIM 32
#define TDIM 512
#define HID  1024
#define NH   16
#define HD   64
#define BT   (BDIM * TDIM)   // 16384

// ------------------------- scratch (device globals) -------------------------
__device__ float  g_scr[(size_t)4 * BDIM * HID];   // o-proj partial maxes
__device__ __half g_xh [(size_t)BT * HID];
__device__ __half g_qh [(size_t)BT * HID];
__device__ __half g_kh [(size_t)BT * HID];
__device__ __half g_vh [(size_t)BT * HID];
__device__ __half g_ch [(size_t)BT * HID];
__device__ __half g_whf[(size_t)4 * HID * HID];    // fp16 weights (q,k,v,o)

// ------------------------------ PTX helpers --------------------------------
__device__ __forceinline__ uint32_t smem_u32(const void* p) {
    uint32_t a;
    asm("{ .reg .u64 t; cvta.to.shared.u64 t, %1; cvt.u32.u64 %0, t; }" : "=r"(a) : "l"(p));
    return a;
}
__device__ __forceinline__ void ldm_x4(uint32_t* r, uint32_t addr) {
    asm volatile("ldmatrix.sync.aligned.m8n8.x4.shared.b16 {%0,%1,%2,%3}, [%4];"
                 : "=r"(r[0]), "=r"(r[1]), "=r"(r[2]), "=r"(r[3]) : "r"(addr));
}
__device__ __forceinline__ void ldm_x4_t(uint32_t* r, uint32_t addr) {
    asm volatile("ldmatrix.sync.aligned.m8n8.x4.trans.shared.b16 {%0,%1,%2,%3}, [%4];"
                 : "=r"(r[0]), "=r"(r[1]), "=r"(r[2]), "=r"(r[3]) : "r"(addr));
}
__device__ __forceinline__ void mma_f16(float* c, const uint32_t* a, const uint32_t* b) {
    asm volatile("mma.sync.aligned.m16n8k16.row.col.f32.f16.f16.f32 "
                 "{%0,%1,%2,%3}, {%4,%5,%6,%7}, {%8,%9}, {%0,%1,%2,%3};"
                 : "+f"(c[0]), "+f"(c[1]), "+f"(c[2]), "+f"(c[3])
                 : "r"(a[0]), "r"(a[1]), "r"(a[2]), "r"(a[3]), "r"(b[0]), "r"(b[1]));
}
#define CP_ASYNC16(saddr, gptr) \
    asm volatile("cp.async.cg.shared.global [%0], [%1], 16;" :: "r"(saddr), "l"(gptr))
#define CP_COMMIT() asm volatile("cp.async.commit_group;" ::: "memory")
#define CP_WAIT0()  asm volatile("cp.async.wait_group 0;" ::: "memory")
#define CP_WAIT1()  asm volatile("cp.async.wait_group 1;" ::: "memory")

__device__ __forceinline__ uint32_t pack_h_hi(float a, float b) {
    __half2 h = __floats2half2_rn(a, b);
    return *(uint32_t*)&h;
}
// two fp16 exps in one MUFU op; result stays packed for mma A-fragment use
__device__ __forceinline__ uint32_t h2ex2(uint32_t x) {
    uint32_t r;
    asm("ex2.approx.f16x2 %0, %1;" : "=r"(r) : "r"(x));
    return r;
}

// ---------------------------------------------------------------------------
// fp16 GEMM core: C = A @ W^T (fp32 acc)
// 128x128 tile, BK=64, 8 warps (2m x 4n), warp tile 64x32.
// 3-stage cp.async ring, ONE __syncthreads per iteration.
// ---------------------------------------------------------------------------
#define BK      64
#define NCHUNK  (HID / BK)          // 16
#define PITCH   72                  // fp16 elems per smem row (144B)
#define P2      (PITCH * 2)
#define TILE_B  (128 * P2)          // 18432 bytes
#define STAGE_B (2 * TILE_B)        // 36864
#define GEMM_SMEM_BYTES (3 * STAGE_B)   // 110592

struct GemmCore {
    uint32_t sbase;
    int tid, wid, lane, wm, wn, m0, n0;
    float acc[4][4][4];

    __device__ __forceinline__ void init(uint32_t sb, int m, int n) {
        sbase = sb;
        tid = threadIdx.x; wid = tid >> 5; lane = tid & 31;
        wm = wid >> 2; wn = wid & 3;
        m0 = m; n0 = n;
#pragma unroll
        for (int i = 0; i < 4; ++i)
#pragma unroll
            for (int j = 0; j < 4; ++j)
#pragma unroll
                for (int e = 0; e < 4; ++e) acc[i][j][e] = 0.f;
    }

    __device__ __forceinline__ void issue_copy(
        const __half* A, const __half* W, int c, int s)
    {
        const int k0 = c * BK;
        const uint32_t sb = sbase + s * STAGE_B;
#pragma unroll
        for (int op = 0; op < 2; ++op) {
            const __half* src = (op == 0) ? A : W;
            const int rbase = (op == 0) ? m0 : n0;
#pragma unroll
            for (int i = 0; i < 4; ++i) {
                const int u   = i * 256 + tid;
                const int row = u >> 3;
                const int cv  = u & 7;
                const void* g = src + (size_t)(rbase + row) * HID + k0 + cv * 8;
                CP_ASYNC16(sb + op * TILE_B + row * P2 + cv * 16, g);
            }
        }
        CP_COMMIT();
    }

    __device__ __forceinline__ void compute(int s) {
        const uint32_t sb = sbase + s * STAGE_B;
        const uint32_t aA = sb;
        const uint32_t aW = sb + TILE_B;

        const int arow = wm * 64 + (lane & 15);
        const int acol = (lane >> 4) * 8;
        const int brow = wn * 32 + (lane & 7) + (lane >> 4) * 8;
        const int bcol = ((lane >> 3) & 1) * 8;

#pragma unroll
        for (int ks = 0; ks < 4; ++ks) {
            uint32_t a[4][4];
#pragma unroll
            for (int i = 0; i < 4; ++i) {
                const uint32_t off = (arow + i * 16) * P2 + (ks * 16 + acol) * 2;
                ldm_x4(a[i], aA + off);
            }
            uint32_t bw[8];
#pragma unroll
            for (int jj = 0; jj < 2; ++jj) {
                const uint32_t off = (brow + jj * 16) * P2 + (ks * 16 + bcol) * 2;
                ldm_x4(&bw[jj * 4], aW + off);
            }
#pragma unroll
            for (int i = 0; i < 4; ++i)
#pragma unroll
                for (int j = 0; j < 4; ++j) {
                    const int bi = (j >> 1) * 4 + (j & 1) * 2;
                    mma_f16(acc[i][j], a[i], &bw[bi]);
                }
        }
    }

    __device__ __forceinline__ void mainloop(const __half* A, const __half* W)
    {
        issue_copy(A, W, 0, 0);
        issue_copy(A, W, 1, 1);
#pragma unroll 1
        for (int c = 0; c < NCHUNK; ++c) {
            if (c + 1 < NCHUNK) { CP_WAIT1(); } else { CP_WAIT0(); }
            __syncthreads();
            if (c + 2 < NCHUNK) issue_copy(A, W, c + 2, (c + 2) % 3);
            compute(c % 3);
        }
    }
};

// ---- fused QKV ----
__global__ void __launch_bounds__(256)
gemm_qkv_kernel(const __half* __restrict__ xh, const __half* __restrict__ whf,
                const float* __restrict__ bq, const float* __restrict__ bk,
                const float* __restrict__ bv,
                __half* __restrict__ qh, __half* __restrict__ kh,
                __half* __restrict__ vh)
{
    extern __shared__ __align__(128) char smem[];
    const int z = blockIdx.z;
    const size_t WSZ = (size_t)HID * HID;
    const float* bias = (z == 0) ? bq : (z == 1) ? bk : bv;
    __half* C = (z == 0) ? qh : (z == 1) ? kh : vh;

    GemmCore g;
    g.init(smem_u32(smem), blockIdx.y * 128, blockIdx.x * 128);
    g.mainloop(xh, whf + z * WSZ);

#pragma unroll
    for (int i = 0; i < 4; ++i) {
        const int r0 = g.m0 + g.wm * 64 + i * 16 + (g.lane >> 2);
#pragma unroll
        for (int j = 0; j < 4; ++j) {
            const int col = g.n0 + g.wn * 32 + j * 8 + (g.lane & 3) * 2;
            const float bx = bias[col], by = bias[col + 1];
            const size_t o0 = (size_t)r0 * HID + col;
            const size_t o1 = (size_t)(r0 + 8) * HID + col;
            *(uint32_t*)(C + o0) = pack_h_hi(g.acc[i][j][0] + bx, g.acc[i][j][1] + by);
            *(uint32_t*)(C + o1) = pack_h_hi(g.acc[i][j][2] + bx, g.acc[i][j][3] + by);
        }
    }
}

// ---- o-proj with fused column-max epilogue ----
__global__ void __launch_bounds__(256)
gemm_omax_kernel(const __half* __restrict__ ch, const __half* __restrict__ Wo,
                 float* __restrict__ scr)
{
    extern __shared__ __align__(128) char smem[];
    GemmCore g;
    g.init(smem_u32(smem), blockIdx.y * 128, blockIdx.x * 128);
    g.mainloop(ch, Wo);
    __syncthreads();

    float* maxbuf = (float*)smem;
#pragma unroll
    for (int j = 0; j < 4; ++j) {
        float c0 = -3.402823466e38f, c1 = c0;
#pragma unroll
        for (int i = 0; i < 4; ++i) {
            c0 = fmaxf(c0, fmaxf(g.acc[i][j][0], g.acc[i][j][2]));
            c1 = fmaxf(c1, fmaxf(g.acc[i][j][1], g.acc[i][j][3]));
        }
        c0 = fmaxf(c0, __shfl_xor_sync(0xffffffff, c0, 4));
        c0 = fmaxf(c0, __shfl_xor_sync(0xffffffff, c0, 8));
        c0 = fmaxf(c0, __shfl_xor_sync(0xffffffff, c0, 16));
        c1 = fmaxf(c1, __shfl_xor_sync(0xffffffff, c1, 4));
        c1 = fmaxf(c1, __shfl_xor_sync(0xffffffff, c1, 8));
        c1 = fmaxf(c1, __shfl_xor_sync(0xffffffff, c1, 16));
        if ((g.lane >> 2) == 0) {
            const int cc = g.wn * 32 + j * 8 + (g.lane & 3) * 2;
            maxbuf[g.wm * 128 + cc]     = c0;
            maxbuf[g.wm * 128 + cc + 1] = c1;
        }
    }
    __syncthreads();
    if (g.tid < 128) {
        const float f = fmaxf(maxbuf[g.tid], maxbuf[128 + g.tid]);
        const int b   = g.m0 >> 9;
        const int sub = (g.m0 >> 7) & 3;
        scr[((size_t)sub * BDIM + b) * HID + g.n0 + g.tid] = f;
    }
}

__global__ void __launch_bounds__(256)
maxcombine_kernel(const float* __restrict__ scr, const float* __restrict__ bias,
                  float* __restrict__ out)
{
    const int i = blockIdx.x * 256 + threadIdx.x;
    const float f = fmaxf(fmaxf(scr[i], scr[BDIM * HID + i]),
                          fmaxf(scr[2 * BDIM * HID + i], scr[3 * BDIM * HID + i]));
    out[i] = f + bias[i & (HID - 1)];
}

// ---------------------------------------------------------------------------
// Attention: QK 1-term fp16, ex2.approx.f16x2 softmax (P stays packed fp16),
// PV 1-term fp16, 3-stage KV ring with one sync per chunk.
// p = exp(s/8) = 2^(s * 0.125*log2e); clip at +-50 -> +-72.1348 in log2 space;
// masked rows: 2^-72 underflows fp16 to 0 (exact w.r.t. reference semantics).
// ---------------------------------------------------------------------------
#define APITCH 72
#define AP2    (APITCH * 2)
#define SM_Q   0
#define KVST   (64 * AP2)               // 9216
#define SM_K0  (128 * AP2)              // 18432
#define SM_V0  (SM_K0 + 3 * KVST)       // 46080
#define SM_MSK (SM_V0 + 3 * KVST)       // 73728
#define ATTN_SMEM_BYTES (SM_MSK + 3 * 64 * 4)   // 74496

#define LOG2E_8 0.1803368801111244f     // 0.125 * log2(e)
#define CLIP2   72.134752044448170f     // 50 * log2(e)

__global__ void __launch_bounds__(256)
attn_mma_kernel(const __half* __restrict__ Qh, const __half* __restrict__ Kh,
                const __half* __restrict__ Vh, const int* __restrict__ mask,
                __half* __restrict__ Ch)
{
    extern __shared__ __align__(128) char smem[];
    const uint32_t sb = smem_u32(smem);
    float* msk01 = (float*)(smem + SM_MSK);

    const int tid  = threadIdx.x;
    const int wid  = tid >> 5, lane = tid & 31;
    const int q0   = blockIdx.x * 128;
    const int h    = blockIdx.y;
    const int b    = blockIdx.z;
    const size_t rowbase = (size_t)b * TDIM;
    const int colbase = h * HD;

    // ---- Q tile load ----
    {
#pragma unroll
        for (int i = 0; i < 4; ++i) {
            const int u = i * 256 + tid;
            const int r = u >> 3, cv = u & 7;
            const void* g = Qh + (rowbase + q0 + r) * HID + colbase + cv * 8;
            CP_ASYNC16(sb + SM_Q + r * AP2 + cv * 16, g);
        }
        CP_COMMIT();
    }

    auto issue_kv = [&](int c, int s) {
        const int k0 = c * 64;
        const uint32_t soK = sb + SM_K0 + s * KVST;
        const uint32_t soV = sb + SM_V0 + s * KVST;
#pragma unroll
        for (int i = 0; i < 2; ++i) {
            const int u = i * 256 + tid;
            const int r = u >> 3, cv = u & 7;
            CP_ASYNC16(soK + r * AP2 + cv * 16,
                       Kh + (rowbase + k0 + r) * HID + colbase + cv * 8);
            CP_ASYNC16(soV + r * AP2 + cv * 16,
                       Vh + (rowbase + k0 + r) * HID + colbase + cv * 8);
        }
        CP_COMMIT();
        if (tid < 64) msk01[s * 64 + tid] = (float)mask[b * TDIM + k0 + tid];
    };

    float oacc[8][4];
#pragma unroll
    for (int j = 0; j < 8; ++j)
#pragma unroll
        for (int e = 0; e < 4; ++e) oacc[j][e] = 0.f;
    float den_r = 0.f, den_r8 = 0.f;

    const int qoff_row = (wid * 16 + (lane & 15)) * AP2;
    const int qoff_col = ((lane >> 4) * 8) * 2;
    const int koff_row = ((lane & 7) + (lane >> 4) * 8) * AP2;
    const int koff_col = (((lane >> 3) & 1) * 8) * 2;
    const int voff_row = ((lane & 15)) * AP2;
    const int voff_col = ((lane >> 4) * 8) * 2;
    const uint32_t qbase = sb + SM_Q + qoff_row + qoff_col;

    issue_kv(0, 0);
    issue_kv(1, 1);

#pragma unroll 1
    for (int c = 0; c < 8; ++c) {
        const int s = c % 3;
        if (c < 7) { CP_WAIT1(); } else { CP_WAIT0(); }
        __syncthreads();
        if (c + 2 < 8) issue_kv(c + 2, (c + 2) % 3);

        // ---- S = Q K^T (1-term fp16) ----
        float sacc[8][4];
#pragma unroll
        for (int j = 0; j < 8; ++j)
#pragma unroll
            for (int e = 0; e < 4; ++e) sacc[j][e] = 0.f;

#pragma unroll
        for (int dk = 0; dk < 4; ++dk) {
            uint32_t a[4];
            ldm_x4(a, qbase + dk * 32);
#pragma unroll
            for (int kb = 0; kb < 4; ++kb) {
                uint32_t bh[4];
                const uint32_t ka = sb + SM_K0 + s * KVST +
                                    (kb * 16) * AP2 + koff_row + dk * 32 + koff_col;
                ldm_x4(bh, ka);
                mma_f16(sacc[2 * kb],     a, &bh[0]);
                mma_f16(sacc[2 * kb + 1], a, &bh[2]);
            }
        }

        // ---- softmax: p = 2^(clip(s*log2e/8)), masked -> 2^-72 -> fp16 zero ----
        uint32_t pk[8][2];
        float dr = 0.f, dr8 = 0.f;
        const float* mk = msk01 + s * 64;
#pragma unroll
        for (int nt = 0; nt < 8; ++nt) {
            const int c0 = nt * 8 + (lane & 3) * 2;
            const float m0 = mk[c0], m1 = mk[c0 + 1];
            float t0 = fminf(fmaxf(sacc[nt][0] * LOG2E_8, -CLIP2), CLIP2);
            float t1 = fminf(fmaxf(sacc[nt][1] * LOG2E_8, -CLIP2), CLIP2);
            float t2 = fminf(fmaxf(sacc[nt][2] * LOG2E_8, -CLIP2), CLIP2);
            float t3 = fminf(fmaxf(sacc[nt][3] * LOG2E_8, -CLIP2), CLIP2);
            t0 = m0 * (t0 + CLIP2) - CLIP2;
            t1 = m1 * (t1 + CLIP2) - CLIP2;
            t2 = m0 * (t2 + CLIP2) - CLIP2;
            t3 = m1 * (t3 + CLIP2) - CLIP2;
            const uint32_t p01 = h2ex2(pack_h_hi(t0, t1));
            const uint32_t p23 = h2ex2(pack_h_hi(t2, t3));
            pk[nt][0] = p01;
            pk[nt][1] = p23;
            const float2 f0 = __half22float2(*(const __half2*)&p01);
            const float2 f1 = __half22float2(*(const __half2*)&p23);
            dr  += f0.x + f0.y;
            dr8 += f1.x + f1.y;
        }
        dr  += __shfl_xor_sync(0xffffffff, dr, 1);
        dr  += __shfl_xor_sync(0xffffffff, dr, 2);
        dr8 += __shfl_xor_sync(0xffffffff, dr8, 1);
        dr8 += __shfl_xor_sync(0xffffffff, dr8, 2);
        den_r  += dr;
        den_r8 += dr8;

        // ---- PV: oacc += P @ V  (P already packed fp16) ----
#pragma unroll
        for (int kb = 0; kb < 4; ++kb) {
            uint32_t pa[4];
            const int t0 = 2 * kb, t1 = 2 * kb + 1;
            pa[0] = pk[t0][0];
            pa[1] = pk[t0][1];
            pa[2] = pk[t1][0];
            pa[3] = pk[t1][1];
#pragma unroll
            for (int dnp = 0; dnp < 4; ++dnp) {
                uint32_t vv[4];
                const uint32_t va = sb + SM_V0 + s * KVST +
                                    (kb * 16) * AP2 + voff_row + dnp * 32 + voff_col;
                ldm_x4_t(vv, va);
                mma_f16(oacc[2 * dnp],     pa, &vv[0]);
                mma_f16(oacc[2 * dnp + 1], pa, &vv[2]);
            }
        }
    }

    const float invr  = 1.f / den_r;
    const float invr8 = 1.f / den_r8;
    const size_t r0 = (rowbase + q0 + wid * 16 + (lane >> 2)) * HID + colbase;
    const size_t r8 = r0 + 8 * HID;
#pragma unroll
    for (int dn = 0; dn < 8; ++dn) {
        const int col = dn * 8 + (lane & 3) * 2;
        *(uint32_t*)(Ch + r0 + col) = pack_h_hi(oacc[dn][0] * invr,  oacc[dn][1] * invr);
        *(uint32_t*)(Ch + r8 + col) = pack_h_hi(oacc[dn][2] * invr8, oacc[dn][3] * invr8);
    }
}

// ---------------------------------------------------------------------------
// x [B, HID, T] fp32 -> [BT, HID] fp16, vectorized: 64x64 tiles,
// float4 loads, 2x uint4 (32B) stores per thread (128B contiguous per row).
// ---------------------------------------------------------------------------
__global__ void __launch_bounds__(256)
xpose_kernel(const float* __restrict__ x, __half* __restrict__ xh)
{
    __shared__ float s[64][65];
    const int b = blockIdx.z, k0 = blockIdx.y * 64, t0 = blockIdx.x * 64;
    const int tid = threadIdx.x;

    const float* src = x + ((size_t)b * HID + k0) * TDIM + t0;
#pragma unroll
    for (int i = 0; i < 4; ++i) {
        const int u  = i * 256 + tid;      // 1024 float4
        const int r  = u >> 4;             // k-row 0..63
        const int c4 = u & 15;             // float4 col
        const float4 v = *(const float4*)(src + (size_t)r * TDIM + c4 * 4);
        s[r][c4 * 4 + 0] = v.x;
        s[r][c4 * 4 + 1] = v.y;
        s[r][c4 * 4 + 2] = v.z;
        s[r][c4 * 4 + 3] = v.w;
    }
    __syncthreads();

    const int t  = tid >> 2;           // 0..63
    const int kc = (tid & 3) * 16;     // k chunk of 16
    uint32_t o[8];
#pragma unroll
    for (int i = 0; i < 8; ++i)
        o[i] = pack_h_hi(s[kc + 2 * i][t], s[kc + 2 * i + 1][t]);
    __half* dst = xh + (size_t)(b * TDIM + t0 + t) * HID + k0 + kc;
    *(uint4*)(dst)     = make_uint4(o[0], o[1], o[2], o[3]);
    *(uint4*)(dst + 8) = make_uint4(o[4], o[5], o[6], o[7]);
}

// all 4 weights fp32 -> fp16 in one launch (blockIdx.y selects)
__global__ void __launch_bounds__(256)
wconv4_kernel(const float* __restrict__ w0, const float* __restrict__ w1,
              const float* __restrict__ w2, const float* __restrict__ w3,
              __half* __restrict__ dst, int n4)
{
    const int z = blockIdx.y;
    const float* src = (z == 0) ? w0 : (z == 1) ? w1 : (z == 2) ? w2 : w3;
    __half* d = dst + (size_t)z * HID * HID;
    const int i = blockIdx.x * 256 + threadIdx.x;
    if (i >= n4) return;
    const float4 v = ((const float4*)src)[i];
    uint2 hp;
    hp.x = pack_h_hi(v.x, v.y);
    hp.y = pack_h_hi(v.z, v.w);
    ((uint2*)d)[i] = hp;
}

// ---------------------------------------------------------------------------
extern "C" void kernel_launch(void* const* d_in, const int* in_sizes, int n_in,
                              void* d_out, int out_size)
{
    const float* x    = (const float*)d_in[0];
    const int*   mask = (const int*)d_in[1];
    const float* Wq   = (const float*)d_in[2];
    const float* bq   = (const float*)d_in[3];
    const float* Wk   = (const float*)d_in[4];
    const float* bk   = (const float*)d_in[5];
    const float* Wv   = (const float*)d_in[6];
    const float* bv   = (const float*)d_in[7];
    const float* Wo   = (const float*)d_in[8];
    const float* bo   = (const float*)d_in[9];
    float* out = (float*)d_out;

    float* scr;
    __half *xh, *qh, *kh, *vh, *ch, *whf;
    cudaGetSymbolAddress((void**)&scr, g_scr);
    cudaGetSymbolAddress((void**)&xh,  g_xh);
    cudaGetSymbolAddress((void**)&qh,  g_qh);
    cudaGetSymbolAddress((void**)&kh,  g_kh);
    cudaGetSymbolAddress((void**)&vh,  g_vh);
    cudaGetSymbolAddress((void**)&ch,  g_ch);
    cudaGetSymbolAddress((void**)&whf, g_whf);

    cudaFuncSetAttribute(gemm_qkv_kernel,
                         cudaFuncAttributeMaxDynamicSharedMemorySize, GEMM_SMEM_BYTES);
    cudaFuncSetAttribute(gemm_omax_kernel,
                         cudaFuncAttributeMaxDynamicSharedMemorySize, GEMM_SMEM_BYTES);
    cudaFuncSetAttribute(attn_mma_kernel,
                         cudaFuncAttributeMaxDynamicSharedMemorySize, ATTN_SMEM_BYTES);

    const int wn4 = HID * HID / 4;
    wconv4_kernel<<<dim3((wn4 + 255) / 256, 4), 256>>>(Wq, Wk, Wv, Wo, whf, wn4);
    xpose_kernel<<<dim3(TDIM / 64, HID / 64, BDIM), 256>>>(x, xh);

    const size_t WSZ = (size_t)HID * HID;

    gemm_qkv_kernel<<<dim3(HID / 128, BT / 128, 3), 256, GEMM_SMEM_BYTES>>>(
        xh, whf, bq, bk, bv, qh, kh, vh);

    attn_mma_kernel<<<dim3(TDIM / 128, NH, BDIM), 256, ATTN_SMEM_BYTES>>>(
        qh, kh, vh, mask, ch);

    gemm_omax_kernel<<<dim3(HID / 128, BT / 128), 256, GEMM_SMEM_BYTES>>>(
        ch, whf + 3 * WSZ, scr);

    maxcombine_kernel<<<(BDIM * HID) / 256, 256>>>(scr, bo, out);
}

// round 12
// speedup vs baseline: 3.1443x; 1.0232x over previous
#include <cuda_runtime.h>
#include <cuda_bf16.h>
#include <cuda_fp16.h>
#include <cstdint>

#define BDIM 32
#define TDIM 512
#define HID  1024
#define NH   16
#define HD   64
#define BT   (BDIM * TDIM)   // 16384

// ------------------------- scratch (device globals) -------------------------
__device__ float  g_scr[(size_t)4 * BDIM * HID];   // o-proj partial maxes
__device__ __half g_xh [(size_t)BT * HID];
__device__ __half g_qh [(size_t)BT * HID];         // pre-scaled by 0.125*log2(e)
__device__ __half g_kh [(size_t)BT * HID];
__device__ __half g_vh [(size_t)BT * HID];
__device__ __half g_ch [(size_t)BT * HID];
__device__ __half g_whf[(size_t)4 * HID * HID];    // fp16 weights (q,k,v,o)

// ------------------------------ PTX helpers --------------------------------
__device__ __forceinline__ uint32_t smem_u32(const void* p) {
    uint32_t a;
    asm("{ .reg .u64 t; cvta.to.shared.u64 t, %1; cvt.u32.u64 %0, t; }" : "=r"(a) : "l"(p));
    return a;
}
__device__ __forceinline__ void ldm_x4(uint32_t* r, uint32_t addr) {
    asm volatile("ldmatrix.sync.aligned.m8n8.x4.shared.b16 {%0,%1,%2,%3}, [%4];"
                 : "=r"(r[0]), "=r"(r[1]), "=r"(r[2]), "=r"(r[3]) : "r"(addr));
}
__device__ __forceinline__ void ldm_x4_t(uint32_t* r, uint32_t addr) {
    asm volatile("ldmatrix.sync.aligned.m8n8.x4.trans.shared.b16 {%0,%1,%2,%3}, [%4];"
                 : "=r"(r[0]), "=r"(r[1]), "=r"(r[2]), "=r"(r[3]) : "r"(addr));
}
// fp32-acc fp16 mma (projections, PV)
__device__ __forceinline__ void mma_f16(float* c, const uint32_t* a, const uint32_t* b) {
    asm volatile("mma.sync.aligned.m16n8k16.row.col.f32.f16.f16.f32 "
                 "{%0,%1,%2,%3}, {%4,%5,%6,%7}, {%8,%9}, {%0,%1,%2,%3};"
                 : "+f"(c[0]), "+f"(c[1]), "+f"(c[2]), "+f"(c[3])
                 : "r"(a[0]), "r"(a[1]), "r"(a[2]), "r"(a[3]), "r"(b[0]), "r"(b[1]));
}
// fp16-acc fp16 mma (attention QK): C fragment = 2 packed half2 regs
__device__ __forceinline__ void mma_f16h(uint32_t* c, const uint32_t* a, const uint32_t* b) {
    asm volatile("mma.sync.aligned.m16n8k16.row.col.f16.f16.f16.f16 "
                 "{%0,%1}, {%2,%3,%4,%5}, {%6,%7}, {%0,%1};"
                 : "+r"(c[0]), "+r"(c[1])
                 : "r"(a[0]), "r"(a[1]), "r"(a[2]), "r"(a[3]), "r"(b[0]), "r"(b[1]));
}
#define CP_ASYNC16(saddr, gptr) \
    asm volatile("cp.async.cg.shared.global [%0], [%1], 16;" :: "r"(saddr), "l"(gptr))
#define CP_COMMIT() asm volatile("cp.async.commit_group;" ::: "memory")
#define CP_WAIT0()  asm volatile("cp.async.wait_group 0;" ::: "memory")
#define CP_WAIT1()  asm volatile("cp.async.wait_group 1;" ::: "memory")

__device__ __forceinline__ uint32_t pack_h_hi(float a, float b) {
    __half2 h = __floats2half2_rn(a, b);
    return *(uint32_t*)&h;
}
__device__ __forceinline__ uint32_t h2ex2(uint32_t x) {
    uint32_t r;
    asm("ex2.approx.f16x2 %0, %1;" : "=r"(r) : "r"(x));
    return r;
}

#define LOG2E_8 0.1803368801111244f     // 0.125 * log2(e) (folded into Q)
#define CLIP2F  72.134752044448170f     // 50 * log2(e)

// ---------------------------------------------------------------------------
// fp16 GEMM core: C = A @ W^T (fp32 acc)
// 128x128 tile, BK=64, 8 warps (2m x 4n), warp tile 64x32.
// 3-stage cp.async ring, ONE __syncthreads per iteration.
// ---------------------------------------------------------------------------
#define BK      64
#define NCHUNK  (HID / BK)          // 16
#define PITCH   72                  // fp16 elems per smem row (144B)
#define P2      (PITCH * 2)
#define TILE_B  (128 * P2)          // 18432 bytes
#define STAGE_B (2 * TILE_B)        // 36864
#define GEMM_SMEM_BYTES (3 * STAGE_B)   // 110592

struct GemmCore {
    uint32_t sbase;
    int tid, wid, lane, wm, wn, m0, n0;
    float acc[4][4][4];

    __device__ __forceinline__ void init(uint32_t sb, int m, int n) {
        sbase = sb;
        tid = threadIdx.x; wid = tid >> 5; lane = tid & 31;
        wm = wid >> 2; wn = wid & 3;
        m0 = m; n0 = n;
#pragma unroll
        for (int i = 0; i < 4; ++i)
#pragma unroll
            for (int j = 0; j < 4; ++j)
#pragma unroll
                for (int e = 0; e < 4; ++e) acc[i][j][e] = 0.f;
    }

    __device__ __forceinline__ void issue_copy(
        const __half* A, const __half* W, int c, int s)
    {
        const int k0 = c * BK;
        const uint32_t sb = sbase + s * STAGE_B;
#pragma unroll
        for (int op = 0; op < 2; ++op) {
            const __half* src = (op == 0) ? A : W;
            const int rbase = (op == 0) ? m0 : n0;
#pragma unroll
            for (int i = 0; i < 4; ++i) {
                const int u   = i * 256 + tid;
                const int row = u >> 3;
                const int cv  = u & 7;
                const void* g = src + (size_t)(rbase + row) * HID + k0 + cv * 8;
                CP_ASYNC16(sb + op * TILE_B + row * P2 + cv * 16, g);
            }
        }
        CP_COMMIT();
    }

    __device__ __forceinline__ void compute(int s) {
        const uint32_t sb = sbase + s * STAGE_B;
        const uint32_t aA = sb;
        const uint32_t aW = sb + TILE_B;

        const int arow = wm * 64 + (lane & 15);
        const int acol = (lane >> 4) * 8;
        const int brow = wn * 32 + (lane & 7) + (lane >> 4) * 8;
        const int bcol = ((lane >> 3) & 1) * 8;

#pragma unroll
        for (int ks = 0; ks < 4; ++ks) {
            uint32_t a[4][4];
#pragma unroll
            for (int i = 0; i < 4; ++i) {
                const uint32_t off = (arow + i * 16) * P2 + (ks * 16 + acol) * 2;
                ldm_x4(a[i], aA + off);
            }
            uint32_t bw[8];
#pragma unroll
            for (int jj = 0; jj < 2; ++jj) {
                const uint32_t off = (brow + jj * 16) * P2 + (ks * 16 + bcol) * 2;
                ldm_x4(&bw[jj * 4], aW + off);
            }
#pragma unroll
            for (int i = 0; i < 4; ++i)
#pragma unroll
                for (int j = 0; j < 4; ++j) {
                    const int bi = (j >> 1) * 4 + (j & 1) * 2;
                    mma_f16(acc[i][j], a[i], &bw[bi]);
                }
        }
    }

    __device__ __forceinline__ void mainloop(const __half* A, const __half* W)
    {
        issue_copy(A, W, 0, 0);
        issue_copy(A, W, 1, 1);
#pragma unroll 1
        for (int c = 0; c < NCHUNK; ++c) {
            if (c + 1 < NCHUNK) { CP_WAIT1(); } else { CP_WAIT0(); }
            __syncthreads();
            if (c + 2 < NCHUNK) issue_copy(A, W, c + 2, (c + 2) % 3);
            compute(c % 3);
        }
    }
};

// ---- fused QKV; q output pre-scaled by LOG2E_8 for the log2-domain softmax ----
__global__ void __launch_bounds__(256)
gemm_qkv_kernel(const __half* __restrict__ xh, const __half* __restrict__ whf,
                const float* __restrict__ bq, const float* __restrict__ bk,
                const float* __restrict__ bv,
                __half* __restrict__ qh, __half* __restrict__ kh,
                __half* __restrict__ vh)
{
    extern __shared__ __align__(128) char smem[];
    const int z = blockIdx.z;
    const size_t WSZ = (size_t)HID * HID;
    const float* bias = (z == 0) ? bq : (z == 1) ? bk : bv;
    __half* C = (z == 0) ? qh : (z == 1) ? kh : vh;
    const float sc = (z == 0) ? LOG2E_8 : 1.f;

    GemmCore g;
    g.init(smem_u32(smem), blockIdx.y * 128, blockIdx.x * 128);
    g.mainloop(xh, whf + z * WSZ);

#pragma unroll
    for (int i = 0; i < 4; ++i) {
        const int r0 = g.m0 + g.wm * 64 + i * 16 + (g.lane >> 2);
#pragma unroll
        for (int j = 0; j < 4; ++j) {
            const int col = g.n0 + g.wn * 32 + j * 8 + (g.lane & 3) * 2;
            const float bx = bias[col], by = bias[col + 1];
            const size_t o0 = (size_t)r0 * HID + col;
            const size_t o1 = (size_t)(r0 + 8) * HID + col;
            *(uint32_t*)(C + o0) = pack_h_hi((g.acc[i][j][0] + bx) * sc,
                                             (g.acc[i][j][1] + by) * sc);
            *(uint32_t*)(C + o1) = pack_h_hi((g.acc[i][j][2] + bx) * sc,
                                             (g.acc[i][j][3] + by) * sc);
        }
    }
}

// ---- o-proj with fused column-max epilogue ----
__global__ void __launch_bounds__(256)
gemm_omax_kernel(const __half* __restrict__ ch, const __half* __restrict__ Wo,
                 float* __restrict__ scr)
{
    extern __shared__ __align__(128) char smem[];
    GemmCore g;
    g.init(smem_u32(smem), blockIdx.y * 128, blockIdx.x * 128);
    g.mainloop(ch, Wo);
    __syncthreads();

    float* maxbuf = (float*)smem;
#pragma unroll
    for (int j = 0; j < 4; ++j) {
        float c0 = -3.402823466e38f, c1 = c0;
#pragma unroll
        for (int i = 0; i < 4; ++i) {
            c0 = fmaxf(c0, fmaxf(g.acc[i][j][0], g.acc[i][j][2]));
            c1 = fmaxf(c1, fmaxf(g.acc[i][j][1], g.acc[i][j][3]));
        }
        c0 = fmaxf(c0, __shfl_xor_sync(0xffffffff, c0, 4));
        c0 = fmaxf(c0, __shfl_xor_sync(0xffffffff, c0, 8));
        c0 = fmaxf(c0, __shfl_xor_sync(0xffffffff, c0, 16));
        c1 = fmaxf(c1, __shfl_xor_sync(0xffffffff, c1, 4));
        c1 = fmaxf(c1, __shfl_xor_sync(0xffffffff, c1, 8));
        c1 = fmaxf(c1, __shfl_xor_sync(0xffffffff, c1, 16));
        if ((g.lane >> 2) == 0) {
            const int cc = g.wn * 32 + j * 8 + (g.lane & 3) * 2;
            maxbuf[g.wm * 128 + cc]     = c0;
            maxbuf[g.wm * 128 + cc + 1] = c1;
        }
    }
    __syncthreads();
    if (g.tid < 128) {
        const float f = fmaxf(maxbuf[g.tid], maxbuf[128 + g.tid]);
        const int b   = g.m0 >> 9;
        const int sub = (g.m0 >> 7) & 3;
        scr[((size_t)sub * BDIM + b) * HID + g.n0 + g.tid] = f;
    }
}

__global__ void __launch_bounds__(256)
maxcombine_kernel(const float* __restrict__ scr, const float* __restrict__ bias,
                  float* __restrict__ out)
{
    const int i = blockIdx.x * 256 + threadIdx.x;
    const float f = fmaxf(fmaxf(scr[i], scr[BDIM * HID + i]),
                          fmaxf(scr[2 * BDIM * HID + i], scr[3 * BDIM * HID + i]));
    out[i] = f + bias[i & (HID - 1)];
}

// ---------------------------------------------------------------------------
// Attention: QK fp16-acc (C frag = packed half2 pairs, zero repacking),
// half2 clip+mask softmax, ex2.f16x2, PV fp32-acc. Q pre-scaled by log2e/8.
// Mask smem: per stage, 32 x half2 m2 and 32 x half2 (m2*C - C) addends.
// ---------------------------------------------------------------------------
#define APITCH 72
#define AP2    (APITCH * 2)
#define SM_Q   0
#define KVST   (64 * AP2)               // 9216
#define SM_K0  (128 * AP2)              // 18432
#define SM_V0  (SM_K0 + 3 * KVST)       // 46080
#define SM_MSK (SM_V0 + 3 * KVST)       // 73728
#define MSKST  256                      // 32*4 m2 + 32*4 a2 bytes
#define ATTN_SMEM_BYTES (SM_MSK + 3 * MSKST)

__global__ void __launch_bounds__(256)
attn_mma_kernel(const __half* __restrict__ Qh, const __half* __restrict__ Kh,
                const __half* __restrict__ Vh, const int* __restrict__ mask,
                __half* __restrict__ Ch)
{
    extern __shared__ __align__(128) char smem[];
    const uint32_t sb = smem_u32(smem);

    const int tid  = threadIdx.x;
    const int wid  = tid >> 5, lane = tid & 31;
    const int q0   = blockIdx.x * 128;
    const int h    = blockIdx.y;
    const int b    = blockIdx.z;
    const size_t rowbase = (size_t)b * TDIM;
    const int colbase = h * HD;

    const __half2 C2  = __float2half2_rn(CLIP2F);
    const __half2 nC2 = __float2half2_rn(-CLIP2F);

    // ---- Q tile load ----
    {
#pragma unroll
        for (int i = 0; i < 4; ++i) {
            const int u = i * 256 + tid;
            const int r = u >> 3, cv = u & 7;
            const void* g = Qh + (rowbase + q0 + r) * HID + colbase + cv * 8;
            CP_ASYNC16(sb + SM_Q + r * AP2 + cv * 16, g);
        }
        CP_COMMIT();
    }

    auto issue_kv = [&](int c, int s) {
        const int k0 = c * 64;
        const uint32_t soK = sb + SM_K0 + s * KVST;
        const uint32_t soV = sb + SM_V0 + s * KVST;
#pragma unroll
        for (int i = 0; i < 2; ++i) {
            const int u = i * 256 + tid;
            const int r = u >> 3, cv = u & 7;
            CP_ASYNC16(soK + r * AP2 + cv * 16,
                       Kh + (rowbase + k0 + r) * HID + colbase + cv * 8);
            CP_ASYNC16(soV + r * AP2 + cv * 16,
                       Vh + (rowbase + k0 + r) * HID + colbase + cv * 8);
        }
        CP_COMMIT();
        if (tid < 32) {
            const int i0 = mask[b * TDIM + k0 + 2 * tid];
            const int i1 = mask[b * TDIM + k0 + 2 * tid + 1];
            const __half2 m2 = __floats2half2_rn((float)i0, (float)i1);
            const __half2 a2 = __hfma2(m2, C2, nC2);   // m*C - C
            __half2* mp = (__half2*)(smem + SM_MSK + s * MSKST);
            mp[tid]      = m2;
            mp[32 + tid] = a2;
        }
    };

    float oacc[8][4];
#pragma unroll
    for (int j = 0; j < 8; ++j)
#pragma unroll
        for (int e = 0; e < 4; ++e) oacc[j][e] = 0.f;
    float den_r = 0.f, den_r8 = 0.f;

    const int qoff_row = (wid * 16 + (lane & 15)) * AP2;
    const int qoff_col = ((lane >> 4) * 8) * 2;
    const int koff_row = ((lane & 7) + (lane >> 4) * 8) * AP2;
    const int koff_col = (((lane >> 3) & 1) * 8) * 2;
    const int voff_row = ((lane & 15)) * AP2;
    const int voff_col = ((lane >> 4) * 8) * 2;
    const uint32_t qbase = sb + SM_Q + qoff_row + qoff_col;

    issue_kv(0, 0);
    issue_kv(1, 1);

#pragma unroll 1
    for (int c = 0; c < 8; ++c) {
        const int s = c % 3;
        if (c < 7) { CP_WAIT1(); } else { CP_WAIT0(); }
        __syncthreads();
        if (c + 2 < 8) issue_kv(c + 2, (c + 2) % 3);

        // ---- S (log2 domain) = Qs K^T, fp16 accumulation, packed output ----
        uint32_t sacc[8][2];
#pragma unroll
        for (int j = 0; j < 8; ++j) { sacc[j][0] = 0; sacc[j][1] = 0; }

#pragma unroll
        for (int dk = 0; dk < 4; ++dk) {
            uint32_t a[4];
            ldm_x4(a, qbase + dk * 32);
#pragma unroll
            for (int kb = 0; kb < 4; ++kb) {
                uint32_t bh[4];
                const uint32_t ka = sb + SM_K0 + s * KVST +
                                    (kb * 16) * AP2 + koff_row + dk * 32 + koff_col;
                ldm_x4(bh, ka);
                mma_f16h(sacc[2 * kb],     a, &bh[0]);
                mma_f16h(sacc[2 * kb + 1], a, &bh[2]);
            }
        }

        // ---- softmax: p = 2^(m*(clip(t)+C)-C), all in half2 ----
        const __half2* mp = (const __half2*)(smem + SM_MSK + s * MSKST);
        float dr = 0.f, dr8 = 0.f;
#pragma unroll
        for (int nt = 0; nt < 8; ++nt) {
            const int cp = nt * 4 + (lane & 3);   // column-pair index
            const __half2 m2 = mp[cp];
            const __half2 a2 = mp[32 + cp];
#pragma unroll
            for (int r = 0; r < 2; ++r) {
                __half2 t2 = *(__half2*)&sacc[nt][r];
                t2 = __hmax2(__hmin2(t2, C2), nC2);
                t2 = __hfma2(m2, t2, a2);
                const uint32_t p = h2ex2(*(uint32_t*)&t2);
                sacc[nt][r] = p;
                const float2 f = __half22float2(*(const __half2*)&p);
                if (r == 0) dr += f.x + f.y; else dr8 += f.x + f.y;
            }
        }
        dr  += __shfl_xor_sync(0xffffffff, dr, 1);
        dr  += __shfl_xor_sync(0xffffffff, dr, 2);
        dr8 += __shfl_xor_sync(0xffffffff, dr8, 1);
        dr8 += __shfl_xor_sync(0xffffffff, dr8, 2);
        den_r  += dr;
        den_r8 += dr8;

        // ---- PV: oacc += P @ V  (P already in A-fragment layout) ----
#pragma unroll
        for (int kb = 0; kb < 4; ++kb) {
            uint32_t pa[4];
            const int t0 = 2 * kb, t1 = 2 * kb + 1;
            pa[0] = sacc[t0][0];
            pa[1] = sacc[t0][1];
            pa[2] = sacc[t1][0];
            pa[3] = sacc[t1][1];
#pragma unroll
            for (int dnp = 0; dnp < 4; ++dnp) {
                uint32_t vv[4];
                const uint32_t va = sb + SM_V0 + s * KVST +
                                    (kb * 16) * AP2 + voff_row + dnp * 32 + voff_col;
                ldm_x4_t(vv, va);
                mma_f16(oacc[2 * dnp],     pa, &vv[0]);
                mma_f16(oacc[2 * dnp + 1], pa, &vv[2]);
            }
        }
    }

    const float invr  = 1.f / den_r;
    const float invr8 = 1.f / den_r8;
    const size_t r0 = (rowbase + q0 + wid * 16 + (lane >> 2)) * HID + colbase;
    const size_t r8 = r0 + 8 * HID;
#pragma unroll
    for (int dn = 0; dn < 8; ++dn) {
        const int col = dn * 8 + (lane & 3) * 2;
        *(uint32_t*)(Ch + r0 + col) = pack_h_hi(oacc[dn][0] * invr,  oacc[dn][1] * invr);
        *(uint32_t*)(Ch + r8 + col) = pack_h_hi(oacc[dn][2] * invr8, oacc[dn][3] * invr8);
    }
}

// ---------------------------------------------------------------------------
// x [B, HID, T] fp32 -> [BT, HID] fp16, vectorized 64x64 tiles.
// ---------------------------------------------------------------------------
__global__ void __launch_bounds__(256)
xpose_kernel(const float* __restrict__ x, __half* __restrict__ xh)
{
    __shared__ float s[64][65];
    const int b = blockIdx.z, k0 = blockIdx.y * 64, t0 = blockIdx.x * 64;
    const int tid = threadIdx.x;

    const float* src = x + ((size_t)b * HID + k0) * TDIM + t0;
#pragma unroll
    for (int i = 0; i < 4; ++i) {
        const int u  = i * 256 + tid;
        const int r  = u >> 4;
        const int c4 = u & 15;
        const float4 v = *(const float4*)(src + (size_t)r * TDIM + c4 * 4);
        s[r][c4 * 4 + 0] = v.x;
        s[r][c4 * 4 + 1] = v.y;
        s[r][c4 * 4 + 2] = v.z;
        s[r][c4 * 4 + 3] = v.w;
    }
    __syncthreads();

    const int t  = tid >> 2;
    const int kc = (tid & 3) * 16;
    uint32_t o[8];
#pragma unroll
    for (int i = 0; i < 8; ++i)
        o[i] = pack_h_hi(s[kc + 2 * i][t], s[kc + 2 * i + 1][t]);
    __half* dst = xh + (size_t)(b * TDIM + t0 + t) * HID + k0 + kc;
    *(uint4*)(dst)     = make_uint4(o[0], o[1], o[2], o[3]);
    *(uint4*)(dst + 8) = make_uint4(o[4], o[5], o[6], o[7]);
}

// all 4 weights fp32 -> fp16 in one launch (blockIdx.y selects)
__global__ void __launch_bounds__(256)
wconv4_kernel(const float* __restrict__ w0, const float* __restrict__ w1,
              const float* __restrict__ w2, const float* __restrict__ w3,
              __half* __restrict__ dst, int n4)
{
    const int z = blockIdx.y;
    const float* src = (z == 0) ? w0 : (z == 1) ? w1 : (z == 2) ? w2 : w3;
    __half* d = dst + (size_t)z * HID * HID;
    const int i = blockIdx.x * 256 + threadIdx.x;
    if (i >= n4) return;
    const float4 v = ((const float4*)src)[i];
    uint2 hp;
    hp.x = pack_h_hi(v.x, v.y);
    hp.y = pack_h_hi(v.z, v.w);
    ((uint2*)d)[i] = hp;
}

// ---------------------------------------------------------------------------
extern "C" void kernel_launch(void* const* d_in, const int* in_sizes, int n_in,
                              void* d_out, int out_size)
{
    const float* x    = (const float*)d_in[0];
    const int*   mask = (const int*)d_in[1];
    const float* Wq   = (const float*)d_in[2];
    const float* bq   = (const float*)d_in[3];
    const float* Wk   = (const float*)d_in[4];
    const float* bk   = (const float*)d_in[5];
    const float* Wv   = (const float*)d_in[6];
    const float* bv   = (const float*)d_in[7];
    const float* Wo   = (const float*)d_in[8];
    const float* bo   = (const float*)d_in[9];
    float* out = (float*)d_out;

    float* scr;
    __half *xh, *qh, *kh, *vh, *ch, *whf;
    cudaGetSymbolAddress((void**)&scr, g_scr);
    cudaGetSymbolAddress((void**)&xh,  g_xh);
    cudaGetSymbolAddress((void**)&qh,  g_qh);
    cudaGetSymbolAddress((void**)&kh,  g_kh);
    cudaGetSymbolAddress((void**)&vh,  g_vh);
    cudaGetSymbolAddress((void**)&ch,  g_ch);
    cudaGetSymbolAddress((void**)&whf, g_whf);

    cudaFuncSetAttribute(gemm_qkv_kernel,
                         cudaFuncAttributeMaxDynamicSharedMemorySize, GEMM_SMEM_BYTES);
    cudaFuncSetAttribute(gemm_omax_kernel,
                         cudaFuncAttributeMaxDynamicSharedMemorySize, GEMM_SMEM_BYTES);
    cudaFuncSetAttribute(attn_mma_kernel,
                         cudaFuncAttributeMaxDynamicSharedMemorySize, ATTN_SMEM_BYTES);

    const int wn4 = HID * HID / 4;
    wconv4_kernel<<<dim3((wn4 + 255) / 256, 4), 256>>>(Wq, Wk, Wv, Wo, whf, wn4);
    xpose_kernel<<<dim3(TDIM / 64, HID / 64, BDIM), 256>>>(x, xh);

    const size_t WSZ = (size_t)HID * HID;

    gemm_qkv_kernel<<<dim3(HID / 128, BT / 128, 3), 256, GEMM_SMEM_BYTES>>>(
        xh, whf, bq, bk, bv, qh, kh, vh);

    attn_mma_kernel<<<dim3(TDIM / 128, NH, BDIM), 256, ATTN_SMEM_BYTES>>>(
        qh, kh, vh, mask, ch);

    gemm_omax_kernel<<<dim3(HID / 128, BT / 128), 256, GEMM_SMEM_BYTES>>>(
        ch, whf + 3 * WSZ, scr);

    maxcombine_kernel<<<(BDIM * HID) / 256, 256>>>(scr, bo, out);
}